// round 1
// baseline (speedup 1.0000x reference)
#include <cuda_runtime.h>
#include <math.h>
#include <math_constants.h>

// ---------------------------------------------------------------------------
// Problem constants (fixed by the reference)
// ---------------------------------------------------------------------------
#define BB   2      // batch
#define QL   2048   // queries
#define KLEN 2048   // keys
#define DMOD 512    // model dim
#define NH   8      // heads
#define NF   5      // rbf bases per head
#define DH   64     // head dim
#define NTAB 1024   // bias lookup table entries per head

static const float D_MAX     = 14.2f;                       // > sqrt(2)*10
static const float TAB_SCALE = (float)(NTAB - 1) / 14.2f;

// ---------------------------------------------------------------------------
// Device scratch (no cudaMalloc allowed)
// ---------------------------------------------------------------------------
__device__ float  g_qp [BB * QL   * DMOD];  // projected+scaled Q
__device__ float  g_kp [BB * KLEN * DMOD];  // projected K
__device__ float  g_vp [BB * KLEN * DMOD];  // projected V
__device__ float  g_ctx[BB * QL   * DMOD];  // attention output (pre out-proj)
__device__ float2 g_tab[NH * NTAB];         // per-head bias table (value, delta)

// ---------------------------------------------------------------------------
// Bias table: tab[h][i] = (f_h(d_i), f_h(d_{i+1}) - f_h(d_i)),
// f_h(d) = sum_f a * exp(-|b| * (d - c)^2)
// ---------------------------------------------------------------------------
__global__ void build_table_kernel(const float* __restrict__ A,
                                   const float* __restrict__ Bp,
                                   const float* __restrict__ C)
{
    int idx = blockIdx.x * blockDim.x + threadIdx.x;
    if (idx >= NH * NTAB) return;
    int h = idx / NTAB;
    int i = idx - h * NTAB;
    const float STEP = 14.2f / (float)(NTAB - 1);
    float d0 = (float)i * STEP;
    float d1 = d0 + STEP;
    float v0 = 0.f, v1 = 0.f;
#pragma unroll
    for (int f = 0; f < NF; f++) {
        float af = A [h * NF + f];
        float bf = fabsf(Bp[h * NF + f]);
        float cf = C [h * NF + f];
        float t0 = d0 - cf;
        float t1 = d1 - cf;
        v0 += af * expf(-bf * t0 * t0);
        v1 += af * expf(-bf * t1 * t1);
    }
    g_tab[idx] = make_float2(v0, v1 - v0);
}

// ---------------------------------------------------------------------------
// GEMM: C[M,512] = (A[M,512] @ W[512,512] + bias) * scale
// 64x64 tile, BK=16, 256 threads, 4x4 register blocking.
// ---------------------------------------------------------------------------
__global__ __launch_bounds__(256)
void gemm_kernel(const float* __restrict__ A,
                 const float* __restrict__ W,
                 const float* __restrict__ bias,
                 float* __restrict__ Cout,
                 float scale)
{
    __shared__ float As[16 * 65];   // transposed: As[k][row], padded
    __shared__ float Bs[16 * 64];   // Bs[k][col]

    const int tid = threadIdx.x;
    const int n0  = blockIdx.x * 64;
    const int m0  = blockIdx.y * 64;
    const int ty  = tid >> 4;       // 0..15
    const int tx  = tid & 15;       // 0..15

    const int rA = tid >> 2;        // 0..63
    const int cg = tid & 3;         // 0..3
    const int rB = tid >> 4;        // 0..15
    const int c4 = tid & 15;        // 0..15

    float acc[4][4];
#pragma unroll
    for (int j = 0; j < 4; j++)
#pragma unroll
        for (int i = 0; i < 4; i++) acc[j][i] = 0.f;

    for (int kb = 0; kb < DMOD; kb += 16) {
        float4 av = *(const float4*)&A[(size_t)(m0 + rA) * DMOD + kb + cg * 4];
        float4 bv = *(const float4*)&W[(size_t)(kb + rB) * DMOD + n0 + c4 * 4];
        __syncthreads();
        As[(4 * cg + 0) * 65 + rA] = av.x;
        As[(4 * cg + 1) * 65 + rA] = av.y;
        As[(4 * cg + 2) * 65 + rA] = av.z;
        As[(4 * cg + 3) * 65 + rA] = av.w;
        *(float4*)&Bs[rB * 64 + c4 * 4] = bv;
        __syncthreads();
#pragma unroll
        for (int kk = 0; kk < 16; kk++) {
            float a0 = As[kk * 65 + ty * 4 + 0];
            float a1 = As[kk * 65 + ty * 4 + 1];
            float a2 = As[kk * 65 + ty * 4 + 2];
            float a3 = As[kk * 65 + ty * 4 + 3];
            float4 b4 = *(float4*)&Bs[kk * 64 + tx * 4];
            acc[0][0] = fmaf(a0, b4.x, acc[0][0]);
            acc[0][1] = fmaf(a0, b4.y, acc[0][1]);
            acc[0][2] = fmaf(a0, b4.z, acc[0][2]);
            acc[0][3] = fmaf(a0, b4.w, acc[0][3]);
            acc[1][0] = fmaf(a1, b4.x, acc[1][0]);
            acc[1][1] = fmaf(a1, b4.y, acc[1][1]);
            acc[1][2] = fmaf(a1, b4.z, acc[1][2]);
            acc[1][3] = fmaf(a1, b4.w, acc[1][3]);
            acc[2][0] = fmaf(a2, b4.x, acc[2][0]);
            acc[2][1] = fmaf(a2, b4.y, acc[2][1]);
            acc[2][2] = fmaf(a2, b4.z, acc[2][2]);
            acc[2][3] = fmaf(a2, b4.w, acc[2][3]);
            acc[3][0] = fmaf(a3, b4.x, acc[3][0]);
            acc[3][1] = fmaf(a3, b4.y, acc[3][1]);
            acc[3][2] = fmaf(a3, b4.z, acc[3][2]);
            acc[3][3] = fmaf(a3, b4.w, acc[3][3]);
        }
    }

    float4 bb = *(const float4*)&bias[n0 + tx * 4];
#pragma unroll
    for (int j = 0; j < 4; j++) {
        int row = m0 + ty * 4 + j;
        float4 o;
        o.x = (acc[j][0] + bb.x) * scale;
        o.y = (acc[j][1] + bb.y) * scale;
        o.z = (acc[j][2] + bb.z) * scale;
        o.w = (acc[j][3] + bb.w) * scale;
        *(float4*)&Cout[(size_t)row * DMOD + n0 + tx * 4] = o;
    }
}

// ---------------------------------------------------------------------------
// Flash attention with table-lerped TISA bias + online softmax + mask skip.
// Block: 128 threads = 64 q-rows x 2 half-threads (each owns 32 of DH=64).
// Grid: (Q/64, H, B). Key tiles of 32 in shared memory.
// Shared k/v layout: row stride 68 floats, cols >=32 shifted +4 floats so the
// two half-thread broadcast groups land in different banks.
// ---------------------------------------------------------------------------
#define KPAD 68

__device__ __forceinline__ void attn_step(
    int kk, const float4 (&qreg)[8], float4 (&acc)[8],
    float& m, float& l,
    const float* ksh, const float* vsh,
    const float2* tsh, const float2* lsh,
    float qlx, float qly, int halfOfs)
{
    // --- QK dot over this thread's 32 dims ---
    float4 s4 = make_float4(0.f, 0.f, 0.f, 0.f);
    int base = kk * KPAD + halfOfs;
#pragma unroll
    for (int j = 0; j < 8; j++) {
        float4 kv = *(const float4*)&ksh[base + j * 4];
        s4.x = fmaf(qreg[j].x, kv.x, s4.x);
        s4.y = fmaf(qreg[j].y, kv.y, s4.y);
        s4.z = fmaf(qreg[j].z, kv.z, s4.z);
        s4.w = fmaf(qreg[j].w, kv.w, s4.w);
    }
    float s = (s4.x + s4.y) + (s4.z + s4.w);
    s += __shfl_xor_sync(0xffffffffu, s, 1);   // combine halves -> full dot

    // --- TISA bias via per-head lerp table ---
    float2 kl = lsh[kk];
    float dx = qlx - kl.x;
    float dy = qly - kl.y;
    float dist = sqrtf(fmaf(dx, dx, dy * dy));
    float tp = dist * TAB_SCALE;
    int   ti = (int)tp;
    ti = min(ti, NTAB - 2);
    float fr = tp - (float)ti;
    float2 tv = tsh[ti];
    s += fmaf(fr, tv.y, tv.x);

    // --- online softmax ---
    if (s > m) {
        float corr = __expf(m - s);     // m=-inf first time -> corr=0
        m = s;
        l *= corr;
#pragma unroll
        for (int j = 0; j < 8; j++) {
            acc[j].x *= corr; acc[j].y *= corr;
            acc[j].z *= corr; acc[j].w *= corr;
        }
    }
    float p = __expf(s - m);
    l += p;

    // --- PV accumulate ---
#pragma unroll
    for (int j = 0; j < 8; j++) {
        float4 vv = *(const float4*)&vsh[base + j * 4];
        acc[j].x = fmaf(p, vv.x, acc[j].x);
        acc[j].y = fmaf(p, vv.y, acc[j].y);
        acc[j].z = fmaf(p, vv.z, acc[j].z);
        acc[j].w = fmaf(p, vv.w, acc[j].w);
    }
}

__global__ __launch_bounds__(128)
void attn_kernel(const float* __restrict__ qlocs,
                 const float* __restrict__ klocs,
                 const int*   __restrict__ vlens)
{
    __shared__ float  ksh[32 * KPAD];
    __shared__ float  vsh[32 * KPAD];
    __shared__ float2 tsh[NTAB];
    __shared__ float2 lsh[32];

    const int b  = blockIdx.z;
    const int h  = blockIdx.y;
    const int q0 = blockIdx.x * 64;
    const int tid = threadIdx.x;
    const int r    = tid >> 1;      // q-row within tile (0..63)
    const int half = tid & 1;       // which 32-dim half of DH
    const int halfOfs = half * 36;  // 32 cols + 4 swizzle shift
    const int q  = q0 + r;

    // stage bias table for this head
    for (int i = tid; i < NTAB; i += 128) tsh[i] = g_tab[h * NTAB + i];

    // q fragment -> registers
    float4 qreg[8];
    {
        const float* qrow = &g_qp[((size_t)b * QL + q) * DMOD + h * DH + half * 32];
#pragma unroll
        for (int j = 0; j < 8; j++) qreg[j] = *(const float4*)&qrow[j * 4];
    }
    float2 ql = *(const float2*)&qlocs[((size_t)b * QL + q) * 2];

    const int vlen = vlens[b];

    float4 acc[8];
#pragma unroll
    for (int j = 0; j < 8; j++) acc[j] = make_float4(0.f, 0.f, 0.f, 0.f);
    float m = -CUDART_INF_F;
    float l = 0.f;

    const int rowL = tid >> 2;      // loader row 0..31
    const int g4   = tid & 3;       // loader col group
    const float* kbase_g = &g_kp[(size_t)b * KLEN * DMOD + h * DH];
    const float* vbase_g = &g_vp[(size_t)b * KLEN * DMOD + h * DH];

    const int ntiles = (vlen + 31) >> 5;   // masked keys fully skipped
    for (int t = 0; t < ntiles; t++) {
        const int kb = t * 32;
        __syncthreads();
#pragma unroll
        for (int jj = 0; jj < 4; jj++) {
            int col  = (g4 + jj * 4) * 4;           // 0,16,...,60 pattern covers 0..63
            int colp = col + ((col >> 5) << 2);     // swizzle shift for cols >= 32
            *(float4*)&ksh[rowL * KPAD + colp] =
                *(const float4*)&kbase_g[(size_t)(kb + rowL) * DMOD + col];
            *(float4*)&vsh[rowL * KPAD + colp] =
                *(const float4*)&vbase_g[(size_t)(kb + rowL) * DMOD + col];
        }
        if (tid < 32)
            lsh[tid] = *(const float2*)&klocs[((size_t)b * KLEN + kb + tid) * 2];
        __syncthreads();

        const int kmax = min(32, vlen - kb);
        if (kmax == 32) {
#pragma unroll 4
            for (int kk = 0; kk < 32; kk++)
                attn_step(kk, qreg, acc, m, l, ksh, vsh, tsh, lsh, ql.x, ql.y, halfOfs);
        } else {
            for (int kk = 0; kk < kmax; kk++)
                attn_step(kk, qreg, acc, m, l, ksh, vsh, tsh, lsh, ql.x, ql.y, halfOfs);
        }
    }

    // normalize + write ctx
    float inv = 1.0f / l;
    float* crow = &g_ctx[((size_t)b * QL + q) * DMOD + h * DH + half * 32];
#pragma unroll
    for (int j = 0; j < 8; j++) {
        float4 o;
        o.x = acc[j].x * inv;
        o.y = acc[j].y * inv;
        o.z = acc[j].z * inv;
        o.w = acc[j].w * inv;
        *(float4*)&crow[j * 4] = o;
    }
}

// ---------------------------------------------------------------------------
// Launch
// ---------------------------------------------------------------------------
extern "C" void kernel_launch(void* const* d_in, const int* in_sizes, int n_in,
                              void* d_out, int out_size)
{
    const float* qs    = (const float*)d_in[0];
    const float* ks    = (const float*)d_in[1];
    const float* vs    = (const float*)d_in[2];
    const float* qlocs = (const float*)d_in[3];
    const float* klocs = (const float*)d_in[4];
    const float* Wq    = (const float*)d_in[5];
    const float* bq    = (const float*)d_in[6];
    const float* Wk    = (const float*)d_in[7];
    const float* bk    = (const float*)d_in[8];
    const float* Wv    = (const float*)d_in[9];
    const float* bv    = (const float*)d_in[10];
    const float* Wo    = (const float*)d_in[11];
    const float* bo    = (const float*)d_in[12];
    const float* ap    = (const float*)d_in[13];
    const float* bp    = (const float*)d_in[14];
    const float* cp    = (const float*)d_in[15];
    const int*   vl    = (const int*)  d_in[16];
    float* out = (float*)d_out;

    float *qp, *kp, *vp, *ctx;
    cudaGetSymbolAddress((void**)&qp,  g_qp);
    cudaGetSymbolAddress((void**)&kp,  g_kp);
    cudaGetSymbolAddress((void**)&vp,  g_vp);
    cudaGetSymbolAddress((void**)&ctx, g_ctx);

    // 1) bias tables
    build_table_kernel<<<(NH * NTAB + 255) / 256, 256>>>(ap, bp, cp);

    // 2) projections  (q scaled by 1/sqrt(DH) = 1/8)
    dim3 ggrid(DMOD / 64, (BB * QL) / 64);
    gemm_kernel<<<ggrid, 256>>>(qs, Wq, bq, qp, 0.125f);
    gemm_kernel<<<ggrid, 256>>>(ks, Wk, bk, kp, 1.0f);
    gemm_kernel<<<ggrid, 256>>>(vs, Wv, bv, vp, 1.0f);

    // 3) fused biased flash attention
    dim3 agrid(QL / 64, NH, BB);
    attn_kernel<<<agrid, 128>>>(qlocs, klocs, vl);

    // 4) output projection -> d_out
    gemm_kernel<<<ggrid, 256>>>(ctx, Wo, bo, out, 1.0f);
}

// round 4
// speedup vs baseline: 1.1993x; 1.1993x over previous
#include <cuda_runtime.h>
#include <math.h>
#include <math_constants.h>
#include <cstdint>

// ---------------------------------------------------------------------------
// Problem constants
// ---------------------------------------------------------------------------
#define BB   2
#define QL   2048
#define KLEN 2048
#define DMOD 512
#define NH   8
#define NF   5
#define DH   64
#define NTAB 1024

static const float TAB_SCALE = (float)(NTAB - 1) / 14.2f;

// ---------------------------------------------------------------------------
// Device scratch
// ---------------------------------------------------------------------------
__device__ float  g_qp [BB * QL   * DMOD];
__device__ float  g_kp [BB * KLEN * DMOD];
__device__ float  g_vp [BB * KLEN * DMOD];
__device__ float  g_ctx[BB * QL   * DMOD];
__device__ float2 g_tab[NH * NTAB];

// ---------------------------------------------------------------------------
// Helpers
// ---------------------------------------------------------------------------
__device__ __forceinline__ uint32_t f2tf32(float x) {
    uint32_t r;
    asm("cvt.rna.tf32.f32 %0, %1;" : "=r"(r) : "f"(x));
    return r;
}
__device__ __forceinline__ float cvt_tf32f(float x) {
    return __uint_as_float(f2tf32(x));
}

// m16n8k8 tf32 MMA (non-'a' PTX path -> HMMA, works on sm_103 base target)
__device__ __forceinline__ void mma_tf32(float* c, const uint32_t* a, const uint32_t* b) {
    asm volatile("mma.sync.aligned.m16n8k8.row.col.f32.tf32.tf32.f32 "
                 "{%0,%1,%2,%3}, {%4,%5,%6,%7}, {%8,%9}, {%0,%1,%2,%3};"
                 : "+f"(c[0]), "+f"(c[1]), "+f"(c[2]), "+f"(c[3])
                 : "r"(a[0]), "r"(a[1]), "r"(a[2]), "r"(a[3]),
                   "r"(b[0]), "r"(b[1]));
}

// ---------------------------------------------------------------------------
// Bias table
// ---------------------------------------------------------------------------
__global__ void build_table_kernel(const float* __restrict__ A,
                                   const float* __restrict__ Bp,
                                   const float* __restrict__ C)
{
    int idx = blockIdx.x * blockDim.x + threadIdx.x;
    if (idx >= NH * NTAB) return;
    int h = idx / NTAB;
    int i = idx - h * NTAB;
    const float STEP = 14.2f / (float)(NTAB - 1);
    float d0 = (float)i * STEP;
    float d1 = d0 + STEP;
    float v0 = 0.f, v1 = 0.f;
#pragma unroll
    for (int f = 0; f < NF; f++) {
        float af = A [h * NF + f];
        float bf = fabsf(Bp[h * NF + f]);
        float cf = C [h * NF + f];
        float t0 = d0 - cf;
        float t1 = d1 - cf;
        v0 += af * expf(-bf * t0 * t0);
        v1 += af * expf(-bf * t1 * t1);
    }
    g_tab[idx] = make_float2(v0, v1 - v0);
}

// ---------------------------------------------------------------------------
// tf32 mma.sync GEMM: C[M,512] = (A[M,512] @ W[512,512] + bias) * scale
// CTA tile 128x128, BK=32 chunks, 8 warps (4m x 2n), warp tile 32x64.
// A smem [128][36] row-major (pad->conflict-free a-frag loads);
// B smem [32][136] = W rows K-major (136%32==8 -> conflict-free b-frag loads).
// ---------------------------------------------------------------------------
#define APAD 36
#define BPAD 136

__global__ __launch_bounds__(256)
void gemm_mma_kernel(const float* __restrict__ A,
                     const float* __restrict__ W,
                     const float* __restrict__ bias,
                     float* __restrict__ Cout,
                     float scale)
{
    __shared__ float sA[128 * APAD];   // 18 KB
    __shared__ float sB[32 * BPAD];    // 17 KB

    const int tid  = threadIdx.x;
    const int lane = tid & 31;
    const int w    = tid >> 5;
    const int m_off = (w >> 1) * 32;
    const int n_off = (w & 1) * 64;
    const int m0 = blockIdx.y * 128;
    const int n0 = blockIdx.x * 128;

    const int lq = lane >> 2;   // 0..7
    const int lr = lane & 3;    // 0..3

    float c[2][8][4];
#pragma unroll
    for (int i = 0; i < 2; i++)
#pragma unroll
        for (int j = 0; j < 8; j++)
#pragma unroll
            for (int e = 0; e < 4; e++) c[i][j][e] = 0.f;

    for (int ch = 0; ch < 16; ch++) {
        const int kc0 = ch * 32;
        __syncthreads();
        // ---- load + tf32-convert chunk ----
#pragma unroll
        for (int i = 0; i < 4; i++) {
            int e = tid + i * 256;            // 0..1023
            // A: 128 rows x 8 float4
            int ra = e >> 3, ca = e & 7;
            float4 v = *(const float4*)&A[(size_t)(m0 + ra) * DMOD + kc0 + ca * 4];
            float4 t = make_float4(cvt_tf32f(v.x), cvt_tf32f(v.y),
                                   cvt_tf32f(v.z), cvt_tf32f(v.w));
            *(float4*)&sA[ra * APAD + ca * 4] = t;
            // B: 32 k-rows x 32 float4 (direct W rows, K-major)
            int kb = e >> 5, cb = e & 31;
            float4 u = *(const float4*)&W[(size_t)(kc0 + kb) * DMOD + n0 + cb * 4];
            float4 s = make_float4(cvt_tf32f(u.x), cvt_tf32f(u.y),
                                   cvt_tf32f(u.z), cvt_tf32f(u.w));
            *(float4*)&sB[kb * BPAD + cb * 4] = s;
        }
        __syncthreads();
        // ---- 4 x K=8 mma steps ----
#pragma unroll
        for (int ks = 0; ks < 4; ks++) {
            const int k0 = ks * 8;
            uint32_t a[2][4], b[8][2];
#pragma unroll
            for (int i = 0; i < 2; i++) {
                int r = m_off + i * 16 + lq;
                a[i][0] = __float_as_uint(sA[(r    ) * APAD + k0 + lr    ]);
                a[i][1] = __float_as_uint(sA[(r + 8) * APAD + k0 + lr    ]);
                a[i][2] = __float_as_uint(sA[(r    ) * APAD + k0 + lr + 4]);
                a[i][3] = __float_as_uint(sA[(r + 8) * APAD + k0 + lr + 4]);
            }
#pragma unroll
            for (int j = 0; j < 8; j++) {
                int n = n_off + j * 8 + lq;
                b[j][0] = __float_as_uint(sB[(k0 + lr    ) * BPAD + n]);
                b[j][1] = __float_as_uint(sB[(k0 + lr + 4) * BPAD + n]);
            }
#pragma unroll
            for (int i = 0; i < 2; i++)
#pragma unroll
                for (int j = 0; j < 8; j++)
                    mma_tf32(c[i][j], a[i], b[j]);
        }
    }

    // ---- epilogue: bias + scale, float2 stores ----
#pragma unroll
    for (int i = 0; i < 2; i++) {
        int row = m0 + m_off + i * 16 + lq;
#pragma unroll
        for (int j = 0; j < 8; j++) {
            int col = n0 + n_off + j * 8 + 2 * lr;
            float b0 = bias[col], b1 = bias[col + 1];
            float2 o0 = make_float2((c[i][j][0] + b0) * scale,
                                    (c[i][j][1] + b1) * scale);
            *(float2*)&Cout[(size_t)row * DMOD + col] = o0;
            float2 o1 = make_float2((c[i][j][2] + b0) * scale,
                                    (c[i][j][3] + b1) * scale);
            *(float2*)&Cout[(size_t)(row + 8) * DMOD + col] = o1;
        }
    }
}

// ---------------------------------------------------------------------------
// Flash attention (unchanged from round 1 passing version)
// ---------------------------------------------------------------------------
#define KPAD 68

__device__ __forceinline__ void attn_step(
    int kk, const float4 (&qreg)[8], float4 (&acc)[8],
    float& m, float& l,
    const float* ksh, const float* vsh,
    const float2* tsh, const float2* lsh,
    float qlx, float qly, int halfOfs)
{
    float4 s4 = make_float4(0.f, 0.f, 0.f, 0.f);
    int base = kk * KPAD + halfOfs;
#pragma unroll
    for (int j = 0; j < 8; j++) {
        float4 kv = *(const float4*)&ksh[base + j * 4];
        s4.x = fmaf(qreg[j].x, kv.x, s4.x);
        s4.y = fmaf(qreg[j].y, kv.y, s4.y);
        s4.z = fmaf(qreg[j].z, kv.z, s4.z);
        s4.w = fmaf(qreg[j].w, kv.w, s4.w);
    }
    float s = (s4.x + s4.y) + (s4.z + s4.w);
    s += __shfl_xor_sync(0xffffffffu, s, 1);

    float2 kl = lsh[kk];
    float dx = qlx - kl.x;
    float dy = qly - kl.y;
    float dist = sqrtf(fmaf(dx, dx, dy * dy));
    float tp = dist * TAB_SCALE;
    int   ti = (int)tp;
    ti = min(ti, NTAB - 2);
    float fr = tp - (float)ti;
    float2 tv = tsh[ti];
    s += fmaf(fr, tv.y, tv.x);

    if (s > m) {
        float corr = __expf(m - s);
        m = s;
        l *= corr;
#pragma unroll
        for (int j = 0; j < 8; j++) {
            acc[j].x *= corr; acc[j].y *= corr;
            acc[j].z *= corr; acc[j].w *= corr;
        }
    }
    float p = __expf(s - m);
    l += p;

#pragma unroll
    for (int j = 0; j < 8; j++) {
        float4 vv = *(const float4*)&vsh[base + j * 4];
        acc[j].x = fmaf(p, vv.x, acc[j].x);
        acc[j].y = fmaf(p, vv.y, acc[j].y);
        acc[j].z = fmaf(p, vv.z, acc[j].z);
        acc[j].w = fmaf(p, vv.w, acc[j].w);
    }
}

__global__ __launch_bounds__(128)
void attn_kernel(const float* __restrict__ qlocs,
                 const float* __restrict__ klocs,
                 const int*   __restrict__ vlens)
{
    __shared__ float  ksh[32 * KPAD];
    __shared__ float  vsh[32 * KPAD];
    __shared__ float2 tsh[NTAB];
    __shared__ float2 lsh[32];

    const int b  = blockIdx.z;
    const int h  = blockIdx.y;
    const int q0 = blockIdx.x * 64;
    const int tid = threadIdx.x;
    const int r    = tid >> 1;
    const int half = tid & 1;
    const int halfOfs = half * 36;
    const int q  = q0 + r;

    for (int i = tid; i < NTAB; i += 128) tsh[i] = g_tab[h * NTAB + i];

    float4 qreg[8];
    {
        const float* qrow = &g_qp[((size_t)b * QL + q) * DMOD + h * DH + half * 32];
#pragma unroll
        for (int j = 0; j < 8; j++) qreg[j] = *(const float4*)&qrow[j * 4];
    }
    float2 ql = *(const float2*)&qlocs[((size_t)b * QL + q) * 2];

    const int vlen = vlens[b];

    float4 acc[8];
#pragma unroll
    for (int j = 0; j < 8; j++) acc[j] = make_float4(0.f, 0.f, 0.f, 0.f);
    float m = -CUDART_INF_F;
    float l = 0.f;

    const int rowL = tid >> 2;
    const int g4   = tid & 3;
    const float* kbase_g = &g_kp[(size_t)b * KLEN * DMOD + h * DH];
    const float* vbase_g = &g_vp[(size_t)b * KLEN * DMOD + h * DH];

    const int ntiles = (vlen + 31) >> 5;
    for (int t = 0; t < ntiles; t++) {
        const int kb = t * 32;
        __syncthreads();
#pragma unroll
        for (int jj = 0; jj < 4; jj++) {
            int col  = (g4 + jj * 4) * 4;
            int colp = col + ((col >> 5) << 2);
            *(float4*)&ksh[rowL * KPAD + colp] =
                *(const float4*)&kbase_g[(size_t)(kb + rowL) * DMOD + col];
            *(float4*)&vsh[rowL * KPAD + colp] =
                *(const float4*)&vbase_g[(size_t)(kb + rowL) * DMOD + col];
        }
        if (tid < 32)
            lsh[tid] = *(const float2*)&klocs[((size_t)b * KLEN + kb + tid) * 2];
        __syncthreads();

        const int kmax = min(32, vlen - kb);
        if (kmax == 32) {
#pragma unroll 4
            for (int kk = 0; kk < 32; kk++)
                attn_step(kk, qreg, acc, m, l, ksh, vsh, tsh, lsh, ql.x, ql.y, halfOfs);
        } else {
            for (int kk = 0; kk < kmax; kk++)
                attn_step(kk, qreg, acc, m, l, ksh, vsh, tsh, lsh, ql.x, ql.y, halfOfs);
        }
    }

    float inv = 1.0f / l;
    float* crow = &g_ctx[((size_t)b * QL + q) * DMOD + h * DH + half * 32];
#pragma unroll
    for (int j = 0; j < 8; j++) {
        float4 o;
        o.x = acc[j].x * inv;
        o.y = acc[j].y * inv;
        o.z = acc[j].z * inv;
        o.w = acc[j].w * inv;
        *(float4*)&crow[j * 4] = o;
    }
}

// ---------------------------------------------------------------------------
// Launch
// ---------------------------------------------------------------------------
extern "C" void kernel_launch(void* const* d_in, const int* in_sizes, int n_in,
                              void* d_out, int out_size)
{
    const float* qs    = (const float*)d_in[0];
    const float* ks    = (const float*)d_in[1];
    const float* vs    = (const float*)d_in[2];
    const float* qlocs = (const float*)d_in[3];
    const float* klocs = (const float*)d_in[4];
    const float* Wq    = (const float*)d_in[5];
    const float* bq    = (const float*)d_in[6];
    const float* Wk    = (const float*)d_in[7];
    const float* bk    = (const float*)d_in[8];
    const float* Wv    = (const float*)d_in[9];
    const float* bv    = (const float*)d_in[10];
    const float* Wo    = (const float*)d_in[11];
    const float* bo    = (const float*)d_in[12];
    const float* ap    = (const float*)d_in[13];
    const float* bp    = (const float*)d_in[14];
    const float* cp    = (const float*)d_in[15];
    const int*   vl    = (const int*)  d_in[16];
    float* out = (float*)d_out;

    float *qp, *kp, *vp, *ctx;
    cudaGetSymbolAddress((void**)&qp,  g_qp);
    cudaGetSymbolAddress((void**)&kp,  g_kp);
    cudaGetSymbolAddress((void**)&vp,  g_vp);
    cudaGetSymbolAddress((void**)&ctx, g_ctx);

    build_table_kernel<<<(NH * NTAB + 255) / 256, 256>>>(ap, bp, cp);

    dim3 ggrid(DMOD / 128, (BB * QL) / 128);   // (4, 32) = 128 CTAs
    gemm_mma_kernel<<<ggrid, 256>>>(qs, Wq, bq, qp, 0.125f);
    gemm_mma_kernel<<<ggrid, 256>>>(ks, Wk, bk, kp, 1.0f);
    gemm_mma_kernel<<<ggrid, 256>>>(vs, Wv, bv, vp, 1.0f);

    dim3 agrid(QL / 64, NH, BB);
    attn_kernel<<<agrid, 128>>>(qlocs, klocs, vl);

    gemm_mma_kernel<<<ggrid, 256>>>(ctx, Wo, bo, out, 1.0f);
}

// round 5
// speedup vs baseline: 2.3417x; 1.9525x over previous
#include <cuda_runtime.h>
#include <math.h>
#include <math_constants.h>
#include <cstdint>

// ---------------------------------------------------------------------------
// Problem constants
// ---------------------------------------------------------------------------
#define BB   2
#define QL   2048
#define KLEN 2048
#define DMOD 512
#define NH   8
#define NF   5
#define DH   64
#define NTAB 1024

static const float TAB_SCALE = (float)(NTAB - 1) / 14.2f;

// ---------------------------------------------------------------------------
// Device scratch
// ---------------------------------------------------------------------------
__device__ float  g_qp [BB * QL   * DMOD];
__device__ float  g_kp [BB * KLEN * DMOD];
__device__ float  g_vp [BB * KLEN * DMOD];
__device__ float  g_ctx[BB * QL   * DMOD];
__device__ float2 g_tab[NH * NTAB];

// ---------------------------------------------------------------------------
// Helpers
// ---------------------------------------------------------------------------
__device__ __forceinline__ uint32_t f2tf32(float x) {
    uint32_t r;
    asm("cvt.rna.tf32.f32 %0, %1;" : "=r"(r) : "f"(x));
    return r;
}
__device__ __forceinline__ float cvt_tf32f(float x) {
    return __uint_as_float(f2tf32(x));
}

__device__ __forceinline__ void mma_tf32(float* c, const uint32_t* a, const uint32_t* b) {
    asm volatile("mma.sync.aligned.m16n8k8.row.col.f32.tf32.tf32.f32 "
                 "{%0,%1,%2,%3}, {%4,%5,%6,%7}, {%8,%9}, {%0,%1,%2,%3};"
                 : "+f"(c[0]), "+f"(c[1]), "+f"(c[2]), "+f"(c[3])
                 : "r"(a[0]), "r"(a[1]), "r"(a[2]), "r"(a[3]),
                   "r"(b[0]), "r"(b[1]));
}

// ---------------------------------------------------------------------------
// Bias table
// ---------------------------------------------------------------------------
__global__ void build_table_kernel(const float* __restrict__ A,
                                   const float* __restrict__ Bp,
                                   const float* __restrict__ C)
{
    int idx = blockIdx.x * blockDim.x + threadIdx.x;
    if (idx >= NH * NTAB) return;
    int h = idx / NTAB;
    int i = idx - h * NTAB;
    const float STEP = 14.2f / (float)(NTAB - 1);
    float d0 = (float)i * STEP;
    float d1 = d0 + STEP;
    float v0 = 0.f, v1 = 0.f;
#pragma unroll
    for (int f = 0; f < NF; f++) {
        float af = A [h * NF + f];
        float bf = fabsf(Bp[h * NF + f]);
        float cf = C [h * NF + f];
        float t0 = d0 - cf;
        float t1 = d1 - cf;
        v0 += af * expf(-bf * t0 * t0);
        v1 += af * expf(-bf * t1 * t1);
    }
    g_tab[idx] = make_float2(v0, v1 - v0);
}

// ---------------------------------------------------------------------------
// tf32 mma.sync GEMM (unchanged, proven 30.6us/launch)
// ---------------------------------------------------------------------------
#define APAD 36
#define BPAD 136

__global__ __launch_bounds__(256)
void gemm_mma_kernel(const float* __restrict__ A,
                     const float* __restrict__ W,
                     const float* __restrict__ bias,
                     float* __restrict__ Cout,
                     float scale)
{
    __shared__ float sA[128 * APAD];
    __shared__ float sB[32 * BPAD];

    const int tid  = threadIdx.x;
    const int lane = tid & 31;
    const int w    = tid >> 5;
    const int m_off = (w >> 1) * 32;
    const int n_off = (w & 1) * 64;
    const int m0 = blockIdx.y * 128;
    const int n0 = blockIdx.x * 128;

    const int lq = lane >> 2;
    const int lr = lane & 3;

    float c[2][8][4];
#pragma unroll
    for (int i = 0; i < 2; i++)
#pragma unroll
        for (int j = 0; j < 8; j++)
#pragma unroll
            for (int e = 0; e < 4; e++) c[i][j][e] = 0.f;

    for (int ch = 0; ch < 16; ch++) {
        const int kc0 = ch * 32;
        __syncthreads();
#pragma unroll
        for (int i = 0; i < 4; i++) {
            int e = tid + i * 256;
            int ra = e >> 3, ca = e & 7;
            float4 v = *(const float4*)&A[(size_t)(m0 + ra) * DMOD + kc0 + ca * 4];
            float4 t = make_float4(cvt_tf32f(v.x), cvt_tf32f(v.y),
                                   cvt_tf32f(v.z), cvt_tf32f(v.w));
            *(float4*)&sA[ra * APAD + ca * 4] = t;
            int kb = e >> 5, cb = e & 31;
            float4 u = *(const float4*)&W[(size_t)(kc0 + kb) * DMOD + n0 + cb * 4];
            float4 s = make_float4(cvt_tf32f(u.x), cvt_tf32f(u.y),
                                   cvt_tf32f(u.z), cvt_tf32f(u.w));
            *(float4*)&sB[kb * BPAD + cb * 4] = s;
        }
        __syncthreads();
#pragma unroll
        for (int ks = 0; ks < 4; ks++) {
            const int k0 = ks * 8;
            uint32_t a[2][4], b[8][2];
#pragma unroll
            for (int i = 0; i < 2; i++) {
                int r = m_off + i * 16 + lq;
                a[i][0] = __float_as_uint(sA[(r    ) * APAD + k0 + lr    ]);
                a[i][1] = __float_as_uint(sA[(r + 8) * APAD + k0 + lr    ]);
                a[i][2] = __float_as_uint(sA[(r    ) * APAD + k0 + lr + 4]);
                a[i][3] = __float_as_uint(sA[(r + 8) * APAD + k0 + lr + 4]);
            }
#pragma unroll
            for (int j = 0; j < 8; j++) {
                int n = n_off + j * 8 + lq;
                b[j][0] = __float_as_uint(sB[(k0 + lr    ) * BPAD + n]);
                b[j][1] = __float_as_uint(sB[(k0 + lr + 4) * BPAD + n]);
            }
#pragma unroll
            for (int i = 0; i < 2; i++)
#pragma unroll
                for (int j = 0; j < 8; j++)
                    mma_tf32(c[i][j], a[i], b[j]);
        }
    }

#pragma unroll
    for (int i = 0; i < 2; i++) {
        int row = m0 + m_off + i * 16 + lq;
#pragma unroll
        for (int j = 0; j < 8; j++) {
            int col = n0 + n_off + j * 8 + 2 * lr;
            float b0 = bias[col], b1 = bias[col + 1];
            float2 o0 = make_float2((c[i][j][0] + b0) * scale,
                                    (c[i][j][1] + b1) * scale);
            *(float2*)&Cout[(size_t)row * DMOD + col] = o0;
            float2 o1 = make_float2((c[i][j][2] + b0) * scale,
                                    (c[i][j][3] + b1) * scale);
            *(float2*)&Cout[(size_t)(row + 8) * DMOD + col] = o1;
        }
    }
}

// ---------------------------------------------------------------------------
// Tensor-core flash attention.
// CTA: 64 q-rows, 4 warps (16 rows each), 128 threads. Key tiles of 64.
// S = Q K^T via m16n8k8 tf32 (A=Q regs, B=K smem); bias+mask+online softmax
// on C-frags; P permuted to A-frag layout via quad shuffles; O += P V.
// ---------------------------------------------------------------------------
#define KT   64
#define KSTR 68   // K/Q smem stride: b-frag banks 4g+t -> bijective
#define VSTR 72   // V smem stride:   b-frag banks 8t+g -> bijective

__global__ __launch_bounds__(128)
void attn_tc_kernel(const float* __restrict__ qlocs,
                    const float* __restrict__ klocs,
                    const int*   __restrict__ vlens)
{
    __shared__ float  sK[KT * KSTR];   // also stages Q
    __shared__ float  sV[KT * VSTR];
    __shared__ float2 tsh[NTAB];
    __shared__ float2 lsh[KT];

    const int b   = blockIdx.z;
    const int h   = blockIdx.y;
    const int q0  = blockIdx.x * 64;
    const int tid = threadIdx.x;
    const int lane = tid & 31;
    const int w    = tid >> 5;
    const int g    = lane >> 2;   // 0..7
    const int t    = lane & 3;    // 0..3
    const int r0   = w * 16 + g;  // this thread's first q-row in CTA tile

    // stage bias table
    for (int i = tid; i < NTAB; i += 128) tsh[i] = g_tab[h * NTAB + i];

    // ---- stage Q tile (fp32) into sK, then pull tf32 a-frags to regs ----
    {
        const float* qg = &g_qp[((size_t)(b * QL + q0)) * DMOD + h * DH];
#pragma unroll
        for (int halfr = 0; halfr < 2; halfr++) {
            int r = (tid >> 2) + halfr * 32;
#pragma unroll
            for (int jj = 0; jj < 4; jj++) {
                int col = (tid & 3) * 16 + jj * 4;
                *(float4*)&sK[r * KSTR + col] =
                    *(const float4*)&qg[(size_t)r * DMOD + col];
            }
        }
    }
    __syncthreads();

    uint32_t qa[8][4];
#pragma unroll
    for (int ks = 0; ks < 8; ks++) {
        int k = ks * 8;
        qa[ks][0] = f2tf32(sK[(r0    ) * KSTR + k + t    ]);
        qa[ks][1] = f2tf32(sK[(r0 + 8) * KSTR + k + t    ]);
        qa[ks][2] = f2tf32(sK[(r0    ) * KSTR + k + t + 4]);
        qa[ks][3] = f2tf32(sK[(r0 + 8) * KSTR + k + t + 4]);
    }
    float2 ql0 = *(const float2*)&qlocs[((size_t)(b * QL + q0 + r0)) * 2];
    float2 ql1 = *(const float2*)&qlocs[((size_t)(b * QL + q0 + r0 + 8)) * 2];

    const int vlen  = vlens[b];
    const int nfull = vlen >> 6;
    const int rem   = vlen & 63;
    const int ntiles = nfull + (rem ? 1 : 0);

    float o[8][4];
#pragma unroll
    for (int n = 0; n < 8; n++)
#pragma unroll
        for (int e = 0; e < 4; e++) o[n][e] = 0.f;
    float m0 = -CUDART_INF_F, m1 = -CUDART_INF_F;
    float l0 = 0.f, l1 = 0.f;

    const float* kg = &g_kp[(size_t)b * KLEN * DMOD + h * DH];
    const float* vg = &g_vp[(size_t)b * KLEN * DMOD + h * DH];

    for (int tile = 0; tile < ntiles; tile++) {
        const int kb = tile * KT;
        __syncthreads();
        // ---- load K (tf32, [key][dh], stride 68) and V (tf32, stride 72) ----
#pragma unroll
        for (int halfr = 0; halfr < 2; halfr++) {
            int r = (tid >> 2) + halfr * 32;
#pragma unroll
            for (int jj = 0; jj < 4; jj++) {
                int col = (tid & 3) * 16 + jj * 4;
                float4 kv = *(const float4*)&kg[(size_t)(kb + r) * DMOD + col];
                float4 kt = make_float4(cvt_tf32f(kv.x), cvt_tf32f(kv.y),
                                        cvt_tf32f(kv.z), cvt_tf32f(kv.w));
                *(float4*)&sK[r * KSTR + col] = kt;
                float4 vv = *(const float4*)&vg[(size_t)(kb + r) * DMOD + col];
                float4 vt = make_float4(cvt_tf32f(vv.x), cvt_tf32f(vv.y),
                                        cvt_tf32f(vv.z), cvt_tf32f(vv.w));
                *(float4*)&sV[r * VSTR + col] = vt;
            }
        }
        if (tid < KT)
            lsh[tid] = *(const float2*)&klocs[((size_t)(b * KLEN + kb + tid)) * 2];
        __syncthreads();

        // ---- S = Q K^T ----
        float s[8][4];
#pragma unroll
        for (int n = 0; n < 8; n++)
#pragma unroll
            for (int e = 0; e < 4; e++) s[n][e] = 0.f;
#pragma unroll
        for (int ks = 0; ks < 8; ks++) {
            const int k0 = ks * 8;
#pragma unroll
            for (int n = 0; n < 8; n++) {
                uint32_t bf[2];
                bf[0] = __float_as_uint(sK[(n * 8 + g) * KSTR + k0 + t    ]);
                bf[1] = __float_as_uint(sK[(n * 8 + g) * KSTR + k0 + t + 4]);
                mma_tf32(s[n], qa[ks], bf);
            }
        }

        // ---- bias + mask + tile row-max ----
        const bool edge = (rem != 0) && (tile == nfull);
        float tmax0 = -CUDART_INF_F, tmax1 = -CUDART_INF_F;
#pragma unroll
        for (int n = 0; n < 8; n++) {
            int c0 = n * 8 + 2 * t;
            float2 kl0 = lsh[c0];
            float2 kl1 = lsh[c0 + 1];
            // row r0 vs col c0/c0+1
            float dx, dy, dist, tp, fr;
            int ti;
            float2 tv;

            dx = ql0.x - kl0.x; dy = ql0.y - kl0.y;
            dist = sqrtf(fmaf(dx, dx, dy * dy));
            tp = dist * TAB_SCALE; ti = min((int)tp, NTAB - 2); fr = tp - (float)ti;
            tv = tsh[ti];
            s[n][0] += fmaf(fr, tv.y, tv.x);

            dx = ql0.x - kl1.x; dy = ql0.y - kl1.y;
            dist = sqrtf(fmaf(dx, dx, dy * dy));
            tp = dist * TAB_SCALE; ti = min((int)tp, NTAB - 2); fr = tp - (float)ti;
            tv = tsh[ti];
            s[n][1] += fmaf(fr, tv.y, tv.x);

            dx = ql1.x - kl0.x; dy = ql1.y - kl0.y;
            dist = sqrtf(fmaf(dx, dx, dy * dy));
            tp = dist * TAB_SCALE; ti = min((int)tp, NTAB - 2); fr = tp - (float)ti;
            tv = tsh[ti];
            s[n][2] += fmaf(fr, tv.y, tv.x);

            dx = ql1.x - kl1.x; dy = ql1.y - kl1.y;
            dist = sqrtf(fmaf(dx, dx, dy * dy));
            tp = dist * TAB_SCALE; ti = min((int)tp, NTAB - 2); fr = tp - (float)ti;
            tv = tsh[ti];
            s[n][3] += fmaf(fr, tv.y, tv.x);

            if (edge) {
                if (kb + c0     >= vlen) { s[n][0] = -CUDART_INF_F; s[n][2] = -CUDART_INF_F; }
                if (kb + c0 + 1 >= vlen) { s[n][1] = -CUDART_INF_F; s[n][3] = -CUDART_INF_F; }
            }
            tmax0 = fmaxf(tmax0, fmaxf(s[n][0], s[n][1]));
            tmax1 = fmaxf(tmax1, fmaxf(s[n][2], s[n][3]));
        }
        tmax0 = fmaxf(tmax0, __shfl_xor_sync(0xffffffffu, tmax0, 1));
        tmax0 = fmaxf(tmax0, __shfl_xor_sync(0xffffffffu, tmax0, 2));
        tmax1 = fmaxf(tmax1, __shfl_xor_sync(0xffffffffu, tmax1, 1));
        tmax1 = fmaxf(tmax1, __shfl_xor_sync(0xffffffffu, tmax1, 2));

        // ---- online softmax update ----
        float mn0 = fmaxf(m0, tmax0), mn1 = fmaxf(m1, tmax1);
        float cor0 = __expf(m0 - mn0), cor1 = __expf(m1 - mn1);
        m0 = mn0; m1 = mn1;
        float rs0 = 0.f, rs1 = 0.f;
#pragma unroll
        for (int n = 0; n < 8; n++) {
            s[n][0] = __expf(s[n][0] - mn0);
            s[n][1] = __expf(s[n][1] - mn0);
            s[n][2] = __expf(s[n][2] - mn1);
            s[n][3] = __expf(s[n][3] - mn1);
            rs0 += s[n][0] + s[n][1];
            rs1 += s[n][2] + s[n][3];
        }
        rs0 += __shfl_xor_sync(0xffffffffu, rs0, 1);
        rs0 += __shfl_xor_sync(0xffffffffu, rs0, 2);
        rs1 += __shfl_xor_sync(0xffffffffu, rs1, 1);
        rs1 += __shfl_xor_sync(0xffffffffu, rs1, 2);
        l0 = l0 * cor0 + rs0;
        l1 = l1 * cor1 + rs1;
#pragma unroll
        for (int n = 0; n < 8; n++) {
            o[n][0] *= cor0; o[n][1] *= cor0;
            o[n][2] *= cor1; o[n][3] *= cor1;
        }

        // ---- O += P V ----
        const int qb   = lane & ~3;         // quad base lane
        const int src0 = qb + (t >> 1);     // holds col t (as 2t' or 2t'+1)
        const int src1 = src0 + 2;          // holds col t+4
        const bool odd = (t & 1);
#pragma unroll
        for (int ks = 0; ks < 8; ks++) {
            float e00 = __shfl_sync(0xffffffffu, s[ks][0], src0);
            float e01 = __shfl_sync(0xffffffffu, s[ks][1], src0);
            float e10 = __shfl_sync(0xffffffffu, s[ks][2], src0);
            float e11 = __shfl_sync(0xffffffffu, s[ks][3], src0);
            float f00 = __shfl_sync(0xffffffffu, s[ks][0], src1);
            float f01 = __shfl_sync(0xffffffffu, s[ks][1], src1);
            float f10 = __shfl_sync(0xffffffffu, s[ks][2], src1);
            float f11 = __shfl_sync(0xffffffffu, s[ks][3], src1);
            uint32_t pf[4];
            pf[0] = f2tf32(odd ? e01 : e00);   // (row g,   k=t)
            pf[1] = f2tf32(odd ? e11 : e10);   // (row g+8, k=t)
            pf[2] = f2tf32(odd ? f01 : f00);   // (row g,   k=t+4)
            pf[3] = f2tf32(odd ? f11 : f10);   // (row g+8, k=t+4)
            const int k0 = ks * 8;
#pragma unroll
            for (int n = 0; n < 8; n++) {
                uint32_t bf[2];
                bf[0] = __float_as_uint(sV[(k0 + t    ) * VSTR + n * 8 + g]);
                bf[1] = __float_as_uint(sV[(k0 + t + 4) * VSTR + n * 8 + g]);
                mma_tf32(o[n], pf, bf);
            }
        }
    }

    // ---- epilogue: normalize, store ctx ----
    float inv0 = 1.0f / l0;
    float inv1 = 1.0f / l1;
    float* op = &g_ctx[((size_t)(b * QL + q0 + r0)) * DMOD + h * DH];
#pragma unroll
    for (int n = 0; n < 8; n++) {
        int col = n * 8 + 2 * t;
        float2 v0 = make_float2(o[n][0] * inv0, o[n][1] * inv0);
        *(float2*)&op[col] = v0;
        float2 v1 = make_float2(o[n][2] * inv1, o[n][3] * inv1);
        *(float2*)&op[(size_t)8 * DMOD + col] = v1;
    }
}

// ---------------------------------------------------------------------------
// Launch
// ---------------------------------------------------------------------------
extern "C" void kernel_launch(void* const* d_in, const int* in_sizes, int n_in,
                              void* d_out, int out_size)
{
    const float* qs    = (const float*)d_in[0];
    const float* ks    = (const float*)d_in[1];
    const float* vs    = (const float*)d_in[2];
    const float* qlocs = (const float*)d_in[3];
    const float* klocs = (const float*)d_in[4];
    const float* Wq    = (const float*)d_in[5];
    const float* bq    = (const float*)d_in[6];
    const float* Wk    = (const float*)d_in[7];
    const float* bk    = (const float*)d_in[8];
    const float* Wv    = (const float*)d_in[9];
    const float* bv    = (const float*)d_in[10];
    const float* Wo    = (const float*)d_in[11];
    const float* bo    = (const float*)d_in[12];
    const float* ap    = (const float*)d_in[13];
    const float* bp    = (const float*)d_in[14];
    const float* cp    = (const float*)d_in[15];
    const int*   vl    = (const int*)  d_in[16];
    float* out = (float*)d_out;

    float *qp, *kp, *vp, *ctx;
    cudaGetSymbolAddress((void**)&qp,  g_qp);
    cudaGetSymbolAddress((void**)&kp,  g_kp);
    cudaGetSymbolAddress((void**)&vp,  g_vp);
    cudaGetSymbolAddress((void**)&ctx, g_ctx);

    build_table_kernel<<<(NH * NTAB + 255) / 256, 256>>>(ap, bp, cp);

    dim3 ggrid(DMOD / 128, (BB * QL) / 128);
    gemm_mma_kernel<<<ggrid, 256>>>(qs, Wq, bq, qp, 0.125f);
    gemm_mma_kernel<<<ggrid, 256>>>(ks, Wk, bk, kp, 1.0f);
    gemm_mma_kernel<<<ggrid, 256>>>(vs, Wv, bv, vp, 1.0f);

    dim3 agrid(QL / 64, NH, BB);
    attn_tc_kernel<<<agrid, 128>>>(qlocs, klocs, vl);

    gemm_mma_kernel<<<ggrid, 256>>>(ctx, Wo, bo, out, 1.0f);
}

// round 6
// speedup vs baseline: 3.1902x; 1.3623x over previous
#include <cuda_runtime.h>
#include <math.h>
#include <math_constants.h>
#include <cstdint>

// ---------------------------------------------------------------------------
// Problem constants
// ---------------------------------------------------------------------------
#define BB   2
#define QL   2048
#define KLEN 2048
#define DMOD 512
#define NH   8
#define NF   5
#define DH   64
#define NTAB 1024

static const float TAB_SCALE = (float)(NTAB - 1) / 14.2f;

// ---------------------------------------------------------------------------
// Device scratch
// ---------------------------------------------------------------------------
__device__ float  g_qp [BB * QL   * DMOD];
__device__ float  g_kp [BB * KLEN * DMOD];
__device__ float  g_vp [BB * KLEN * DMOD];
__device__ float  g_ctx[BB * QL   * DMOD];
__device__ float2 g_tab[NH * NTAB];

// ---------------------------------------------------------------------------
// Helpers
// ---------------------------------------------------------------------------
__device__ __forceinline__ uint32_t f2tf32(float x) {
    uint32_t r;
    asm("cvt.rna.tf32.f32 %0, %1;" : "=r"(r) : "f"(x));
    return r;
}
__device__ __forceinline__ float cvt_tf32f(float x) {
    return __uint_as_float(f2tf32(x));
}

__device__ __forceinline__ void mma_tf32(float* c, const uint32_t* a, const uint32_t* b) {
    asm volatile("mma.sync.aligned.m16n8k8.row.col.f32.tf32.tf32.f32 "
                 "{%0,%1,%2,%3}, {%4,%5,%6,%7}, {%8,%9}, {%0,%1,%2,%3};"
                 : "+f"(c[0]), "+f"(c[1]), "+f"(c[2]), "+f"(c[3])
                 : "r"(a[0]), "r"(a[1]), "r"(a[2]), "r"(a[3]),
                   "r"(b[0]), "r"(b[1]));
}

__device__ __forceinline__ uint32_t sptr(const void* p) {
    return (uint32_t)__cvta_generic_to_shared(p);
}
__device__ __forceinline__ void cp16(uint32_t smem_addr, const void* gptr) {
    asm volatile("cp.async.cg.shared.global [%0], [%1], 16;"
                 :: "r"(smem_addr), "l"(gptr) : "memory");
}
__device__ __forceinline__ void cp_commit() {
    asm volatile("cp.async.commit_group;" ::: "memory");
}
template <int N>
__device__ __forceinline__ void cp_wait() {
    asm volatile("cp.async.wait_group %0;" :: "n"(N) : "memory");
}

// ---------------------------------------------------------------------------
// Bias table
// ---------------------------------------------------------------------------
__global__ void build_table_kernel(const float* __restrict__ A,
                                   const float* __restrict__ Bp,
                                   const float* __restrict__ C)
{
    int idx = blockIdx.x * blockDim.x + threadIdx.x;
    if (idx >= NH * NTAB) return;
    int h = idx / NTAB;
    int i = idx - h * NTAB;
    const float STEP = 14.2f / (float)(NTAB - 1);
    float d0 = (float)i * STEP;
    float d1 = d0 + STEP;
    float v0 = 0.f, v1 = 0.f;
#pragma unroll
    for (int f = 0; f < NF; f++) {
        float af = A [h * NF + f];
        float bf = fabsf(Bp[h * NF + f]);
        float cf = C [h * NF + f];
        float t0 = d0 - cf;
        float t1 = d1 - cf;
        v0 += af * expf(-bf * t0 * t0);
        v1 += af * expf(-bf * t1 * t1);
    }
    g_tab[idx] = make_float2(v0, v1 - v0);
}

// ---------------------------------------------------------------------------
// tf32 mma.sync GEMM body. ROUND: round output to tf32 (for Q/K/V feeding
// the attention MMAs -- saves all cvt work in the attention hot loop).
// ---------------------------------------------------------------------------
#define APAD 36
#define BPAD 136

template <bool ROUND>
__device__ __forceinline__ void gemm_body(const float* __restrict__ A,
                                          const float* __restrict__ W,
                                          const float* __restrict__ bias,
                                          float* __restrict__ Cout,
                                          float scale)
{
    __shared__ float sA[128 * APAD];
    __shared__ float sB[32 * BPAD];

    const int tid  = threadIdx.x;
    const int lane = tid & 31;
    const int wrp  = tid >> 5;
    const int m_off = (wrp >> 1) * 32;
    const int n_off = (wrp & 1) * 64;
    const int m0 = blockIdx.y * 128;
    const int n0 = blockIdx.x * 128;

    const int lq = lane >> 2;
    const int lr = lane & 3;

    float c[2][8][4];
#pragma unroll
    for (int i = 0; i < 2; i++)
#pragma unroll
        for (int j = 0; j < 8; j++)
#pragma unroll
            for (int e = 0; e < 4; e++) c[i][j][e] = 0.f;

    for (int ch = 0; ch < 16; ch++) {
        const int kc0 = ch * 32;
        __syncthreads();
#pragma unroll
        for (int i = 0; i < 4; i++) {
            int e = tid + i * 256;
            int ra = e >> 3, ca = e & 7;
            float4 v = *(const float4*)&A[(size_t)(m0 + ra) * DMOD + kc0 + ca * 4];
            float4 t = make_float4(cvt_tf32f(v.x), cvt_tf32f(v.y),
                                   cvt_tf32f(v.z), cvt_tf32f(v.w));
            *(float4*)&sA[ra * APAD + ca * 4] = t;
            int kb = e >> 5, cb = e & 31;
            float4 u = *(const float4*)&W[(size_t)(kc0 + kb) * DMOD + n0 + cb * 4];
            float4 s = make_float4(cvt_tf32f(u.x), cvt_tf32f(u.y),
                                   cvt_tf32f(u.z), cvt_tf32f(u.w));
            *(float4*)&sB[kb * BPAD + cb * 4] = s;
        }
        __syncthreads();
#pragma unroll
        for (int ks = 0; ks < 4; ks++) {
            const int k0 = ks * 8;
            uint32_t a[2][4], b[8][2];
#pragma unroll
            for (int i = 0; i < 2; i++) {
                int r = m_off + i * 16 + lq;
                a[i][0] = __float_as_uint(sA[(r    ) * APAD + k0 + lr    ]);
                a[i][1] = __float_as_uint(sA[(r + 8) * APAD + k0 + lr    ]);
                a[i][2] = __float_as_uint(sA[(r    ) * APAD + k0 + lr + 4]);
                a[i][3] = __float_as_uint(sA[(r + 8) * APAD + k0 + lr + 4]);
            }
#pragma unroll
            for (int j = 0; j < 8; j++) {
                int n = n_off + j * 8 + lq;
                b[j][0] = __float_as_uint(sB[(k0 + lr    ) * BPAD + n]);
                b[j][1] = __float_as_uint(sB[(k0 + lr + 4) * BPAD + n]);
            }
#pragma unroll
            for (int i = 0; i < 2; i++)
#pragma unroll
                for (int j = 0; j < 8; j++)
                    mma_tf32(c[i][j], a[i], b[j]);
        }
    }

#pragma unroll
    for (int i = 0; i < 2; i++) {
        int row = m0 + m_off + i * 16 + lq;
#pragma unroll
        for (int j = 0; j < 8; j++) {
            int col = n0 + n_off + j * 8 + 2 * lr;
            float b0 = bias[col], b1 = bias[col + 1];
            float v00 = (c[i][j][0] + b0) * scale;
            float v01 = (c[i][j][1] + b1) * scale;
            float v10 = (c[i][j][2] + b0) * scale;
            float v11 = (c[i][j][3] + b1) * scale;
            if (ROUND) {
                v00 = cvt_tf32f(v00); v01 = cvt_tf32f(v01);
                v10 = cvt_tf32f(v10); v11 = cvt_tf32f(v11);
            }
            *(float2*)&Cout[(size_t)row * DMOD + col] = make_float2(v00, v01);
            *(float2*)&Cout[(size_t)(row + 8) * DMOD + col] = make_float2(v10, v11);
        }
    }
}

// Fused Q/K/V projection: grid.z selects which projection this CTA computes.
__global__ __launch_bounds__(256)
void gemm_qkv_kernel(const float* __restrict__ qs, const float* __restrict__ ks,
                     const float* __restrict__ vs,
                     const float* __restrict__ Wq, const float* __restrict__ Wk,
                     const float* __restrict__ Wv,
                     const float* __restrict__ bq, const float* __restrict__ bk,
                     const float* __restrict__ bv,
                     float* __restrict__ qp, float* __restrict__ kp,
                     float* __restrict__ vp)
{
    const int z = blockIdx.z;
    const float* A = (z == 0) ? qs : (z == 1) ? ks : vs;
    const float* W = (z == 0) ? Wq : (z == 1) ? Wk : Wv;
    const float* B = (z == 0) ? bq : (z == 1) ? bk : bv;
    float*       C = (z == 0) ? qp : (z == 1) ? kp : vp;
    const float  s = (z == 0) ? 0.125f : 1.0f;
    gemm_body<true>(A, W, B, C, s);
}

__global__ __launch_bounds__(256)
void gemm_out_kernel(const float* __restrict__ A, const float* __restrict__ W,
                     const float* __restrict__ bias, float* __restrict__ Cout)
{
    gemm_body<false>(A, W, bias, Cout, 1.0f);
}

// ---------------------------------------------------------------------------
// Tensor-core flash attention, cp.async 2-stage pipeline.
// CTA: 64 q-rows, 4 warps. Key tiles of 32, double-buffered K/V/klocs.
// K/V/Q in global are PRE-ROUNDED tf32 (gemm epilogue) -> pure byte copies.
// ---------------------------------------------------------------------------
#define KT   32
#define KSTR 68   // b-frag banks 4g+t -> bijective
#define VSTR 72   // b-frag banks 8t+g -> bijective

__global__ __launch_bounds__(128)
void attn_tc_kernel(const float* __restrict__ qlocs,
                    const float* __restrict__ klocs,
                    const int*   __restrict__ vlens)
{
    __shared__ float  sK[2][KT * KSTR];   // stage 0+1 contiguous: also stages Q (64 rows)
    __shared__ float  sV[2][KT * VSTR];
    __shared__ float2 tsh[NTAB];
    __shared__ float2 lsh[2][KT];

    const int b   = blockIdx.z;
    const int h   = blockIdx.y;
    const int q0  = blockIdx.x * 64;
    const int tid = threadIdx.x;
    const int lane = tid & 31;
    const int w    = tid >> 5;
    const int g    = lane >> 2;
    const int t    = lane & 3;
    const int r0   = w * 16 + g;

    for (int i = tid; i < NTAB; i += 128) tsh[i] = g_tab[h * NTAB + i];

    // ---- stage Q (pre-rounded tf32) across both sK stages, pull a-frags ----
    {
        const float* qg = &g_qp[((size_t)(b * QL + q0)) * DMOD + h * DH];
        float* sQ = &sK[0][0];
        int rq = tid >> 1, cq = (tid & 1) * 32;
#pragma unroll
        for (int jj = 0; jj < 8; jj++)
            *(float4*)&sQ[rq * KSTR + cq + jj * 4] =
                *(const float4*)&qg[(size_t)rq * DMOD + cq + jj * 4];
    }
    __syncthreads();

    uint32_t qa[8][4];
    {
        const float* sQ = &sK[0][0];
#pragma unroll
        for (int ks = 0; ks < 8; ks++) {
            int k = ks * 8;
            qa[ks][0] = __float_as_uint(sQ[(r0    ) * KSTR + k + t    ]);
            qa[ks][1] = __float_as_uint(sQ[(r0 + 8) * KSTR + k + t    ]);
            qa[ks][2] = __float_as_uint(sQ[(r0    ) * KSTR + k + t + 4]);
            qa[ks][3] = __float_as_uint(sQ[(r0 + 8) * KSTR + k + t + 4]);
        }
    }
    float2 ql0 = *(const float2*)&qlocs[((size_t)(b * QL + q0 + r0)) * 2];
    float2 ql1 = *(const float2*)&qlocs[((size_t)(b * QL + q0 + r0 + 8)) * 2];
    __syncthreads();   // Q frags extracted; sK reusable

    const int vlen  = vlens[b];
    const int nfull = vlen >> 5;
    const int rem   = vlen & 31;
    const int ntiles = nfull + (rem ? 1 : 0);

    float o[8][4];
#pragma unroll
    for (int n = 0; n < 8; n++)
#pragma unroll
        for (int e = 0; e < 4; e++) o[n][e] = 0.f;
    float m0 = -CUDART_INF_F, m1 = -CUDART_INF_F;
    float l0 = 0.f, l1 = 0.f;

    const float* kg = &g_kp[(size_t)b * KLEN * DMOD + h * DH];
    const float* vg = &g_vp[(size_t)b * KLEN * DMOD + h * DH];

    // per-thread prefetch addressing: row tid>>2 (0..31), col (tid&3)*16
    const int pr = tid >> 2;
    const int pc = (tid & 3) * 16;

    // ---- prologue: prefetch tile 0 ----
    {
        const float* kp_ = &kg[(size_t)pr * DMOD + pc];
        const float* vp_ = &vg[(size_t)pr * DMOD + pc];
        uint32_t dk = sptr(&sK[0][pr * KSTR + pc]);
        uint32_t dv = sptr(&sV[0][pr * VSTR + pc]);
#pragma unroll
        for (int jj = 0; jj < 4; jj++) {
            cp16(dk + jj * 16, kp_ + jj * 4);
            cp16(dv + jj * 16, vp_ + jj * 4);
        }
        if (tid < 16)
            cp16(sptr(&lsh[0][0]) + tid * 16,
                 &klocs[((size_t)(b * KLEN)) * 2 + tid * 4]);
        cp_commit();
    }

    for (int tile = 0; tile < ntiles; tile++) {
        const int st = tile & 1;
        const int kb = tile * KT;
        if (tile + 1 < ntiles) {
            const int kb2 = kb + KT;
            const float* kp_ = &kg[(size_t)(kb2 + pr) * DMOD + pc];
            const float* vp_ = &vg[(size_t)(kb2 + pr) * DMOD + pc];
            uint32_t dk = sptr(&sK[st ^ 1][pr * KSTR + pc]);
            uint32_t dv = sptr(&sV[st ^ 1][pr * VSTR + pc]);
#pragma unroll
            for (int jj = 0; jj < 4; jj++) {
                cp16(dk + jj * 16, kp_ + jj * 4);
                cp16(dv + jj * 16, vp_ + jj * 4);
            }
            if (tid < 16)
                cp16(sptr(&lsh[st ^ 1][0]) + tid * 16,
                     &klocs[((size_t)(b * KLEN + kb2)) * 2 + tid * 4]);
            cp_commit();
            cp_wait<1>();
        } else {
            cp_wait<0>();
        }
        __syncthreads();

        const float* sk = sK[st];
        const float* sv = sV[st];
        const float2* sl = lsh[st];

        // ---- S = Q K^T ----
        float s[4][4];
#pragma unroll
        for (int n = 0; n < 4; n++)
#pragma unroll
            for (int e = 0; e < 4; e++) s[n][e] = 0.f;
#pragma unroll
        for (int ks = 0; ks < 8; ks++) {
            const int k0 = ks * 8;
#pragma unroll
            for (int n = 0; n < 4; n++) {
                uint32_t bf[2];
                bf[0] = __float_as_uint(sk[(n * 8 + g) * KSTR + k0 + t    ]);
                bf[1] = __float_as_uint(sk[(n * 8 + g) * KSTR + k0 + t + 4]);
                mma_tf32(s[n], qa[ks], bf);
            }
        }

        // ---- bias + mask + tile row-max ----
        const bool edge = (rem != 0) && (tile == nfull);
        float tmax0 = -CUDART_INF_F, tmax1 = -CUDART_INF_F;
#pragma unroll
        for (int n = 0; n < 4; n++) {
            int c0 = n * 8 + 2 * t;
            float2 kl0 = sl[c0];
            float2 kl1 = sl[c0 + 1];
            float dx, dy, dist, tp, fr;
            int ti;
            float2 tv;

            dx = ql0.x - kl0.x; dy = ql0.y - kl0.y;
            dist = sqrtf(fmaf(dx, dx, dy * dy));
            tp = dist * TAB_SCALE; ti = min((int)tp, NTAB - 2); fr = tp - (float)ti;
            tv = tsh[ti];
            s[n][0] += fmaf(fr, tv.y, tv.x);

            dx = ql0.x - kl1.x; dy = ql0.y - kl1.y;
            dist = sqrtf(fmaf(dx, dx, dy * dy));
            tp = dist * TAB_SCALE; ti = min((int)tp, NTAB - 2); fr = tp - (float)ti;
            tv = tsh[ti];
            s[n][1] += fmaf(fr, tv.y, tv.x);

            dx = ql1.x - kl0.x; dy = ql1.y - kl0.y;
            dist = sqrtf(fmaf(dx, dx, dy * dy));
            tp = dist * TAB_SCALE; ti = min((int)tp, NTAB - 2); fr = tp - (float)ti;
            tv = tsh[ti];
            s[n][2] += fmaf(fr, tv.y, tv.x);

            dx = ql1.x - kl1.x; dy = ql1.y - kl1.y;
            dist = sqrtf(fmaf(dx, dx, dy * dy));
            tp = dist * TAB_SCALE; ti = min((int)tp, NTAB - 2); fr = tp - (float)ti;
            tv = tsh[ti];
            s[n][3] += fmaf(fr, tv.y, tv.x);

            if (edge) {
                if (kb + c0     >= vlen) { s[n][0] = -CUDART_INF_F; s[n][2] = -CUDART_INF_F; }
                if (kb + c0 + 1 >= vlen) { s[n][1] = -CUDART_INF_F; s[n][3] = -CUDART_INF_F; }
            }
            tmax0 = fmaxf(tmax0, fmaxf(s[n][0], s[n][1]));
            tmax1 = fmaxf(tmax1, fmaxf(s[n][2], s[n][3]));
        }
        tmax0 = fmaxf(tmax0, __shfl_xor_sync(0xffffffffu, tmax0, 1));
        tmax0 = fmaxf(tmax0, __shfl_xor_sync(0xffffffffu, tmax0, 2));
        tmax1 = fmaxf(tmax1, __shfl_xor_sync(0xffffffffu, tmax1, 1));
        tmax1 = fmaxf(tmax1, __shfl_xor_sync(0xffffffffu, tmax1, 2));

        // ---- online softmax update ----
        float mn0 = fmaxf(m0, tmax0), mn1 = fmaxf(m1, tmax1);
        float cor0 = __expf(m0 - mn0), cor1 = __expf(m1 - mn1);
        m0 = mn0; m1 = mn1;
        float rs0 = 0.f, rs1 = 0.f;
#pragma unroll
        for (int n = 0; n < 4; n++) {
            s[n][0] = __expf(s[n][0] - mn0);
            s[n][1] = __expf(s[n][1] - mn0);
            s[n][2] = __expf(s[n][2] - mn1);
            s[n][3] = __expf(s[n][3] - mn1);
            rs0 += s[n][0] + s[n][1];
            rs1 += s[n][2] + s[n][3];
        }
        rs0 += __shfl_xor_sync(0xffffffffu, rs0, 1);
        rs0 += __shfl_xor_sync(0xffffffffu, rs0, 2);
        rs1 += __shfl_xor_sync(0xffffffffu, rs1, 1);
        rs1 += __shfl_xor_sync(0xffffffffu, rs1, 2);
        l0 = l0 * cor0 + rs0;
        l1 = l1 * cor1 + rs1;
#pragma unroll
        for (int n = 0; n < 8; n++) {
            o[n][0] *= cor0; o[n][1] *= cor0;
            o[n][2] *= cor1; o[n][3] *= cor1;
        }

        // ---- O += P V ----
        const int qb   = lane & ~3;
        const int src0 = qb + (t >> 1);
        const int src1 = src0 + 2;
        const bool odd = (t & 1);
#pragma unroll
        for (int ks = 0; ks < 4; ks++) {
            float e00 = __shfl_sync(0xffffffffu, s[ks][0], src0);
            float e01 = __shfl_sync(0xffffffffu, s[ks][1], src0);
            float e10 = __shfl_sync(0xffffffffu, s[ks][2], src0);
            float e11 = __shfl_sync(0xffffffffu, s[ks][3], src0);
            float f00 = __shfl_sync(0xffffffffu, s[ks][0], src1);
            float f01 = __shfl_sync(0xffffffffu, s[ks][1], src1);
            float f10 = __shfl_sync(0xffffffffu, s[ks][2], src1);
            float f11 = __shfl_sync(0xffffffffu, s[ks][3], src1);
            uint32_t pf[4];
            pf[0] = f2tf32(odd ? e01 : e00);
            pf[1] = f2tf32(odd ? e11 : e10);
            pf[2] = f2tf32(odd ? f01 : f00);
            pf[3] = f2tf32(odd ? f11 : f10);
            const int k0 = ks * 8;
#pragma unroll
            for (int n = 0; n < 8; n++) {
                uint32_t bf[2];
                bf[0] = __float_as_uint(sv[(k0 + t    ) * VSTR + n * 8 + g]);
                bf[1] = __float_as_uint(sv[(k0 + t + 4) * VSTR + n * 8 + g]);
                mma_tf32(o[n], pf, bf);
            }
        }
        __syncthreads();   // all warps done with this stage before it is re-filled
    }

    // ---- epilogue ----
    float inv0 = 1.0f / l0;
    float inv1 = 1.0f / l1;
    float* op = &g_ctx[((size_t)(b * QL + q0 + r0)) * DMOD + h * DH];
#pragma unroll
    for (int n = 0; n < 8; n++) {
        int col = n * 8 + 2 * t;
        *(float2*)&op[col] = make_float2(o[n][0] * inv0, o[n][1] * inv0);
        *(float2*)&op[(size_t)8 * DMOD + col] = make_float2(o[n][2] * inv1, o[n][3] * inv1);
    }
}

// ---------------------------------------------------------------------------
// Launch
// ---------------------------------------------------------------------------
extern "C" void kernel_launch(void* const* d_in, const int* in_sizes, int n_in,
                              void* d_out, int out_size)
{
    const float* qs    = (const float*)d_in[0];
    const float* ks    = (const float*)d_in[1];
    const float* vs    = (const float*)d_in[2];
    const float* qlocs = (const float*)d_in[3];
    const float* klocs = (const float*)d_in[4];
    const float* Wq    = (const float*)d_in[5];
    const float* bq    = (const float*)d_in[6];
    const float* Wk    = (const float*)d_in[7];
    const float* bk    = (const float*)d_in[8];
    const float* Wv    = (const float*)d_in[9];
    const float* bv    = (const float*)d_in[10];
    const float* Wo    = (const float*)d_in[11];
    const float* bo    = (const float*)d_in[12];
    const float* ap    = (const float*)d_in[13];
    const float* bp    = (const float*)d_in[14];
    const float* cp    = (const float*)d_in[15];
    const int*   vl    = (const int*)  d_in[16];
    float* out = (float*)d_out;

    float *qp, *kp, *vp, *ctx;
    cudaGetSymbolAddress((void**)&qp,  g_qp);
    cudaGetSymbolAddress((void**)&kp,  g_kp);
    cudaGetSymbolAddress((void**)&vp,  g_vp);
    cudaGetSymbolAddress((void**)&ctx, g_ctx);

    build_table_kernel<<<(NH * NTAB + 255) / 256, 256>>>(ap, bp, cp);

    dim3 g3(DMOD / 128, (BB * QL) / 128, 3);   // 384 CTAs, all three projections
    gemm_qkv_kernel<<<g3, 256>>>(qs, ks, vs, Wq, Wk, Wv, bq, bk, bv, qp, kp, vp);

    dim3 agrid(QL / 64, NH, BB);
    attn_tc_kernel<<<agrid, 128>>>(qlocs, klocs, vl);

    dim3 ggrid(DMOD / 128, (BB * QL) / 128);
    gemm_out_kernel<<<ggrid, 256>>>(ctx, Wo, bo, out);
}

// round 9
// speedup vs baseline: 3.2872x; 1.0304x over previous
#include <cuda_runtime.h>
#include <math.h>
#include <math_constants.h>
#include <cstdint>

// ---------------------------------------------------------------------------
// Problem constants
// ---------------------------------------------------------------------------
#define BB   2
#define QL   2048
#define KLEN 2048
#define DMOD 512
#define NH   8
#define NF   5
#define DH   64
#define NTAB 1024

static const float TAB_SCALE = (float)(NTAB - 1) / 14.2f;

// ---------------------------------------------------------------------------
// Device scratch
// ---------------------------------------------------------------------------
__device__ float  g_qp [BB * QL   * DMOD];
__device__ float  g_kp [BB * KLEN * DMOD];
__device__ float  g_vp [BB * KLEN * DMOD];
__device__ float  g_ctx[BB * QL   * DMOD];
__device__ float  g_rq [BB * QL   * DMOD];   // tf32-rounded inputs
__device__ float  g_rk [BB * KLEN * DMOD];
__device__ float  g_rv [BB * KLEN * DMOD];
__device__ float  g_rw [4][DMOD * DMOD];     // tf32-rounded weights
__device__ float2 g_tab[NH * NTAB];

// ---------------------------------------------------------------------------
// Helpers
// ---------------------------------------------------------------------------
__device__ __forceinline__ uint32_t f2tf32(float x) {
    uint32_t r;
    asm("cvt.rna.tf32.f32 %0, %1;" : "=r"(r) : "f"(x));
    return r;
}
__device__ __forceinline__ float cvt_tf32f(float x) {
    return __uint_as_float(f2tf32(x));
}

__device__ __forceinline__ void mma_tf32(float* c, const uint32_t* a, const uint32_t* b) {
    asm volatile("mma.sync.aligned.m16n8k8.row.col.f32.tf32.tf32.f32 "
                 "{%0,%1,%2,%3}, {%4,%5,%6,%7}, {%8,%9}, {%0,%1,%2,%3};"
                 : "+f"(c[0]), "+f"(c[1]), "+f"(c[2]), "+f"(c[3])
                 : "r"(a[0]), "r"(a[1]), "r"(a[2]), "r"(a[3]),
                   "r"(b[0]), "r"(b[1]));
}

__device__ __forceinline__ uint32_t sptr(const void* p) {
    return (uint32_t)__cvta_generic_to_shared(p);
}
__device__ __forceinline__ void cp16(uint32_t smem_addr, const void* gptr) {
    asm volatile("cp.async.cg.shared.global [%0], [%1], 16;"
                 :: "r"(smem_addr), "l"(gptr) : "memory");
}
__device__ __forceinline__ void cp_commit() {
    asm volatile("cp.async.commit_group;" ::: "memory");
}
template <int N>
__device__ __forceinline__ void cp_wait() {
    asm volatile("cp.async.wait_group %0;" :: "n"(N) : "memory");
}

// ---------------------------------------------------------------------------
// Pre-round kernels: tf32-round activations and weights once.
// ---------------------------------------------------------------------------
__global__ __launch_bounds__(256)
void round_acts_kernel(const float* __restrict__ qs,
                       const float* __restrict__ ks,
                       const float* __restrict__ vs)
{
    const int z = blockIdx.y;
    const float* src = (z == 0) ? qs : (z == 1) ? ks : vs;
    float* dst = (z == 0) ? g_rq : (z == 1) ? g_rk : g_rv;
    size_t i = ((size_t)blockIdx.x * blockDim.x + threadIdx.x) * 4;
    if (i >= (size_t)BB * QL * DMOD) return;
    float4 v = *(const float4*)&src[i];
    *(float4*)&dst[i] = make_float4(cvt_tf32f(v.x), cvt_tf32f(v.y),
                                    cvt_tf32f(v.z), cvt_tf32f(v.w));
}

__global__ __launch_bounds__(256)
void round_w_kernel(const float* __restrict__ Wq, const float* __restrict__ Wk,
                    const float* __restrict__ Wv, const float* __restrict__ Wo)
{
    const int z = blockIdx.y;
    const float* src = (z == 0) ? Wq : (z == 1) ? Wk : (z == 2) ? Wv : Wo;
    float* dst = g_rw[z];
    size_t i = ((size_t)blockIdx.x * blockDim.x + threadIdx.x) * 4;
    if (i >= (size_t)DMOD * DMOD) return;
    float4 v = *(const float4*)&src[i];
    *(float4*)&dst[i] = make_float4(cvt_tf32f(v.x), cvt_tf32f(v.y),
                                    cvt_tf32f(v.z), cvt_tf32f(v.w));
}

// ---------------------------------------------------------------------------
// Bias table
// ---------------------------------------------------------------------------
__global__ void build_table_kernel(const float* __restrict__ A,
                                   const float* __restrict__ Bp,
                                   const float* __restrict__ C)
{
    int idx = blockIdx.x * blockDim.x + threadIdx.x;
    if (idx >= NH * NTAB) return;
    int h = idx / NTAB;
    int i = idx - h * NTAB;
    const float STEP = 14.2f / (float)(NTAB - 1);
    float d0 = (float)i * STEP;
    float d1 = d0 + STEP;
    float v0 = 0.f, v1 = 0.f;
#pragma unroll
    for (int f = 0; f < NF; f++) {
        float af = A [h * NF + f];
        float bf = fabsf(Bp[h * NF + f]);
        float cf = C [h * NF + f];
        float t0 = d0 - cf;
        float t1 = d1 - cf;
        v0 += af * expf(-bf * t0 * t0);
        v1 += af * expf(-bf * t1 * t1);
    }
    g_tab[idx] = make_float2(v0, v1 - v0);
}

// ---------------------------------------------------------------------------
// GEMM v2: 128x128 tile, BK=16, 2-stage cp.async, inputs pre-rounded tf32.
// sA stride 20 (banks 20*lq+t bijective); sB stride 136 (banks 8t+g bijective).
// ---------------------------------------------------------------------------
#define GAPAD 20
#define GBPAD 136

template <bool ROUND>
__device__ __forceinline__ void gemm_body(const float* __restrict__ A,
                                          const float* __restrict__ W,
                                          const float* __restrict__ bias,
                                          float* __restrict__ Cout,
                                          float scale)
{
    __shared__ __align__(16) float sA[2][128 * GAPAD];  // 20 KB
    __shared__ __align__(16) float sB[2][16 * GBPAD];   // 17.4 KB

    const int tid  = threadIdx.x;
    const int lane = tid & 31;
    const int wrp  = tid >> 5;
    const int m_off = (wrp >> 1) * 32;
    const int n_off = (wrp & 1) * 64;
    const int m0 = blockIdx.y * 128;
    const int n0 = blockIdx.x * 128;

    const int lq = lane >> 2;
    const int lr = lane & 3;

    // prefetch addressing
    const int ra = tid >> 1;            // A row 0..127
    const int ca = (tid & 1) * 8;       // A col group (2 float4)
    const int rb = tid >> 4;            // B row 0..15
    const int cb = (tid & 15) * 8;      // B col group (2 float4)

    float c[2][8][4];
#pragma unroll
    for (int i = 0; i < 2; i++)
#pragma unroll
        for (int j = 0; j < 8; j++)
#pragma unroll
            for (int e = 0; e < 4; e++) c[i][j][e] = 0.f;

    // prologue: prefetch chunk 0
    {
        cp16(sptr(&sA[0][ra * GAPAD + ca]),     &A[(size_t)(m0 + ra) * DMOD + ca]);
        cp16(sptr(&sA[0][ra * GAPAD + ca + 4]), &A[(size_t)(m0 + ra) * DMOD + ca + 4]);
        cp16(sptr(&sB[0][rb * GBPAD + cb]),     &W[(size_t)rb * DMOD + n0 + cb]);
        cp16(sptr(&sB[0][rb * GBPAD + cb + 4]), &W[(size_t)rb * DMOD + n0 + cb + 4]);
        cp_commit();
    }

    for (int ch = 0; ch < 32; ch++) {
        const int st = ch & 1;
        if (ch + 1 < 32) {
            const int kc = (ch + 1) * 16;
            cp16(sptr(&sA[st ^ 1][ra * GAPAD + ca]),     &A[(size_t)(m0 + ra) * DMOD + kc + ca]);
            cp16(sptr(&sA[st ^ 1][ra * GAPAD + ca + 4]), &A[(size_t)(m0 + ra) * DMOD + kc + ca + 4]);
            cp16(sptr(&sB[st ^ 1][rb * GBPAD + cb]),     &W[(size_t)(kc + rb) * DMOD + n0 + cb]);
            cp16(sptr(&sB[st ^ 1][rb * GBPAD + cb + 4]), &W[(size_t)(kc + rb) * DMOD + n0 + cb + 4]);
            cp_commit();
            cp_wait<1>();
        } else {
            cp_wait<0>();
        }
        __syncthreads();

        const float* cA = sA[st];
        const float* cB = sB[st];
#pragma unroll
        for (int ks = 0; ks < 2; ks++) {
            const int k0 = ks * 8;
            uint32_t a[2][4], b[8][2];
#pragma unroll
            for (int i = 0; i < 2; i++) {
                int r = m_off + i * 16 + lq;
                a[i][0] = __float_as_uint(cA[(r    ) * GAPAD + k0 + lr    ]);
                a[i][1] = __float_as_uint(cA[(r + 8) * GAPAD + k0 + lr    ]);
                a[i][2] = __float_as_uint(cA[(r    ) * GAPAD + k0 + lr + 4]);
                a[i][3] = __float_as_uint(cA[(r + 8) * GAPAD + k0 + lr + 4]);
            }
#pragma unroll
            for (int j = 0; j < 8; j++) {
                int n = n_off + j * 8 + lq;
                b[j][0] = __float_as_uint(cB[(k0 + lr    ) * GBPAD + n]);
                b[j][1] = __float_as_uint(cB[(k0 + lr + 4) * GBPAD + n]);
            }
#pragma unroll
            for (int i = 0; i < 2; i++)
#pragma unroll
                for (int j = 0; j < 8; j++)
                    mma_tf32(c[i][j], a[i], b[j]);
        }
        __syncthreads();   // compute done before buffer st is refilled
    }

#pragma unroll
    for (int i = 0; i < 2; i++) {
        int row = m0 + m_off + i * 16 + lq;
#pragma unroll
        for (int j = 0; j < 8; j++) {
            int col = n0 + n_off + j * 8 + 2 * lr;
            float b0 = bias[col], b1 = bias[col + 1];
            float v00 = (c[i][j][0] + b0) * scale;
            float v01 = (c[i][j][1] + b1) * scale;
            float v10 = (c[i][j][2] + b0) * scale;
            float v11 = (c[i][j][3] + b1) * scale;
            if (ROUND) {
                v00 = cvt_tf32f(v00); v01 = cvt_tf32f(v01);
                v10 = cvt_tf32f(v10); v11 = cvt_tf32f(v11);
            }
            *(float2*)&Cout[(size_t)row * DMOD + col] = make_float2(v00, v01);
            *(float2*)&Cout[(size_t)(row + 8) * DMOD + col] = make_float2(v10, v11);
        }
    }
}

__global__ __launch_bounds__(256)
void gemm_qkv_kernel(const float* __restrict__ bq, const float* __restrict__ bk,
                     const float* __restrict__ bv)
{
    const int z = blockIdx.z;
    const float* A = (z == 0) ? g_rq : (z == 1) ? g_rk : g_rv;
    const float* W = g_rw[z];
    const float* B = (z == 0) ? bq : (z == 1) ? bk : bv;
    float*       C = (z == 0) ? g_qp : (z == 1) ? g_kp : g_vp;
    const float  s = (z == 0) ? 0.125f : 1.0f;
    gemm_body<true>(A, W, B, C, s);
}

__global__ __launch_bounds__(256)
void gemm_out_kernel(const float* __restrict__ bias, float* __restrict__ Cout)
{
    gemm_body<false>(g_ctx, g_rw[3], bias, Cout, 1.0f);
}

// ---------------------------------------------------------------------------
// Tensor-core flash attention: 256 threads, 128 q-rows/CTA, 8 warps
// (16 rows each), key tiles of 32, cp.async double buffer.
// ---------------------------------------------------------------------------
#define KT   32
#define KSTR 68
#define VSTR 72

__global__ __launch_bounds__(256)
void attn_tc_kernel(const float* __restrict__ qlocs,
                    const float* __restrict__ klocs,
                    const int*   __restrict__ vlens)
{
    __shared__ __align__(16) float  sK[2][KT * KSTR];   // 17.4 KB (also stages Q: 64 rows)
    __shared__ __align__(16) float  sV[2][KT * VSTR];   // 18.4 KB
    __shared__ __align__(16) float2 tsh[NTAB];          // 8 KB
    __shared__ __align__(16) float2 lsh[2][KT];         // 0.5 KB

    const int b   = blockIdx.z;
    const int h   = blockIdx.y;
    const int q0  = blockIdx.x * 128;
    const int tid = threadIdx.x;
    const int lane = tid & 31;
    const int w    = tid >> 5;        // 0..7
    const int g    = lane >> 2;
    const int t    = lane & 3;
    const int r0   = w * 16 + g;      // q-row in CTA tile (0..127)

    for (int i = tid; i < NTAB; i += 256) tsh[i] = g_tab[h * NTAB + i];

    // ---- stage Q (pre-rounded tf32) in two 64-row halves through sK ----
    uint32_t qa[8][4];
    {
        const float* qg = &g_qp[((size_t)(b * QL + q0)) * DMOD + h * DH];
        float* sQ = &sK[0][0];          // 64 rows x stride KSTR (both stages)
        const int rq = tid >> 2;        // 0..63
        const int cq = (tid & 3) * 16;  // 0,16,32,48
#pragma unroll
        for (int half = 0; half < 2; half++) {
#pragma unroll
            for (int jj = 0; jj < 4; jj++)
                *(float4*)&sQ[rq * KSTR + cq + jj * 4] =
                    *(const float4*)&qg[(size_t)(half * 64 + rq) * DMOD + cq + jj * 4];
            __syncthreads();
            if ((w >> 2) == half) {
                const int lr0 = (w & 3) * 16 + g;
#pragma unroll
                for (int ks = 0; ks < 8; ks++) {
                    int k = ks * 8;
                    qa[ks][0] = __float_as_uint(sQ[(lr0    ) * KSTR + k + t    ]);
                    qa[ks][1] = __float_as_uint(sQ[(lr0 + 8) * KSTR + k + t    ]);
                    qa[ks][2] = __float_as_uint(sQ[(lr0    ) * KSTR + k + t + 4]);
                    qa[ks][3] = __float_as_uint(sQ[(lr0 + 8) * KSTR + k + t + 4]);
                }
            }
            __syncthreads();
        }
    }
    float2 ql0 = *(const float2*)&qlocs[((size_t)(b * QL + q0 + r0)) * 2];
    float2 ql1 = *(const float2*)&qlocs[((size_t)(b * QL + q0 + r0 + 8)) * 2];

    const int vlen  = vlens[b];
    const int nfull = vlen >> 5;
    const int rem   = vlen & 31;
    const int ntiles = nfull + (rem ? 1 : 0);

    float o[8][4];
#pragma unroll
    for (int n = 0; n < 8; n++)
#pragma unroll
        for (int e = 0; e < 4; e++) o[n][e] = 0.f;
    float m0 = -CUDART_INF_F, m1 = -CUDART_INF_F;
    float l0 = 0.f, l1 = 0.f;

    const float* kg = &g_kp[(size_t)b * KLEN * DMOD + h * DH];
    const float* vg = &g_vp[(size_t)b * KLEN * DMOD + h * DH];

    // prefetch addressing: 256 threads, 32 rows x 64 cols per tile
    const int pr = tid >> 3;            // 0..31
    const int pc = (tid & 7) * 8;       // 0..56 step 8

    {
        const float* kp_ = &kg[(size_t)pr * DMOD + pc];
        const float* vp_ = &vg[(size_t)pr * DMOD + pc];
        uint32_t dk = sptr(&sK[0][pr * KSTR + pc]);
        uint32_t dv = sptr(&sV[0][pr * VSTR + pc]);
        cp16(dk,      kp_);
        cp16(dk + 16, kp_ + 4);
        cp16(dv,      vp_);
        cp16(dv + 16, vp_ + 4);
        if (tid < 16)
            cp16(sptr(&lsh[0][0]) + tid * 16,
                 &klocs[((size_t)(b * KLEN)) * 2 + tid * 4]);
        cp_commit();
    }

    for (int tile = 0; tile < ntiles; tile++) {
        const int st = tile & 1;
        const int kb = tile * KT;
        if (tile + 1 < ntiles) {
            const int kb2 = kb + KT;
            const float* kp_ = &kg[(size_t)(kb2 + pr) * DMOD + pc];
            const float* vp_ = &vg[(size_t)(kb2 + pr) * DMOD + pc];
            uint32_t dk = sptr(&sK[st ^ 1][pr * KSTR + pc]);
            uint32_t dv = sptr(&sV[st ^ 1][pr * VSTR + pc]);
            cp16(dk,      kp_);
            cp16(dk + 16, kp_ + 4);
            cp16(dv,      vp_);
            cp16(dv + 16, vp_ + 4);
            if (tid < 16)
                cp16(sptr(&lsh[st ^ 1][0]) + tid * 16,
                     &klocs[((size_t)(b * KLEN + kb2)) * 2 + tid * 4]);
            cp_commit();
            cp_wait<1>();
        } else {
            cp_wait<0>();
        }
        __syncthreads();

        const float* sk = sK[st];
        const float* sv = sV[st];
        const float2* sl = lsh[st];

        // ---- S = Q K^T ----
        float s[4][4];
#pragma unroll
        for (int n = 0; n < 4; n++)
#pragma unroll
            for (int e = 0; e < 4; e++) s[n][e] = 0.f;
#pragma unroll
        for (int ks = 0; ks < 8; ks++) {
            const int k0 = ks * 8;
#pragma unroll
            for (int n = 0; n < 4; n++) {
                uint32_t bf[2];
                bf[0] = __float_as_uint(sk[(n * 8 + g) * KSTR + k0 + t    ]);
                bf[1] = __float_as_uint(sk[(n * 8 + g) * KSTR + k0 + t + 4]);
                mma_tf32(s[n], qa[ks], bf);
            }
        }

        // ---- bias + mask + tile row-max ----
        const bool edge = (rem != 0) && (tile == nfull);
        float tmax0 = -CUDART_INF_F, tmax1 = -CUDART_INF_F;
#pragma unroll
        for (int n = 0; n < 4; n++) {
            int c0 = n * 8 + 2 * t;
            float2 kl0 = sl[c0];
            float2 kl1 = sl[c0 + 1];
            float dx, dy, dist, tp, fr;
            int ti;
            float2 tv;

            dx = ql0.x - kl0.x; dy = ql0.y - kl0.y;
            dist = sqrtf(fmaf(dx, dx, dy * dy));
            tp = dist * TAB_SCALE; ti = min((int)tp, NTAB - 2); fr = tp - (float)ti;
            tv = tsh[ti];
            s[n][0] += fmaf(fr, tv.y, tv.x);

            dx = ql0.x - kl1.x; dy = ql0.y - kl1.y;
            dist = sqrtf(fmaf(dx, dx, dy * dy));
            tp = dist * TAB_SCALE; ti = min((int)tp, NTAB - 2); fr = tp - (float)ti;
            tv = tsh[ti];
            s[n][1] += fmaf(fr, tv.y, tv.x);

            dx = ql1.x - kl0.x; dy = ql1.y - kl0.y;
            dist = sqrtf(fmaf(dx, dx, dy * dy));
            tp = dist * TAB_SCALE; ti = min((int)tp, NTAB - 2); fr = tp - (float)ti;
            tv = tsh[ti];
            s[n][2] += fmaf(fr, tv.y, tv.x);

            dx = ql1.x - kl1.x; dy = ql1.y - kl1.y;
            dist = sqrtf(fmaf(dx, dx, dy * dy));
            tp = dist * TAB_SCALE; ti = min((int)tp, NTAB - 2); fr = tp - (float)ti;
            tv = tsh[ti];
            s[n][3] += fmaf(fr, tv.y, tv.x);

            if (edge) {
                if (kb + c0     >= vlen) { s[n][0] = -CUDART_INF_F; s[n][2] = -CUDART_INF_F; }
                if (kb + c0 + 1 >= vlen) { s[n][1] = -CUDART_INF_F; s[n][3] = -CUDART_INF_F; }
            }
            tmax0 = fmaxf(tmax0, fmaxf(s[n][0], s[n][1]));
            tmax1 = fmaxf(tmax1, fmaxf(s[n][2], s[n][3]));
        }
        tmax0 = fmaxf(tmax0, __shfl_xor_sync(0xffffffffu, tmax0, 1));
        tmax0 = fmaxf(tmax0, __shfl_xor_sync(0xffffffffu, tmax0, 2));
        tmax1 = fmaxf(tmax1, __shfl_xor_sync(0xffffffffu, tmax1, 1));
        tmax1 = fmaxf(tmax1, __shfl_xor_sync(0xffffffffu, tmax1, 2));

        // ---- online softmax update ----
        float mn0 = fmaxf(m0, tmax0), mn1 = fmaxf(m1, tmax1);
        float cor0 = __expf(m0 - mn0), cor1 = __expf(m1 - mn1);
        m0 = mn0; m1 = mn1;
        float rs0 = 0.f, rs1 = 0.f;
#pragma unroll
        for (int n = 0; n < 4; n++) {
            s[n][0] = __expf(s[n][0] - mn0);
            s[n][1] = __expf(s[n][1] - mn0);
            s[n][2] = __expf(s[n][2] - mn1);
            s[n][3] = __expf(s[n][3] - mn1);
            rs0 += s[n][0] + s[n][1];
            rs1 += s[n][2] + s[n][3];
        }
        rs0 += __shfl_xor_sync(0xffffffffu, rs0, 1);
        rs0 += __shfl_xor_sync(0xffffffffu, rs0, 2);
        rs1 += __shfl_xor_sync(0xffffffffu, rs1, 1);
        rs1 += __shfl_xor_sync(0xffffffffu, rs1, 2);
        l0 = l0 * cor0 + rs0;
        l1 = l1 * cor1 + rs1;
#pragma unroll
        for (int n = 0; n < 8; n++) {
            o[n][0] *= cor0; o[n][1] *= cor0;
            o[n][2] *= cor1; o[n][3] *= cor1;
        }

        // ---- O += P V ----
        const int qb   = lane & ~3;
        const int src0 = qb + (t >> 1);
        const int src1 = src0 + 2;
        const bool odd = (t & 1);
#pragma unroll
        for (int ks = 0; ks < 4; ks++) {
            float e00 = __shfl_sync(0xffffffffu, s[ks][0], src0);
            float e01 = __shfl_sync(0xffffffffu, s[ks][1], src0);
            float e10 = __shfl_sync(0xffffffffu, s[ks][2], src0);
            float e11 = __shfl_sync(0xffffffffu, s[ks][3], src0);
            float f00 = __shfl_sync(0xffffffffu, s[ks][0], src1);
            float f01 = __shfl_sync(0xffffffffu, s[ks][1], src1);
            float f10 = __shfl_sync(0xffffffffu, s[ks][2], src1);
            float f11 = __shfl_sync(0xffffffffu, s[ks][3], src1);
            uint32_t pf[4];
            pf[0] = f2tf32(odd ? e01 : e00);
            pf[1] = f2tf32(odd ? e11 : e10);
            pf[2] = f2tf32(odd ? f01 : f00);
            pf[3] = f2tf32(odd ? f11 : f10);
            const int k0 = ks * 8;
#pragma unroll
            for (int n = 0; n < 8; n++) {
                uint32_t bf[2];
                bf[0] = __float_as_uint(sv[(k0 + t    ) * VSTR + n * 8 + g]);
                bf[1] = __float_as_uint(sv[(k0 + t + 4) * VSTR + n * 8 + g]);
                mma_tf32(o[n], pf, bf);
            }
        }
        __syncthreads();
    }

    // ---- epilogue: normalize, tf32-round, store ctx ----
    float inv0 = 1.0f / l0;
    float inv1 = 1.0f / l1;
    float* op = &g_ctx[((size_t)(b * QL + q0 + r0)) * DMOD + h * DH];
#pragma unroll
    for (int n = 0; n < 8; n++) {
        int col = n * 8 + 2 * t;
        *(float2*)&op[col] =
            make_float2(cvt_tf32f(o[n][0] * inv0), cvt_tf32f(o[n][1] * inv0));
        *(float2*)&op[(size_t)8 * DMOD + col] =
            make_float2(cvt_tf32f(o[n][2] * inv1), cvt_tf32f(o[n][3] * inv1));
    }
}

// ---------------------------------------------------------------------------
// Launch
// ---------------------------------------------------------------------------
extern "C" void kernel_launch(void* const* d_in, const int* in_sizes, int n_in,
                              void* d_out, int out_size)
{
    const float* qs    = (const float*)d_in[0];
    const float* ks    = (const float*)d_in[1];
    const float* vs    = (const float*)d_in[2];
    const float* qlocs = (const float*)d_in[3];
    const float* klocs = (const float*)d_in[4];
    const float* Wq    = (const float*)d_in[5];
    const float* bq    = (const float*)d_in[6];
    const float* Wk    = (const float*)d_in[7];
    const float* bk    = (const float*)d_in[8];
    const float* Wv    = (const float*)d_in[9];
    const float* bv    = (const float*)d_in[10];
    const float* Wo    = (const float*)d_in[11];
    const float* bo    = (const float*)d_in[12];
    const float* ap    = (const float*)d_in[13];
    const float* bp    = (const float*)d_in[14];
    const float* cp    = (const float*)d_in[15];
    const int*   vl    = (const int*)  d_in[16];
    float* out = (float*)d_out;

    // pre-round inputs + weights to tf32
    dim3 rga((BB * QL * DMOD / 4 + 255) / 256, 3);
    round_acts_kernel<<<rga, 256>>>(qs, ks, vs);
    dim3 rgw((DMOD * DMOD / 4 + 255) / 256, 4);
    round_w_kernel<<<rgw, 256>>>(Wq, Wk, Wv, Wo);

    build_table_kernel<<<(NH * NTAB + 255) / 256, 256>>>(ap, bp, cp);

    dim3 g3(DMOD / 128, (BB * QL) / 128, 3);
    gemm_qkv_kernel<<<g3, 256>>>(bq, bk, bv);

    dim3 agrid(QL / 128, NH, BB);
    attn_tc_kernel<<<agrid, 256>>>(qlocs, klocs, vl);

    dim3 ggrid(DMOD / 128, (BB * QL) / 128);
    gemm_out_kernel<<<ggrid, 256>>>(bo, out);
}

// round 10
// speedup vs baseline: 5.0907x; 1.5487x over previous
#include <cuda_runtime.h>
#include <cuda_fp16.h>
#include <math.h>
#include <math_constants.h>
#include <cstdint>

// ---------------------------------------------------------------------------
// Problem constants
// ---------------------------------------------------------------------------
#define BB   2
#define QL   2048
#define KLEN 2048
#define DMOD 512
#define NH   8
#define NF   5
#define DH   64
#define NTAB 1024

static const float TAB_SCALE = (float)(NTAB - 1) / 14.2f;

// ---------------------------------------------------------------------------
// Device scratch (all fp16 intermediates)
// ---------------------------------------------------------------------------
__device__ __half g_qp [BB * QL   * DMOD];   // projected+scaled Q (fp16)
__device__ __half g_kp [BB * KLEN * DMOD];   // projected K (fp16)
__device__ __half g_vpT[BB * DMOD * KLEN];   // projected V TRANSPOSED [b, dm, key]
__device__ __half g_ctx[BB * QL   * DMOD];   // attention output (fp16)
__device__ __half g_rq [BB * QL   * DMOD];   // fp16-rounded inputs
__device__ __half g_rk [BB * KLEN * DMOD];
__device__ __half g_rv [BB * KLEN * DMOD];
__device__ __half g_rw [4][DMOD * DMOD];     // fp16 TRANSPOSED weights [n][k]
__device__ float2 g_tab[NH * NTAB];

// ---------------------------------------------------------------------------
// Helpers
// ---------------------------------------------------------------------------
__device__ __forceinline__ uint32_t pack_f16x2(float lo, float hi) {
    uint32_t r;
    asm("cvt.rn.f16x2.f32 %0, %1, %2;" : "=r"(r) : "f"(hi), "f"(lo));
    return r;
}

// m16n8k16 fp16 MMA, fp32 accumulate (non-'a' PTX, full-rate HMMA)
__device__ __forceinline__ void mma_f16(float* c, const uint32_t* a,
                                        uint32_t b0, uint32_t b1) {
    asm volatile("mma.sync.aligned.m16n8k16.row.col.f32.f16.f16.f32 "
                 "{%0,%1,%2,%3}, {%4,%5,%6,%7}, {%8,%9}, {%0,%1,%2,%3};"
                 : "+f"(c[0]), "+f"(c[1]), "+f"(c[2]), "+f"(c[3])
                 : "r"(a[0]), "r"(a[1]), "r"(a[2]), "r"(a[3]),
                   "r"(b0), "r"(b1));
}

__device__ __forceinline__ uint32_t sptr(const void* p) {
    return (uint32_t)__cvta_generic_to_shared(p);
}
__device__ __forceinline__ void cp16(uint32_t smem_addr, const void* gptr) {
    asm volatile("cp.async.cg.shared.global [%0], [%1], 16;"
                 :: "r"(smem_addr), "l"(gptr) : "memory");
}
__device__ __forceinline__ void cp_commit() {
    asm volatile("cp.async.commit_group;" ::: "memory");
}
template <int N>
__device__ __forceinline__ void cp_wait() {
    asm volatile("cp.async.wait_group %0;" :: "n"(N) : "memory");
}

// ---------------------------------------------------------------------------
// Pre-round: fp16-round activations; fp16+transpose weights.
// ---------------------------------------------------------------------------
__global__ __launch_bounds__(256)
void round_acts_kernel(const float* __restrict__ qs,
                       const float* __restrict__ ks,
                       const float* __restrict__ vs)
{
    const int z = blockIdx.y;
    const float* src = (z == 0) ? qs : (z == 1) ? ks : vs;
    __half* dst = (z == 0) ? g_rq : (z == 1) ? g_rk : g_rv;
    size_t i = ((size_t)blockIdx.x * blockDim.x + threadIdx.x) * 8;
    if (i >= (size_t)BB * QL * DMOD) return;
    float4 v0 = *(const float4*)&src[i];
    float4 v1 = *(const float4*)&src[i + 4];
    uint4 o;
    o.x = pack_f16x2(v0.x, v0.y);
    o.y = pack_f16x2(v0.z, v0.w);
    o.z = pack_f16x2(v1.x, v1.y);
    o.w = pack_f16x2(v1.z, v1.w);
    *(uint4*)&dst[i] = o;
}

__global__ __launch_bounds__(256)
void round_w_kernel(const float* __restrict__ Wq, const float* __restrict__ Wk,
                    const float* __restrict__ Wv, const float* __restrict__ Wo)
{
    __shared__ float t[32][33];
    const int z = blockIdx.z;
    const float* W = (z == 0) ? Wq : (z == 1) ? Wk : (z == 2) ? Wv : Wo;
    __half* Wt = g_rw[z];
    int bx = blockIdx.x * 32, by = blockIdx.y * 32;   // bx: n, by: k
    int tx = threadIdx.x, ty = threadIdx.y;           // 32 x 8
#pragma unroll
    for (int i = 0; i < 32; i += 8)
        t[ty + i][tx] = W[(size_t)(by + ty + i) * DMOD + bx + tx];
    __syncthreads();
#pragma unroll
    for (int i = 0; i < 32; i += 8)
        Wt[(size_t)(bx + ty + i) * DMOD + by + tx] = __float2half(t[tx][ty + i]);
}

// ---------------------------------------------------------------------------
// Bias table
// ---------------------------------------------------------------------------
__global__ void build_table_kernel(const float* __restrict__ A,
                                   const float* __restrict__ Bp,
                                   const float* __restrict__ C)
{
    int idx = blockIdx.x * blockDim.x + threadIdx.x;
    if (idx >= NH * NTAB) return;
    int h = idx / NTAB;
    int i = idx - h * NTAB;
    const float STEP = 14.2f / (float)(NTAB - 1);
    float d0 = (float)i * STEP;
    float d1 = d0 + STEP;
    float v0 = 0.f, v1 = 0.f;
#pragma unroll
    for (int f = 0; f < NF; f++) {
        float af = A [h * NF + f];
        float bf = fabsf(Bp[h * NF + f]);
        float cf = C [h * NF + f];
        float t0 = d0 - cf;
        float t1 = d1 - cf;
        v0 += af * expf(-bf * t0 * t0);
        v1 += af * expf(-bf * t1 * t1);
    }
    g_tab[idx] = make_float2(v0, v1 - v0);
}

// ---------------------------------------------------------------------------
// fp16 GEMM: 128x128 tile, BK=32 (2 k16 steps), 2-stage cp.async.
// A [m][k] fp16, Wt [n][k] fp16 (pre-transposed). smem stride 20 uint32
// (16 half2 data + 4 pad) -> frag banks 20*lq+lr bijective mod 32.
// MODE: 0 = f32 out, 1 = fp16 out, 2 = fp16 transposed out ([b,col,key]).
// ---------------------------------------------------------------------------
#define GP 20

template <int MODE>
__device__ __forceinline__ void gemm_core(const __half* __restrict__ Ah,
                                          const __half* __restrict__ Wt,
                                          const float* __restrict__ bias,
                                          float scale,
                                          float* __restrict__ outF,
                                          __half* __restrict__ outH)
{
    __shared__ __align__(16) uint32_t sA[2][128 * GP];  // 10 KB each
    __shared__ __align__(16) uint32_t sB[2][128 * GP];

    const int tid  = threadIdx.x;
    const int lane = tid & 31;
    const int wrp  = tid >> 5;
    const int m_off = (wrp >> 1) * 32;
    const int n_off = (wrp & 1) * 64;
    const int m0 = blockIdx.y * 128;
    const int n0 = blockIdx.x * 128;
    const int lq = lane >> 2;
    const int lr = lane & 3;

    const int ra = tid >> 1;          // row 0..127
    const int ca = (tid & 1) * 2;     // 16B-chunk base (of 4 per 64B row)

    float c[2][8][4];
#pragma unroll
    for (int i = 0; i < 2; i++)
#pragma unroll
        for (int j = 0; j < 8; j++)
#pragma unroll
            for (int e = 0; e < 4; e++) c[i][j][e] = 0.f;

    // prologue: chunk 0
    {
        const __half* As = Ah + (size_t)(m0 + ra) * DMOD + ca * 8;
        cp16(sptr(&sA[0][ra * GP + ca * 4]),     As);
        cp16(sptr(&sA[0][ra * GP + ca * 4 + 4]), As + 8);
        const __half* Bs = Wt + (size_t)(n0 + ra) * DMOD + ca * 8;
        cp16(sptr(&sB[0][ra * GP + ca * 4]),     Bs);
        cp16(sptr(&sB[0][ra * GP + ca * 4 + 4]), Bs + 8);
        cp_commit();
    }

    for (int ch = 0; ch < 16; ch++) {
        const int st = ch & 1;
        if (ch + 1 < 16) {
            const int kc = (ch + 1) * 32;
            const __half* As = Ah + (size_t)(m0 + ra) * DMOD + kc + ca * 8;
            cp16(sptr(&sA[st ^ 1][ra * GP + ca * 4]),     As);
            cp16(sptr(&sA[st ^ 1][ra * GP + ca * 4 + 4]), As + 8);
            const __half* Bs = Wt + (size_t)(n0 + ra) * DMOD + kc + ca * 8;
            cp16(sptr(&sB[st ^ 1][ra * GP + ca * 4]),     Bs);
            cp16(sptr(&sB[st ^ 1][ra * GP + ca * 4 + 4]), Bs + 8);
            cp_commit();
            cp_wait<1>();
        } else {
            cp_wait<0>();
        }
        __syncthreads();

        const uint32_t* cA = sA[st];
        const uint32_t* cB = sB[st];
#pragma unroll
        for (int ks = 0; ks < 2; ks++) {
            const int k0 = ks * 8;
            uint32_t a[2][4], b[8][2];
#pragma unroll
            for (int i = 0; i < 2; i++) {
                int r = m_off + i * 16 + lq;
                a[i][0] = cA[(r    ) * GP + k0 + lr    ];
                a[i][1] = cA[(r + 8) * GP + k0 + lr    ];
                a[i][2] = cA[(r    ) * GP + k0 + lr + 4];
                a[i][3] = cA[(r + 8) * GP + k0 + lr + 4];
            }
#pragma unroll
            for (int j = 0; j < 8; j++) {
                int n = n_off + j * 8 + lq;
                b[j][0] = cB[n * GP + k0 + lr    ];
                b[j][1] = cB[n * GP + k0 + lr + 4];
            }
#pragma unroll
            for (int i = 0; i < 2; i++)
#pragma unroll
                for (int j = 0; j < 8; j++)
                    mma_f16(c[i][j], a[i], b[j][0], b[j][1]);
        }
        __syncthreads();
    }

    // epilogue
#pragma unroll
    for (int i = 0; i < 2; i++) {
        int row = m0 + m_off + i * 16 + lq;
#pragma unroll
        for (int j = 0; j < 8; j++) {
            int col = n0 + n_off + j * 8 + 2 * lr;
            float b0 = bias[col], b1 = bias[col + 1];
            float v00 = (c[i][j][0] + b0) * scale;
            float v01 = (c[i][j][1] + b1) * scale;
            float v10 = (c[i][j][2] + b0) * scale;
            float v11 = (c[i][j][3] + b1) * scale;
            if (MODE == 0) {
                *(float2*)&outF[(size_t)row * DMOD + col] = make_float2(v00, v01);
                *(float2*)&outF[(size_t)(row + 8) * DMOD + col] = make_float2(v10, v11);
            } else if (MODE == 1) {
                uint32_t* o32 = (uint32_t*)outH;
                o32[(size_t)row * (DMOD / 2) + (col >> 1)] = pack_f16x2(v00, v01);
                o32[(size_t)(row + 8) * (DMOD / 2) + (col >> 1)] = pack_f16x2(v10, v11);
            } else {
                // transposed: outH[b][col][key], key = row within batch
                int bb = row >> 11;
                int key = row & 2047;
                __half* base0 = outH + ((size_t)(bb * DMOD + col)) * KLEN;
                __half* base1 = outH + ((size_t)(bb * DMOD + col + 1)) * KLEN;
                base0[key]     = __float2half(v00);
                base1[key]     = __float2half(v01);
                base0[key + 8] = __float2half(v10);
                base1[key + 8] = __float2half(v11);
            }
        }
    }
}

__global__ __launch_bounds__(256)
void gemm_qkv_kernel(const float* __restrict__ bq, const float* __restrict__ bk,
                     const float* __restrict__ bv)
{
    const int z = blockIdx.z;
    if (z == 0)      gemm_core<1>(g_rq, g_rw[0], bq, 0.125f, nullptr, g_qp);
    else if (z == 1) gemm_core<1>(g_rk, g_rw[1], bk, 1.0f,   nullptr, g_kp);
    else             gemm_core<2>(g_rv, g_rw[2], bv, 1.0f,   nullptr, g_vpT);
}

__global__ __launch_bounds__(256)
void gemm_out_kernel(const float* __restrict__ bias, float* __restrict__ Cout)
{
    gemm_core<0>(g_ctx, g_rw[3], bias, 1.0f, Cout, nullptr);
}

// ---------------------------------------------------------------------------
// fp16 tensor-core flash attention.
// 256 threads / 128 q-rows / 8 warps (16 rows each). Key tiles of 64,
// cp.async double buffer. K smem [key][dh] half2 stride 36 (banks 4g+t);
// V^T smem [dh][key] half2 stride 36. S C-frag reused directly as PV A-frag
// (pack_f16x2 only, no shuffles).
// ---------------------------------------------------------------------------
#define KT 64

__global__ __launch_bounds__(256)
void attn_tc_kernel(const float* __restrict__ qlocs,
                    const float* __restrict__ klocs,
                    const int*   __restrict__ vlens)
{
    __shared__ __align__(16) uint32_t sK [2][KT * 36];  // 9216 B each
    __shared__ __align__(16) uint32_t sVT[2][KT * 36];
    __shared__ __align__(16) float2   tsh[NTAB];        // 8 KB
    __shared__ __align__(16) float2   lsh[2][KT];       // 1 KB

    const int b   = blockIdx.z;
    const int h   = blockIdx.y;
    const int q0  = blockIdx.x * 128;
    const int tid = threadIdx.x;
    const int lane = tid & 31;
    const int w    = tid >> 5;
    const int g    = lane >> 2;
    const int t    = lane & 3;
    const int r0   = w * 16 + g;

    for (int i = tid; i < NTAB; i += 256) tsh[i] = g_tab[h * NTAB + i];

    // ---- Q a-frags direct from global (fp16, m16n8k16 layout) ----
    uint32_t qa[4][4];
    {
        const uint32_t* q32a = (const uint32_t*)(g_qp +
            (size_t)(b * QL + q0 + r0) * DMOD + h * DH);
        const uint32_t* q32b = q32a + 4 * DMOD;   // +8 rows
#pragma unroll
        for (int ks = 0; ks < 4; ks++) {
            qa[ks][0] = __ldg(&q32a[8 * ks + t]);
            qa[ks][1] = __ldg(&q32b[8 * ks + t]);
            qa[ks][2] = __ldg(&q32a[8 * ks + t + 4]);
            qa[ks][3] = __ldg(&q32b[8 * ks + t + 4]);
        }
    }
    float2 ql0 = *(const float2*)&qlocs[((size_t)(b * QL + q0 + r0)) * 2];
    float2 ql1 = *(const float2*)&qlocs[((size_t)(b * QL + q0 + r0 + 8)) * 2];

    const int vlen  = vlens[b];
    const int nfull = vlen >> 6;
    const int rem   = vlen & 63;
    const int ntiles = nfull + (rem ? 1 : 0);

    float o[8][4];
#pragma unroll
    for (int n = 0; n < 8; n++)
#pragma unroll
        for (int e = 0; e < 4; e++) o[n][e] = 0.f;
    float m0 = -CUDART_INF_F, m1 = -CUDART_INF_F;
    float l0 = 0.f, l1 = 0.f;

    const __half* kgh = g_kp + (size_t)b * KLEN * DMOD + h * DH;
    const __half* vgh = g_vpT + ((size_t)(b * DMOD + h * DH)) * KLEN;

    // tile loader mapping: 64 rows x 8 chunks(16B); thread -> row tid>>2, chunks (tid&3)*2+{0,1}
    const int kr = tid >> 2;
    const int kc = (tid & 3) * 2;

    // ---- prologue: prefetch tile 0 ----
    {
        const __half* ks_ = kgh + (size_t)kr * DMOD + kc * 8;
        cp16(sptr(&sK[0][kr * 36 + kc * 4]),     ks_);
        cp16(sptr(&sK[0][kr * 36 + kc * 4 + 4]), ks_ + 8);
        const __half* vs_ = vgh + (size_t)kr * KLEN + kc * 8;
        cp16(sptr(&sVT[0][kr * 36 + kc * 4]),     vs_);
        cp16(sptr(&sVT[0][kr * 36 + kc * 4 + 4]), vs_ + 8);
        if (tid < 32)
            cp16(sptr(&lsh[0][0]) + tid * 16,
                 &klocs[((size_t)(b * KLEN)) * 2 + tid * 4]);
        cp_commit();
    }

    for (int tile = 0; tile < ntiles; tile++) {
        const int st = tile & 1;
        const int kb = tile * KT;
        if (tile + 1 < ntiles) {
            const int kb2 = kb + KT;
            const __half* ks_ = kgh + (size_t)(kb2 + kr) * DMOD + kc * 8;
            cp16(sptr(&sK[st ^ 1][kr * 36 + kc * 4]),     ks_);
            cp16(sptr(&sK[st ^ 1][kr * 36 + kc * 4 + 4]), ks_ + 8);
            const __half* vs_ = vgh + (size_t)kr * KLEN + kb2 + kc * 8;
            cp16(sptr(&sVT[st ^ 1][kr * 36 + kc * 4]),     vs_);
            cp16(sptr(&sVT[st ^ 1][kr * 36 + kc * 4 + 4]), vs_ + 8);
            if (tid < 32)
                cp16(sptr(&lsh[st ^ 1][0]) + tid * 16,
                     &klocs[((size_t)(b * KLEN + kb2)) * 2 + tid * 4]);
            cp_commit();
            cp_wait<1>();
        } else {
            cp_wait<0>();
        }
        __syncthreads();

        const uint32_t* sk = sK[st];
        const uint32_t* sv = sVT[st];
        const float2*   sl = lsh[st];

        // ---- S = Q K^T : 4 k16 steps x 8 key-groups ----
        float s[8][4];
#pragma unroll
        for (int n = 0; n < 8; n++)
#pragma unroll
            for (int e = 0; e < 4; e++) s[n][e] = 0.f;
#pragma unroll
        for (int ks = 0; ks < 4; ks++) {
#pragma unroll
            for (int n = 0; n < 8; n++) {
                uint32_t b0 = sk[(n * 8 + g) * 36 + 8 * ks + t    ];
                uint32_t b1 = sk[(n * 8 + g) * 36 + 8 * ks + t + 4];
                mma_f16(s[n], qa[ks], b0, b1);
            }
        }

        // ---- bias + mask + tile row-max ----
        const bool edge = (rem != 0) && (tile == nfull);
        float tmax0 = -CUDART_INF_F, tmax1 = -CUDART_INF_F;
#pragma unroll
        for (int n = 0; n < 8; n++) {
            int c0 = n * 8 + 2 * t;
            float2 kl0 = sl[c0];
            float2 kl1 = sl[c0 + 1];
            float dx, dy, dist, tp, fr;
            int ti;
            float2 tv;

            dx = ql0.x - kl0.x; dy = ql0.y - kl0.y;
            dist = sqrtf(fmaf(dx, dx, dy * dy));
            tp = dist * TAB_SCALE; ti = min((int)tp, NTAB - 2); fr = tp - (float)ti;
            tv = tsh[ti];
            s[n][0] += fmaf(fr, tv.y, tv.x);

            dx = ql0.x - kl1.x; dy = ql0.y - kl1.y;
            dist = sqrtf(fmaf(dx, dx, dy * dy));
            tp = dist * TAB_SCALE; ti = min((int)tp, NTAB - 2); fr = tp - (float)ti;
            tv = tsh[ti];
            s[n][1] += fmaf(fr, tv.y, tv.x);

            dx = ql1.x - kl0.x; dy = ql1.y - kl0.y;
            dist = sqrtf(fmaf(dx, dx, dy * dy));
            tp = dist * TAB_SCALE; ti = min((int)tp, NTAB - 2); fr = tp - (float)ti;
            tv = tsh[ti];
            s[n][2] += fmaf(fr, tv.y, tv.x);

            dx = ql1.x - kl1.x; dy = ql1.y - kl1.y;
            dist = sqrtf(fmaf(dx, dx, dy * dy));
            tp = dist * TAB_SCALE; ti = min((int)tp, NTAB - 2); fr = tp - (float)ti;
            tv = tsh[ti];
            s[n][3] += fmaf(fr, tv.y, tv.x);

            if (edge) {
                if (kb + c0     >= vlen) { s[n][0] = -CUDART_INF_F; s[n][2] = -CUDART_INF_F; }
                if (kb + c0 + 1 >= vlen) { s[n][1] = -CUDART_INF_F; s[n][3] = -CUDART_INF_F; }
            }
            tmax0 = fmaxf(tmax0, fmaxf(s[n][0], s[n][1]));
            tmax1 = fmaxf(tmax1, fmaxf(s[n][2], s[n][3]));
        }
        tmax0 = fmaxf(tmax0, __shfl_xor_sync(0xffffffffu, tmax0, 1));
        tmax0 = fmaxf(tmax0, __shfl_xor_sync(0xffffffffu, tmax0, 2));
        tmax1 = fmaxf(tmax1, __shfl_xor_sync(0xffffffffu, tmax1, 1));
        tmax1 = fmaxf(tmax1, __shfl_xor_sync(0xffffffffu, tmax1, 2));

        // ---- online softmax ----
        float mn0 = fmaxf(m0, tmax0), mn1 = fmaxf(m1, tmax1);
        float cor0 = __expf(m0 - mn0), cor1 = __expf(m1 - mn1);
        m0 = mn0; m1 = mn1;
        float rs0 = 0.f, rs1 = 0.f;
#pragma unroll
        for (int n = 0; n < 8; n++) {
            s[n][0] = __expf(s[n][0] - mn0);
            s[n][1] = __expf(s[n][1] - mn0);
            s[n][2] = __expf(s[n][2] - mn1);
            s[n][3] = __expf(s[n][3] - mn1);
            rs0 += s[n][0] + s[n][1];
            rs1 += s[n][2] + s[n][3];
        }
        rs0 += __shfl_xor_sync(0xffffffffu, rs0, 1);
        rs0 += __shfl_xor_sync(0xffffffffu, rs0, 2);
        rs1 += __shfl_xor_sync(0xffffffffu, rs1, 1);
        rs1 += __shfl_xor_sync(0xffffffffu, rs1, 2);
        l0 = l0 * cor0 + rs0;
        l1 = l1 * cor1 + rs1;
#pragma unroll
        for (int n = 0; n < 8; n++) {
            o[n][0] *= cor0; o[n][1] *= cor0;
            o[n][2] *= cor1; o[n][3] *= cor1;
        }

        // ---- O += P V : C-frag of S is A-frag of PV (pack only) ----
#pragma unroll
        for (int ks = 0; ks < 4; ks++) {
            uint32_t pa[4];
            pa[0] = pack_f16x2(s[2 * ks    ][0], s[2 * ks    ][1]);
            pa[1] = pack_f16x2(s[2 * ks    ][2], s[2 * ks    ][3]);
            pa[2] = pack_f16x2(s[2 * ks + 1][0], s[2 * ks + 1][1]);
            pa[3] = pack_f16x2(s[2 * ks + 1][2], s[2 * ks + 1][3]);
#pragma unroll
            for (int n = 0; n < 8; n++) {
                uint32_t b0 = sv[(n * 8 + g) * 36 + 8 * ks + t    ];
                uint32_t b1 = sv[(n * 8 + g) * 36 + 8 * ks + t + 4];
                mma_f16(o[n], pa, b0, b1);
            }
        }
        __syncthreads();
    }

    // ---- epilogue: normalize, fp16 ctx ----
    float inv0 = 1.0f / l0;
    float inv1 = 1.0f / l1;
    uint32_t* ctx32 = (uint32_t*)(g_ctx +
        (size_t)(b * QL + q0 + r0) * DMOD + h * DH);
    uint32_t* ctx32b = ctx32 + 4 * DMOD;   // +8 rows
#pragma unroll
    for (int n = 0; n < 8; n++) {
        ctx32 [4 * n + t] = pack_f16x2(o[n][0] * inv0, o[n][1] * inv0);
        ctx32b[4 * n + t] = pack_f16x2(o[n][2] * inv1, o[n][3] * inv1);
    }
}

// ---------------------------------------------------------------------------
// Launch
// ---------------------------------------------------------------------------
extern "C" void kernel_launch(void* const* d_in, const int* in_sizes, int n_in,
                              void* d_out, int out_size)
{
    const float* qs    = (const float*)d_in[0];
    const float* ks    = (const float*)d_in[1];
    const float* vs    = (const float*)d_in[2];
    const float* qlocs = (const float*)d_in[3];
    const float* klocs = (const float*)d_in[4];
    const float* Wq    = (const float*)d_in[5];
    const float* bq    = (const float*)d_in[6];
    const float* Wk    = (const float*)d_in[7];
    const float* bk    = (const float*)d_in[8];
    const float* Wv    = (const float*)d_in[9];
    const float* bv    = (const float*)d_in[10];
    const float* Wo    = (const float*)d_in[11];
    const float* bo    = (const float*)d_in[12];
    const float* ap    = (const float*)d_in[13];
    const float* bp    = (const float*)d_in[14];
    const float* cp    = (const float*)d_in[15];
    const int*   vl    = (const int*)  d_in[16];
    float* out = (float*)d_out;

    // fp16 pre-round + weight transpose
    dim3 rga((BB * QL * DMOD / 8 + 255) / 256, 3);
    round_acts_kernel<<<rga, 256>>>(qs, ks, vs);
    dim3 twg(16, 16, 4), twb(32, 8);
    round_w_kernel<<<twg, twb>>>(Wq, Wk, Wv, Wo);

    build_table_kernel<<<(NH * NTAB + 255) / 256, 256>>>(ap, bp, cp);

    dim3 g3(DMOD / 128, (BB * QL) / 128, 3);
    gemm_qkv_kernel<<<g3, 256>>>(bq, bk, bv);

    dim3 agrid(QL / 128, NH, BB);
    attn_tc_kernel<<<agrid, 256>>>(qlocs, klocs, vl);

    dim3 ggrid(DMOD / 128, (BB * QL) / 128);
    gemm_out_kernel<<<ggrid, 256>>>(bo, out);
}

// round 11
// speedup vs baseline: 5.2149x; 1.0244x over previous
#include <cuda_runtime.h>
#include <cuda_fp16.h>
#include <math.h>
#include <math_constants.h>
#include <cstdint>

// ---------------------------------------------------------------------------
// Problem constants
// ---------------------------------------------------------------------------
#define BB   2
#define QL   2048
#define KLEN 2048
#define DMOD 512
#define NH   8
#define NF   5
#define DH   64
#define NTAB 1024

static const float TAB_SCALE = (float)(NTAB - 1) / 14.2f;

// ---------------------------------------------------------------------------
// Device scratch (all fp16 intermediates)
// ---------------------------------------------------------------------------
__device__ __half g_qp [BB * QL   * DMOD];   // projected+scaled Q (fp16)
__device__ __half g_kp [BB * KLEN * DMOD];   // projected K (fp16)
__device__ __half g_vp [BB * KLEN * DMOD];   // projected V [b, key, dm]
__device__ __half g_vpT[BB * DMOD * KLEN];   // V transposed [b, dm, key]
__device__ __half g_ctx[BB * QL   * DMOD];   // attention output (fp16)
__device__ __half g_rq [BB * QL   * DMOD];   // fp16-rounded inputs
__device__ __half g_rk [BB * KLEN * DMOD];
__device__ __half g_rv [BB * KLEN * DMOD];
__device__ __half g_rw [4][DMOD * DMOD];     // fp16 TRANSPOSED weights [n][k]
__device__ float2 g_tab[NH * NTAB];

// ---------------------------------------------------------------------------
// Helpers
// ---------------------------------------------------------------------------
__device__ __forceinline__ uint32_t pack_f16x2(float lo, float hi) {
    uint32_t r;
    asm("cvt.rn.f16x2.f32 %0, %1, %2;" : "=r"(r) : "f"(hi), "f"(lo));
    return r;
}

// m16n8k16 fp16 MMA, fp32 accumulate
__device__ __forceinline__ void mma_f16(float* c, const uint32_t* a,
                                        uint32_t b0, uint32_t b1) {
    asm volatile("mma.sync.aligned.m16n8k16.row.col.f32.f16.f16.f32 "
                 "{%0,%1,%2,%3}, {%4,%5,%6,%7}, {%8,%9}, {%0,%1,%2,%3};"
                 : "+f"(c[0]), "+f"(c[1]), "+f"(c[2]), "+f"(c[3])
                 : "r"(a[0]), "r"(a[1]), "r"(a[2]), "r"(a[3]),
                   "r"(b0), "r"(b1));
}

__device__ __forceinline__ uint32_t sptr(const void* p) {
    return (uint32_t)__cvta_generic_to_shared(p);
}
__device__ __forceinline__ void cp16(uint32_t smem_addr, const void* gptr) {
    asm volatile("cp.async.cg.shared.global [%0], [%1], 16;"
                 :: "r"(smem_addr), "l"(gptr) : "memory");
}
__device__ __forceinline__ void cp_commit() {
    asm volatile("cp.async.commit_group;" ::: "memory");
}
template <int N>
__device__ __forceinline__ void cp_wait() {
    asm volatile("cp.async.wait_group %0;" :: "n"(N) : "memory");
}

// ---------------------------------------------------------------------------
// Pre-round: fp16-round activations; fp16+transpose weights.
// ---------------------------------------------------------------------------
__global__ __launch_bounds__(256)
void round_acts_kernel(const float* __restrict__ qs,
                       const float* __restrict__ ks,
                       const float* __restrict__ vs)
{
    const int z = blockIdx.y;
    const float* src = (z == 0) ? qs : (z == 1) ? ks : vs;
    __half* dst = (z == 0) ? g_rq : (z == 1) ? g_rk : g_rv;
    size_t i = ((size_t)blockIdx.x * blockDim.x + threadIdx.x) * 8;
    if (i >= (size_t)BB * QL * DMOD) return;
    float4 v0 = *(const float4*)&src[i];
    float4 v1 = *(const float4*)&src[i + 4];
    uint4 o;
    o.x = pack_f16x2(v0.x, v0.y);
    o.y = pack_f16x2(v0.z, v0.w);
    o.z = pack_f16x2(v1.x, v1.y);
    o.w = pack_f16x2(v1.z, v1.w);
    *(uint4*)&dst[i] = o;
}

__global__ __launch_bounds__(256)
void round_w_kernel(const float* __restrict__ Wq, const float* __restrict__ Wk,
                    const float* __restrict__ Wv, const float* __restrict__ Wo)
{
    __shared__ float t[32][33];
    const int z = blockIdx.z;
    const float* W = (z == 0) ? Wq : (z == 1) ? Wk : (z == 2) ? Wv : Wo;
    __half* Wt = g_rw[z];
    int bx = blockIdx.x * 32, by = blockIdx.y * 32;   // bx: n, by: k
    int tx = threadIdx.x, ty = threadIdx.y;           // 32 x 8
#pragma unroll
    for (int i = 0; i < 32; i += 8)
        t[ty + i][tx] = W[(size_t)(by + ty + i) * DMOD + bx + tx];
    __syncthreads();
#pragma unroll
    for (int i = 0; i < 32; i += 8)
        Wt[(size_t)(bx + ty + i) * DMOD + by + tx] = __float2half(t[tx][ty + i]);
}

// ---------------------------------------------------------------------------
// V transpose (fp16): g_vp [b, key, dm] -> g_vpT [b, dm, key].
// 64x64 tiles, smem staged, coalesced 16B on both sides.
// ---------------------------------------------------------------------------
__global__ __launch_bounds__(256)
void transpose_v_kernel()
{
    __shared__ __half t[64][72];
    const int b  = blockIdx.z;
    const int k0 = blockIdx.x * 64;
    const int d0 = blockIdx.y * 64;
    const int tid = threadIdx.x;

    // load: 64 keys x 32 half2
#pragma unroll
    for (int p = 0; p < 8; p++) {
        int e = tid + p * 256;           // 0..2047
        int key = e >> 5;
        int dp  = e & 31;
        uint32_t v = *(const uint32_t*)&g_vp[((size_t)(b * KLEN + k0 + key)) * DMOD + d0 + 2 * dp];
        __half2 h2 = *(__half2*)&v;
        t[2 * dp    ][key] = __low2half(h2);
        t[2 * dp + 1][key] = __high2half(h2);
    }
    __syncthreads();
    // store: 64 dm rows x 8 chunks of 8 halfs
#pragma unroll
    for (int p = 0; p < 2; p++) {
        int e = tid + p * 256;           // 0..511
        int dm = e >> 3;
        int c  = e & 7;
        uint4 v = *(uint4*)&t[dm][c * 8];
        *(uint4*)&g_vpT[((size_t)(b * DMOD + d0 + dm)) * KLEN + k0 + c * 8] = v;
    }
}

// ---------------------------------------------------------------------------
// Bias table
// ---------------------------------------------------------------------------
__global__ void build_table_kernel(const float* __restrict__ A,
                                   const float* __restrict__ Bp,
                                   const float* __restrict__ C)
{
    int idx = blockIdx.x * blockDim.x + threadIdx.x;
    if (idx >= NH * NTAB) return;
    int h = idx / NTAB;
    int i = idx - h * NTAB;
    const float STEP = 14.2f / (float)(NTAB - 1);
    float d0 = (float)i * STEP;
    float d1 = d0 + STEP;
    float v0 = 0.f, v1 = 0.f;
#pragma unroll
    for (int f = 0; f < NF; f++) {
        float af = A [h * NF + f];
        float bf = fabsf(Bp[h * NF + f]);
        float cf = C [h * NF + f];
        float t0 = d0 - cf;
        float t1 = d1 - cf;
        v0 += af * expf(-bf * t0 * t0);
        v1 += af * expf(-bf * t1 * t1);
    }
    g_tab[idx] = make_float2(v0, v1 - v0);
}

// ---------------------------------------------------------------------------
// fp16 GEMM: 128x128 tile, BK=32, 2-stage cp.async.
// MODE: 0 = f32 out, 1 = fp16 out. Single instantiation per kernel.
// ---------------------------------------------------------------------------
#define GP 20

template <int MODE>
__device__ __forceinline__ void gemm_core(const __half* __restrict__ Ah,
                                          const __half* __restrict__ Wt,
                                          const float* __restrict__ bias,
                                          float scale,
                                          float* __restrict__ outF,
                                          __half* __restrict__ outH)
{
    __shared__ __align__(16) uint32_t sA[2][128 * GP];  // 10 KB each
    __shared__ __align__(16) uint32_t sB[2][128 * GP];

    const int tid  = threadIdx.x;
    const int lane = tid & 31;
    const int wrp  = tid >> 5;
    const int m_off = (wrp >> 1) * 32;
    const int n_off = (wrp & 1) * 64;
    const int m0 = blockIdx.y * 128;
    const int n0 = blockIdx.x * 128;
    const int lq = lane >> 2;
    const int lr = lane & 3;

    const int ra = tid >> 1;
    const int ca = (tid & 1) * 2;

    float c[2][8][4];
#pragma unroll
    for (int i = 0; i < 2; i++)
#pragma unroll
        for (int j = 0; j < 8; j++)
#pragma unroll
            for (int e = 0; e < 4; e++) c[i][j][e] = 0.f;

    {
        const __half* As = Ah + (size_t)(m0 + ra) * DMOD + ca * 8;
        cp16(sptr(&sA[0][ra * GP + ca * 4]),     As);
        cp16(sptr(&sA[0][ra * GP + ca * 4 + 4]), As + 8);
        const __half* Bs = Wt + (size_t)(n0 + ra) * DMOD + ca * 8;
        cp16(sptr(&sB[0][ra * GP + ca * 4]),     Bs);
        cp16(sptr(&sB[0][ra * GP + ca * 4 + 4]), Bs + 8);
        cp_commit();
    }

    for (int ch = 0; ch < 16; ch++) {
        const int st = ch & 1;
        if (ch + 1 < 16) {
            const int kc = (ch + 1) * 32;
            const __half* As = Ah + (size_t)(m0 + ra) * DMOD + kc + ca * 8;
            cp16(sptr(&sA[st ^ 1][ra * GP + ca * 4]),     As);
            cp16(sptr(&sA[st ^ 1][ra * GP + ca * 4 + 4]), As + 8);
            const __half* Bs = Wt + (size_t)(n0 + ra) * DMOD + kc + ca * 8;
            cp16(sptr(&sB[st ^ 1][ra * GP + ca * 4]),     Bs);
            cp16(sptr(&sB[st ^ 1][ra * GP + ca * 4 + 4]), Bs + 8);
            cp_commit();
            cp_wait<1>();
        } else {
            cp_wait<0>();
        }
        __syncthreads();

        const uint32_t* cA = sA[st];
        const uint32_t* cB = sB[st];
#pragma unroll
        for (int ks = 0; ks < 2; ks++) {
            const int k0 = ks * 8;
            uint32_t a[2][4], b[8][2];
#pragma unroll
            for (int i = 0; i < 2; i++) {
                int r = m_off + i * 16 + lq;
                a[i][0] = cA[(r    ) * GP + k0 + lr    ];
                a[i][1] = cA[(r + 8) * GP + k0 + lr    ];
                a[i][2] = cA[(r    ) * GP + k0 + lr + 4];
                a[i][3] = cA[(r + 8) * GP + k0 + lr + 4];
            }
#pragma unroll
            for (int j = 0; j < 8; j++) {
                int n = n_off + j * 8 + lq;
                b[j][0] = cB[n * GP + k0 + lr    ];
                b[j][1] = cB[n * GP + k0 + lr + 4];
            }
#pragma unroll
            for (int i = 0; i < 2; i++)
#pragma unroll
                for (int j = 0; j < 8; j++)
                    mma_f16(c[i][j], a[i], b[j][0], b[j][1]);
        }
        __syncthreads();
    }

#pragma unroll
    for (int i = 0; i < 2; i++) {
        int row = m0 + m_off + i * 16 + lq;
#pragma unroll
        for (int j = 0; j < 8; j++) {
            int col = n0 + n_off + j * 8 + 2 * lr;
            float b0 = bias[col], b1 = bias[col + 1];
            float v00 = (c[i][j][0] + b0) * scale;
            float v01 = (c[i][j][1] + b1) * scale;
            float v10 = (c[i][j][2] + b0) * scale;
            float v11 = (c[i][j][3] + b1) * scale;
            if (MODE == 0) {
                *(float2*)&outF[(size_t)row * DMOD + col] = make_float2(v00, v01);
                *(float2*)&outF[(size_t)(row + 8) * DMOD + col] = make_float2(v10, v11);
            } else {
                uint32_t* o32 = (uint32_t*)outH;
                o32[(size_t)row * (DMOD / 2) + (col >> 1)] = pack_f16x2(v00, v01);
                o32[(size_t)(row + 8) * (DMOD / 2) + (col >> 1)] = pack_f16x2(v10, v11);
            }
        }
    }
}

// single gemm_core<1> instantiation -> one 40KB smem block, 2 CTAs/SM
__global__ __launch_bounds__(256, 2)
void gemm_qkv_kernel(const float* __restrict__ bq, const float* __restrict__ bk,
                     const float* __restrict__ bv)
{
    const int z = blockIdx.z;
    const __half* A = (z == 0) ? g_rq : (z == 1) ? g_rk : g_rv;
    const __half* W = g_rw[z];
    const float*  B = (z == 0) ? bq : (z == 1) ? bk : bv;
    __half*       C = (z == 0) ? g_qp : (z == 1) ? g_kp : g_vp;
    const float   s = (z == 0) ? 0.125f : 1.0f;
    gemm_core<1>(A, W, B, s, nullptr, C);
}

__global__ __launch_bounds__(256, 2)
void gemm_out_kernel(const float* __restrict__ bias, float* __restrict__ Cout)
{
    gemm_core<0>(g_ctx, g_rw[3], bias, 1.0f, Cout, nullptr);
}

// ---------------------------------------------------------------------------
// fp16 tensor-core flash attention (as round 10, + launch_bounds(256,2)).
// ---------------------------------------------------------------------------
#define KT 64

__global__ __launch_bounds__(256, 2)
void attn_tc_kernel(const float* __restrict__ qlocs,
                    const float* __restrict__ klocs,
                    const int*   __restrict__ vlens)
{
    __shared__ __align__(16) uint32_t sK [2][KT * 36];
    __shared__ __align__(16) uint32_t sVT[2][KT * 36];
    __shared__ __align__(16) float2   tsh[NTAB];
    __shared__ __align__(16) float2   lsh[2][KT];

    const int b   = blockIdx.z;
    const int h   = blockIdx.y;
    const int q0  = blockIdx.x * 128;
    const int tid = threadIdx.x;
    const int lane = tid & 31;
    const int w    = tid >> 5;
    const int g    = lane >> 2;
    const int t    = lane & 3;
    const int r0   = w * 16 + g;

    for (int i = tid; i < NTAB; i += 256) tsh[i] = g_tab[h * NTAB + i];

    uint32_t qa[4][4];
    {
        const uint32_t* q32a = (const uint32_t*)(g_qp +
            (size_t)(b * QL + q0 + r0) * DMOD + h * DH);
        const uint32_t* q32b = q32a + 4 * DMOD;
#pragma unroll
        for (int ks = 0; ks < 4; ks++) {
            qa[ks][0] = __ldg(&q32a[8 * ks + t]);
            qa[ks][1] = __ldg(&q32b[8 * ks + t]);
            qa[ks][2] = __ldg(&q32a[8 * ks + t + 4]);
            qa[ks][3] = __ldg(&q32b[8 * ks + t + 4]);
        }
    }
    float2 ql0 = *(const float2*)&qlocs[((size_t)(b * QL + q0 + r0)) * 2];
    float2 ql1 = *(const float2*)&qlocs[((size_t)(b * QL + q0 + r0 + 8)) * 2];

    const int vlen  = vlens[b];
    const int nfull = vlen >> 6;
    const int rem   = vlen & 63;
    const int ntiles = nfull + (rem ? 1 : 0);

    float o[8][4];
#pragma unroll
    for (int n = 0; n < 8; n++)
#pragma unroll
        for (int e = 0; e < 4; e++) o[n][e] = 0.f;
    float m0 = -CUDART_INF_F, m1 = -CUDART_INF_F;
    float l0 = 0.f, l1 = 0.f;

    const __half* kgh = g_kp + (size_t)b * KLEN * DMOD + h * DH;
    const __half* vgh = g_vpT + ((size_t)(b * DMOD + h * DH)) * KLEN;

    const int kr = tid >> 2;
    const int kc = (tid & 3) * 2;

    {
        const __half* ks_ = kgh + (size_t)kr * DMOD + kc * 8;
        cp16(sptr(&sK[0][kr * 36 + kc * 4]),     ks_);
        cp16(sptr(&sK[0][kr * 36 + kc * 4 + 4]), ks_ + 8);
        const __half* vs_ = vgh + (size_t)kr * KLEN + kc * 8;
        cp16(sptr(&sVT[0][kr * 36 + kc * 4]),     vs_);
        cp16(sptr(&sVT[0][kr * 36 + kc * 4 + 4]), vs_ + 8);
        if (tid < 32)
            cp16(sptr(&lsh[0][0]) + tid * 16,
                 &klocs[((size_t)(b * KLEN)) * 2 + tid * 4]);
        cp_commit();
    }

    for (int tile = 0; tile < ntiles; tile++) {
        const int st = tile & 1;
        const int kb = tile * KT;
        if (tile + 1 < ntiles) {
            const int kb2 = kb + KT;
            const __half* ks_ = kgh + (size_t)(kb2 + kr) * DMOD + kc * 8;
            cp16(sptr(&sK[st ^ 1][kr * 36 + kc * 4]),     ks_);
            cp16(sptr(&sK[st ^ 1][kr * 36 + kc * 4 + 4]), ks_ + 8);
            const __half* vs_ = vgh + (size_t)kr * KLEN + kb2 + kc * 8;
            cp16(sptr(&sVT[st ^ 1][kr * 36 + kc * 4]),     vs_);
            cp16(sptr(&sVT[st ^ 1][kr * 36 + kc * 4 + 4]), vs_ + 8);
            if (tid < 32)
                cp16(sptr(&lsh[st ^ 1][0]) + tid * 16,
                     &klocs[((size_t)(b * KLEN + kb2)) * 2 + tid * 4]);
            cp_commit();
            cp_wait<1>();
        } else {
            cp_wait<0>();
        }
        __syncthreads();

        const uint32_t* sk = sK[st];
        const uint32_t* sv = sVT[st];
        const float2*   sl = lsh[st];

        float s[8][4];
#pragma unroll
        for (int n = 0; n < 8; n++)
#pragma unroll
            for (int e = 0; e < 4; e++) s[n][e] = 0.f;
#pragma unroll
        for (int ks = 0; ks < 4; ks++) {
#pragma unroll
            for (int n = 0; n < 8; n++) {
                uint32_t b0 = sk[(n * 8 + g) * 36 + 8 * ks + t    ];
                uint32_t b1 = sk[(n * 8 + g) * 36 + 8 * ks + t + 4];
                mma_f16(s[n], qa[ks], b0, b1);
            }
        }

        const bool edge = (rem != 0) && (tile == nfull);
        float tmax0 = -CUDART_INF_F, tmax1 = -CUDART_INF_F;
#pragma unroll
        for (int n = 0; n < 8; n++) {
            int c0 = n * 8 + 2 * t;
            float2 kl0 = sl[c0];
            float2 kl1 = sl[c0 + 1];
            float dx, dy, dist, tp, fr;
            int ti;
            float2 tv;

            dx = ql0.x - kl0.x; dy = ql0.y - kl0.y;
            dist = sqrtf(fmaf(dx, dx, dy * dy));
            tp = dist * TAB_SCALE; ti = min((int)tp, NTAB - 2); fr = tp - (float)ti;
            tv = tsh[ti];
            s[n][0] += fmaf(fr, tv.y, tv.x);

            dx = ql0.x - kl1.x; dy = ql0.y - kl1.y;
            dist = sqrtf(fmaf(dx, dx, dy * dy));
            tp = dist * TAB_SCALE; ti = min((int)tp, NTAB - 2); fr = tp - (float)ti;
            tv = tsh[ti];
            s[n][1] += fmaf(fr, tv.y, tv.x);

            dx = ql1.x - kl0.x; dy = ql1.y - kl0.y;
            dist = sqrtf(fmaf(dx, dx, dy * dy));
            tp = dist * TAB_SCALE; ti = min((int)tp, NTAB - 2); fr = tp - (float)ti;
            tv = tsh[ti];
            s[n][2] += fmaf(fr, tv.y, tv.x);

            dx = ql1.x - kl1.x; dy = ql1.y - kl1.y;
            dist = sqrtf(fmaf(dx, dx, dy * dy));
            tp = dist * TAB_SCALE; ti = min((int)tp, NTAB - 2); fr = tp - (float)ti;
            tv = tsh[ti];
            s[n][3] += fmaf(fr, tv.y, tv.x);

            if (edge) {
                if (kb + c0     >= vlen) { s[n][0] = -CUDART_INF_F; s[n][2] = -CUDART_INF_F; }
                if (kb + c0 + 1 >= vlen) { s[n][1] = -CUDART_INF_F; s[n][3] = -CUDART_INF_F; }
            }
            tmax0 = fmaxf(tmax0, fmaxf(s[n][0], s[n][1]));
            tmax1 = fmaxf(tmax1, fmaxf(s[n][2], s[n][3]));
        }
        tmax0 = fmaxf(tmax0, __shfl_xor_sync(0xffffffffu, tmax0, 1));
        tmax0 = fmaxf(tmax0, __shfl_xor_sync(0xffffffffu, tmax0, 2));
        tmax1 = fmaxf(tmax1, __shfl_xor_sync(0xffffffffu, tmax1, 1));
        tmax1 = fmaxf(tmax1, __shfl_xor_sync(0xffffffffu, tmax1, 2));

        float mn0 = fmaxf(m0, tmax0), mn1 = fmaxf(m1, tmax1);
        float cor0 = __expf(m0 - mn0), cor1 = __expf(m1 - mn1);
        m0 = mn0; m1 = mn1;
        float rs0 = 0.f, rs1 = 0.f;
#pragma unroll
        for (int n = 0; n < 8; n++) {
            s[n][0] = __expf(s[n][0] - mn0);
            s[n][1] = __expf(s[n][1] - mn0);
            s[n][2] = __expf(s[n][2] - mn1);
            s[n][3] = __expf(s[n][3] - mn1);
            rs0 += s[n][0] + s[n][1];
            rs1 += s[n][2] + s[n][3];
        }
        rs0 += __shfl_xor_sync(0xffffffffu, rs0, 1);
        rs0 += __shfl_xor_sync(0xffffffffu, rs0, 2);
        rs1 += __shfl_xor_sync(0xffffffffu, rs1, 1);
        rs1 += __shfl_xor_sync(0xffffffffu, rs1, 2);
        l0 = l0 * cor0 + rs0;
        l1 = l1 * cor1 + rs1;
#pragma unroll
        for (int n = 0; n < 8; n++) {
            o[n][0] *= cor0; o[n][1] *= cor0;
            o[n][2] *= cor1; o[n][3] *= cor1;
        }

#pragma unroll
        for (int ks = 0; ks < 4; ks++) {
            uint32_t pa[4];
            pa[0] = pack_f16x2(s[2 * ks    ][0], s[2 * ks    ][1]);
            pa[1] = pack_f16x2(s[2 * ks    ][2], s[2 * ks    ][3]);
            pa[2] = pack_f16x2(s[2 * ks + 1][0], s[2 * ks + 1][1]);
            pa[3] = pack_f16x2(s[2 * ks + 1][2], s[2 * ks + 1][3]);
#pragma unroll
            for (int n = 0; n < 8; n++) {
                uint32_t b0 = sv[(n * 8 + g) * 36 + 8 * ks + t    ];
                uint32_t b1 = sv[(n * 8 + g) * 36 + 8 * ks + t + 4];
                mma_f16(o[n], pa, b0, b1);
            }
        }
        __syncthreads();
    }

    float inv0 = 1.0f / l0;
    float inv1 = 1.0f / l1;
    uint32_t* ctx32 = (uint32_t*)(g_ctx +
        (size_t)(b * QL + q0 + r0) * DMOD + h * DH);
    uint32_t* ctx32b = ctx32 + 4 * DMOD;
#pragma unroll
    for (int n = 0; n < 8; n++) {
        ctx32 [4 * n + t] = pack_f16x2(o[n][0] * inv0, o[n][1] * inv0);
        ctx32b[4 * n + t] = pack_f16x2(o[n][2] * inv1, o[n][3] * inv1);
    }
}

// ---------------------------------------------------------------------------
// Launch
// ---------------------------------------------------------------------------
extern "C" void kernel_launch(void* const* d_in, const int* in_sizes, int n_in,
                              void* d_out, int out_size)
{
    const float* qs    = (const float*)d_in[0];
    const float* ks    = (const float*)d_in[1];
    const float* vs    = (const float*)d_in[2];
    const float* qlocs = (const float*)d_in[3];
    const float* klocs = (const float*)d_in[4];
    const float* Wq    = (const float*)d_in[5];
    const float* bq    = (const float*)d_in[6];
    const float* Wk    = (const float*)d_in[7];
    const float* bk    = (const float*)d_in[8];
    const float* Wv    = (const float*)d_in[9];
    const float* bv    = (const float*)d_in[10];
    const float* Wo    = (const float*)d_in[11];
    const float* bo    = (const float*)d_in[12];
    const float* ap    = (const float*)d_in[13];
    const float* bp    = (const float*)d_in[14];
    const float* cp    = (const float*)d_in[15];
    const int*   vl    = (const int*)  d_in[16];
    float* out = (float*)d_out;

    dim3 rga((BB * QL * DMOD / 8 + 255) / 256, 3);
    round_acts_kernel<<<rga, 256>>>(qs, ks, vs);
    dim3 twg(16, 16, 4), twb(32, 8);
    round_w_kernel<<<twg, twb>>>(Wq, Wk, Wv, Wo);

    build_table_kernel<<<(NH * NTAB + 255) / 256, 256>>>(ap, bp, cp);

    dim3 g3(DMOD / 128, (BB * QL) / 128, 3);
    gemm_qkv_kernel<<<g3, 256>>>(bq, bk, bv);

    dim3 tvg(KLEN / 64, DMOD / 64, BB);
    transpose_v_kernel<<<tvg, 256>>>();

    dim3 agrid(QL / 128, NH, BB);
    attn_tc_kernel<<<agrid, 256>>>(qlocs, klocs, vl);

    dim3 ggrid(DMOD / 128, (BB * QL) / 128);
    gemm_out_kernel<<<ggrid, 256>>>(bo, out);
}

// round 12
// speedup vs baseline: 5.3557x; 1.0270x over previous
#include <cuda_runtime.h>
#include <cuda_fp16.h>
#include <math.h>
#include <math_constants.h>
#include <cstdint>

// ---------------------------------------------------------------------------
// Problem constants
// ---------------------------------------------------------------------------
#define BB   2
#define QL   2048
#define KLEN 2048
#define DMOD 512
#define NH   8
#define NF   5
#define DH   64
#define NTAB 1024

static const float TAB_SCALE = (float)(NTAB - 1) / 14.2f;
#define LOG2E 1.4426950408889634f

// ---------------------------------------------------------------------------
// Device scratch (all fp16 intermediates)
// ---------------------------------------------------------------------------
__device__ __half g_qp [BB * QL   * DMOD];   // projected Q * (1/8)*log2e (fp16)
__device__ __half g_kp [BB * KLEN * DMOD];   // projected K (fp16)
__device__ __half g_vp [BB * KLEN * DMOD];   // projected V [b, key, dm]
__device__ __half g_vpT[BB * DMOD * KLEN];   // V transposed [b, dm, key]
__device__ __half g_ctx[BB * QL   * DMOD];   // attention output (fp16)
__device__ __half g_rq [BB * QL   * DMOD];   // fp16-rounded inputs
__device__ __half g_rk [BB * KLEN * DMOD];
__device__ __half g_rv [BB * KLEN * DMOD];
__device__ __half g_rw [4][DMOD * DMOD];     // fp16 TRANSPOSED weights [n][k]
__device__ float2 g_tab[NH * NTAB];          // bias table in log2 units

// ---------------------------------------------------------------------------
// Helpers
// ---------------------------------------------------------------------------
__device__ __forceinline__ uint32_t pack_f16x2(float lo, float hi) {
    uint32_t r;
    asm("cvt.rn.f16x2.f32 %0, %1, %2;" : "=r"(r) : "f"(hi), "f"(lo));
    return r;
}
__device__ __forceinline__ float ex2f(float x) {
    float r;
    asm("ex2.approx.f32 %0, %1;" : "=f"(r) : "f"(x));
    return r;
}
__device__ __forceinline__ uint32_t ex2h2(uint32_t x) {
    uint32_t r;
    asm("ex2.approx.f16x2 %0, %1;" : "=r"(r) : "r"(x));
    return r;
}

// m16n8k16 fp16 MMA, fp32 accumulate
__device__ __forceinline__ void mma_f16(float* c, const uint32_t* a,
                                        uint32_t b0, uint32_t b1) {
    asm volatile("mma.sync.aligned.m16n8k16.row.col.f32.f16.f16.f32 "
                 "{%0,%1,%2,%3}, {%4,%5,%6,%7}, {%8,%9}, {%0,%1,%2,%3};"
                 : "+f"(c[0]), "+f"(c[1]), "+f"(c[2]), "+f"(c[3])
                 : "r"(a[0]), "r"(a[1]), "r"(a[2]), "r"(a[3]),
                   "r"(b0), "r"(b1));
}

__device__ __forceinline__ uint32_t sptr(const void* p) {
    return (uint32_t)__cvta_generic_to_shared(p);
}
__device__ __forceinline__ void cp16(uint32_t smem_addr, const void* gptr) {
    asm volatile("cp.async.cg.shared.global [%0], [%1], 16;"
                 :: "r"(smem_addr), "l"(gptr) : "memory");
}
__device__ __forceinline__ void cp_commit() {
    asm volatile("cp.async.commit_group;" ::: "memory");
}
template <int N>
__device__ __forceinline__ void cp_wait() {
    asm volatile("cp.async.wait_group %0;" :: "n"(N) : "memory");
}

// ---------------------------------------------------------------------------
// Pre-round: fp16-round activations; fp16+transpose weights.
// ---------------------------------------------------------------------------
__global__ __launch_bounds__(256)
void round_acts_kernel(const float* __restrict__ qs,
                       const float* __restrict__ ks,
                       const float* __restrict__ vs)
{
    const int z = blockIdx.y;
    const float* src = (z == 0) ? qs : (z == 1) ? ks : vs;
    __half* dst = (z == 0) ? g_rq : (z == 1) ? g_rk : g_rv;
    size_t i = ((size_t)blockIdx.x * blockDim.x + threadIdx.x) * 8;
    if (i >= (size_t)BB * QL * DMOD) return;
    float4 v0 = *(const float4*)&src[i];
    float4 v1 = *(const float4*)&src[i + 4];
    uint4 o;
    o.x = pack_f16x2(v0.x, v0.y);
    o.y = pack_f16x2(v0.z, v0.w);
    o.z = pack_f16x2(v1.x, v1.y);
    o.w = pack_f16x2(v1.z, v1.w);
    *(uint4*)&dst[i] = o;
}

__global__ __launch_bounds__(256)
void round_w_kernel(const float* __restrict__ Wq, const float* __restrict__ Wk,
                    const float* __restrict__ Wv, const float* __restrict__ Wo)
{
    __shared__ float t[32][33];
    const int z = blockIdx.z;
    const float* W = (z == 0) ? Wq : (z == 1) ? Wk : (z == 2) ? Wv : Wo;
    __half* Wt = g_rw[z];
    int bx = blockIdx.x * 32, by = blockIdx.y * 32;
    int tx = threadIdx.x, ty = threadIdx.y;
#pragma unroll
    for (int i = 0; i < 32; i += 8)
        t[ty + i][tx] = W[(size_t)(by + ty + i) * DMOD + bx + tx];
    __syncthreads();
#pragma unroll
    for (int i = 0; i < 32; i += 8)
        Wt[(size_t)(bx + ty + i) * DMOD + by + tx] = __float2half(t[tx][ty + i]);
}

// ---------------------------------------------------------------------------
// V transpose (fp16): g_vp [b, key, dm] -> g_vpT [b, dm, key].
// ---------------------------------------------------------------------------
__global__ __launch_bounds__(256)
void transpose_v_kernel()
{
    __shared__ __half t[64][72];
    const int b  = blockIdx.z;
    const int k0 = blockIdx.x * 64;
    const int d0 = blockIdx.y * 64;
    const int tid = threadIdx.x;
#pragma unroll
    for (int p = 0; p < 8; p++) {
        int e = tid + p * 256;
        int key = e >> 5;
        int dp  = e & 31;
        uint32_t v = *(const uint32_t*)&g_vp[((size_t)(b * KLEN + k0 + key)) * DMOD + d0 + 2 * dp];
        __half2 h2 = *(__half2*)&v;
        t[2 * dp    ][key] = __low2half(h2);
        t[2 * dp + 1][key] = __high2half(h2);
    }
    __syncthreads();
#pragma unroll
    for (int p = 0; p < 2; p++) {
        int e = tid + p * 256;
        int dm = e >> 3;
        int c  = e & 7;
        uint4 v = *(uint4*)&t[dm][c * 8];
        *(uint4*)&g_vpT[((size_t)(b * DMOD + d0 + dm)) * KLEN + k0 + c * 8] = v;
    }
}

// ---------------------------------------------------------------------------
// Bias table (values pre-multiplied by log2e -> softmax via exp2)
// ---------------------------------------------------------------------------
__global__ void build_table_kernel(const float* __restrict__ A,
                                   const float* __restrict__ Bp,
                                   const float* __restrict__ C)
{
    int idx = blockIdx.x * blockDim.x + threadIdx.x;
    if (idx >= NH * NTAB) return;
    int h = idx / NTAB;
    int i = idx - h * NTAB;
    const float STEP = 14.2f / (float)(NTAB - 1);
    float d0 = (float)i * STEP;
    float d1 = d0 + STEP;
    float v0 = 0.f, v1 = 0.f;
#pragma unroll
    for (int f = 0; f < NF; f++) {
        float af = A [h * NF + f];
        float bf = fabsf(Bp[h * NF + f]);
        float cf = C [h * NF + f];
        float t0 = d0 - cf;
        float t1 = d1 - cf;
        v0 += af * expf(-bf * t0 * t0);
        v1 += af * expf(-bf * t1 * t1);
    }
    v0 *= LOG2E;
    v1 *= LOG2E;
    g_tab[idx] = make_float2(v0, v1 - v0);
}

// ---------------------------------------------------------------------------
// fp16 GEMM: 128x128 tile, BK=32, 4-stage cp.async pipeline (dynamic smem).
// ---------------------------------------------------------------------------
#define GP 20
#define STG_U32 (128 * GP)            // one matrix per stage (10 KB)
#define GEMM_SMEM (4 * 2 * STG_U32 * 4)   // 81920 bytes

template <int MODE>
__device__ __forceinline__ void gemm_core(const __half* __restrict__ Ah,
                                          const __half* __restrict__ Wt,
                                          const float* __restrict__ bias,
                                          float scale,
                                          float* __restrict__ outF,
                                          __half* __restrict__ outH)
{
    extern __shared__ __align__(16) uint32_t dsm[];

    const int tid  = threadIdx.x;
    const int lane = tid & 31;
    const int wrp  = tid >> 5;
    const int m_off = (wrp >> 1) * 32;
    const int n_off = (wrp & 1) * 64;
    const int m0 = blockIdx.y * 128;
    const int n0 = blockIdx.x * 128;
    const int lq = lane >> 2;
    const int lr = lane & 3;

    const int ra = tid >> 1;
    const int ca = (tid & 1) * 2;

    float c[2][8][4];
#pragma unroll
    for (int i = 0; i < 2; i++)
#pragma unroll
        for (int j = 0; j < 8; j++)
#pragma unroll
            for (int e = 0; e < 4; e++) c[i][j][e] = 0.f;

#define GEMM_PREFETCH(CH, STG)                                                 \
    {                                                                          \
        uint32_t* A_s = dsm + (STG) * 2 * STG_U32;                             \
        uint32_t* B_s = A_s + STG_U32;                                         \
        const __half* Asrc = Ah + (size_t)(m0 + ra) * DMOD + (CH) * 32 + ca * 8; \
        cp16(sptr(&A_s[ra * GP + ca * 4]),     Asrc);                          \
        cp16(sptr(&A_s[ra * GP + ca * 4 + 4]), Asrc + 8);                      \
        const __half* Bsrc = Wt + (size_t)(n0 + ra) * DMOD + (CH) * 32 + ca * 8; \
        cp16(sptr(&B_s[ra * GP + ca * 4]),     Bsrc);                          \
        cp16(sptr(&B_s[ra * GP + ca * 4 + 4]), Bsrc + 8);                      \
        cp_commit();                                                           \
    }

    GEMM_PREFETCH(0, 0)
    GEMM_PREFETCH(1, 1)
    GEMM_PREFETCH(2, 2)

    for (int ch = 0; ch < 16; ch++) {
        const int st = ch & 3;
        if (ch + 3 < 16) {
            GEMM_PREFETCH(ch + 3, (ch + 3) & 3)
            cp_wait<3>();
        } else if (ch == 13) cp_wait<2>();
        else if (ch == 14)   cp_wait<1>();
        else                 cp_wait<0>();
        __syncthreads();

        const uint32_t* cA = dsm + st * 2 * STG_U32;
        const uint32_t* cB = cA + STG_U32;
#pragma unroll
        for (int ks = 0; ks < 2; ks++) {
            const int k0 = ks * 8;
            uint32_t a[2][4], b[8][2];
#pragma unroll
            for (int i = 0; i < 2; i++) {
                int r = m_off + i * 16 + lq;
                a[i][0] = cA[(r    ) * GP + k0 + lr    ];
                a[i][1] = cA[(r + 8) * GP + k0 + lr    ];
                a[i][2] = cA[(r    ) * GP + k0 + lr + 4];
                a[i][3] = cA[(r + 8) * GP + k0 + lr + 4];
            }
#pragma unroll
            for (int j = 0; j < 8; j++) {
                int n = n_off + j * 8 + lq;
                b[j][0] = cB[n * GP + k0 + lr    ];
                b[j][1] = cB[n * GP + k0 + lr + 4];
            }
#pragma unroll
            for (int i = 0; i < 2; i++)
#pragma unroll
                for (int j = 0; j < 8; j++)
                    mma_f16(c[i][j], a[i], b[j][0], b[j][1]);
        }
        __syncthreads();   // all warps done reading stage st before it refills
    }

#pragma unroll
    for (int i = 0; i < 2; i++) {
        int row = m0 + m_off + i * 16 + lq;
#pragma unroll
        for (int j = 0; j < 8; j++) {
            int col = n0 + n_off + j * 8 + 2 * lr;
            float b0 = bias[col], b1 = bias[col + 1];
            float v00 = (c[i][j][0] + b0) * scale;
            float v01 = (c[i][j][1] + b1) * scale;
            float v10 = (c[i][j][2] + b0) * scale;
            float v11 = (c[i][j][3] + b1) * scale;
            if (MODE == 0) {
                *(float2*)&outF[(size_t)row * DMOD + col] = make_float2(v00, v01);
                *(float2*)&outF[(size_t)(row + 8) * DMOD + col] = make_float2(v10, v11);
            } else {
                uint32_t* o32 = (uint32_t*)outH;
                o32[(size_t)row * (DMOD / 2) + (col >> 1)] = pack_f16x2(v00, v01);
                o32[(size_t)(row + 8) * (DMOD / 2) + (col >> 1)] = pack_f16x2(v10, v11);
            }
        }
    }
#undef GEMM_PREFETCH
}

__global__ __launch_bounds__(256, 2)
void gemm_qkv_kernel(const float* __restrict__ bq, const float* __restrict__ bk,
                     const float* __restrict__ bv)
{
    const int z = blockIdx.z;
    const __half* A = (z == 0) ? g_rq : (z == 1) ? g_rk : g_rv;
    const __half* W = g_rw[z];
    const float*  B = (z == 0) ? bq : (z == 1) ? bk : bv;
    __half*       C = (z == 0) ? g_qp : (z == 1) ? g_kp : g_vp;
    const float   s = (z == 0) ? 0.125f * LOG2E : 1.0f;   // Q carries log2e
    gemm_core<1>(A, W, B, s, nullptr, C);
}

__global__ __launch_bounds__(256, 2)
void gemm_out_kernel(const float* __restrict__ bias, float* __restrict__ Cout)
{
    gemm_core<0>(g_ctx, g_rw[3], bias, 1.0f, Cout, nullptr);
}

// ---------------------------------------------------------------------------
// fp16 tensor-core flash attention; softmax via ex2.approx.f16x2
// (scores are in log2 units: Q pre-scaled by log2e, table in log2 units).
// ---------------------------------------------------------------------------
#define KT 64

__global__ __launch_bounds__(256, 2)
void attn_tc_kernel(const float* __restrict__ qlocs,
                    const float* __restrict__ klocs,
                    const int*   __restrict__ vlens)
{
    __shared__ __align__(16) uint32_t sK [2][KT * 36];
    __shared__ __align__(16) uint32_t sVT[2][KT * 36];
    __shared__ __align__(16) float2   tsh[NTAB];
    __shared__ __align__(16) float2   lsh[2][KT];

    const int b   = blockIdx.z;
    const int h   = blockIdx.y;
    const int q0  = blockIdx.x * 128;
    const int tid = threadIdx.x;
    const int lane = tid & 31;
    const int w    = tid >> 5;
    const int g    = lane >> 2;
    const int t    = lane & 3;
    const int r0   = w * 16 + g;

    for (int i = tid; i < NTAB; i += 256) tsh[i] = g_tab[h * NTAB + i];

    uint32_t qa[4][4];
    {
        const uint32_t* q32a = (const uint32_t*)(g_qp +
            (size_t)(b * QL + q0 + r0) * DMOD + h * DH);
        const uint32_t* q32b = q32a + 4 * DMOD;
#pragma unroll
        for (int ks = 0; ks < 4; ks++) {
            qa[ks][0] = __ldg(&q32a[8 * ks + t]);
            qa[ks][1] = __ldg(&q32b[8 * ks + t]);
            qa[ks][2] = __ldg(&q32a[8 * ks + t + 4]);
            qa[ks][3] = __ldg(&q32b[8 * ks + t + 4]);
        }
    }
    float2 ql0 = *(const float2*)&qlocs[((size_t)(b * QL + q0 + r0)) * 2];
    float2 ql1 = *(const float2*)&qlocs[((size_t)(b * QL + q0 + r0 + 8)) * 2];

    const int vlen  = vlens[b];
    const int nfull = vlen >> 6;
    const int rem   = vlen & 63;
    const int ntiles = nfull + (rem ? 1 : 0);

    float o[8][4];
#pragma unroll
    for (int n = 0; n < 8; n++)
#pragma unroll
        for (int e = 0; e < 4; e++) o[n][e] = 0.f;
    float m0 = -CUDART_INF_F, m1 = -CUDART_INF_F;
    float l0 = 0.f, l1 = 0.f;

    const __half* kgh = g_kp + (size_t)b * KLEN * DMOD + h * DH;
    const __half* vgh = g_vpT + ((size_t)(b * DMOD + h * DH)) * KLEN;

    const int kr = tid >> 2;
    const int kc = (tid & 3) * 2;

    {
        const __half* ks_ = kgh + (size_t)kr * DMOD + kc * 8;
        cp16(sptr(&sK[0][kr * 36 + kc * 4]),     ks_);
        cp16(sptr(&sK[0][kr * 36 + kc * 4 + 4]), ks_ + 8);
        const __half* vs_ = vgh + (size_t)kr * KLEN + kc * 8;
        cp16(sptr(&sVT[0][kr * 36 + kc * 4]),     vs_);
        cp16(sptr(&sVT[0][kr * 36 + kc * 4 + 4]), vs_ + 8);
        if (tid < 32)
            cp16(sptr(&lsh[0][0]) + tid * 16,
                 &klocs[((size_t)(b * KLEN)) * 2 + tid * 4]);
        cp_commit();
    }

    for (int tile = 0; tile < ntiles; tile++) {
        const int st = tile & 1;
        const int kb = tile * KT;
        if (tile + 1 < ntiles) {
            const int kb2 = kb + KT;
            const __half* ks_ = kgh + (size_t)(kb2 + kr) * DMOD + kc * 8;
            cp16(sptr(&sK[st ^ 1][kr * 36 + kc * 4]),     ks_);
            cp16(sptr(&sK[st ^ 1][kr * 36 + kc * 4 + 4]), ks_ + 8);
            const __half* vs_ = vgh + (size_t)kr * KLEN + kb2 + kc * 8;
            cp16(sptr(&sVT[st ^ 1][kr * 36 + kc * 4]),     vs_);
            cp16(sptr(&sVT[st ^ 1][kr * 36 + kc * 4 + 4]), vs_ + 8);
            if (tid < 32)
                cp16(sptr(&lsh[st ^ 1][0]) + tid * 16,
                     &klocs[((size_t)(b * KLEN + kb2)) * 2 + tid * 4]);
            cp_commit();
            cp_wait<1>();
        } else {
            cp_wait<0>();
        }
        __syncthreads();

        const uint32_t* sk = sK[st];
        const uint32_t* sv = sVT[st];
        const float2*   sl = lsh[st];

        // ---- S = Q K^T (log2 units) ----
        float s[8][4];
#pragma unroll
        for (int n = 0; n < 8; n++)
#pragma unroll
            for (int e = 0; e < 4; e++) s[n][e] = 0.f;
#pragma unroll
        for (int ks = 0; ks < 4; ks++) {
#pragma unroll
            for (int n = 0; n < 8; n++) {
                uint32_t b0 = sk[(n * 8 + g) * 36 + 8 * ks + t    ];
                uint32_t b1 = sk[(n * 8 + g) * 36 + 8 * ks + t + 4];
                mma_f16(s[n], qa[ks], b0, b1);
            }
        }

        // ---- bias (log2 units) + mask + tile row-max ----
        const bool edge = (rem != 0) && (tile == nfull);
        float tmax0 = -CUDART_INF_F, tmax1 = -CUDART_INF_F;
#pragma unroll
        for (int n = 0; n < 8; n++) {
            int c0 = n * 8 + 2 * t;
            float2 kl0 = sl[c0];
            float2 kl1 = sl[c0 + 1];
            float dx, dy, dist, tp, fr;
            int ti;
            float2 tv;

            dx = ql0.x - kl0.x; dy = ql0.y - kl0.y;
            dist = sqrtf(fmaf(dx, dx, dy * dy));
            tp = dist * TAB_SCALE; ti = min((int)tp, NTAB - 2); fr = tp - (float)ti;
            tv = tsh[ti];
            s[n][0] += fmaf(fr, tv.y, tv.x);

            dx = ql0.x - kl1.x; dy = ql0.y - kl1.y;
            dist = sqrtf(fmaf(dx, dx, dy * dy));
            tp = dist * TAB_SCALE; ti = min((int)tp, NTAB - 2); fr = tp - (float)ti;
            tv = tsh[ti];
            s[n][1] += fmaf(fr, tv.y, tv.x);

            dx = ql1.x - kl0.x; dy = ql1.y - kl0.y;
            dist = sqrtf(fmaf(dx, dx, dy * dy));
            tp = dist * TAB_SCALE; ti = min((int)tp, NTAB - 2); fr = tp - (float)ti;
            tv = tsh[ti];
            s[n][2] += fmaf(fr, tv.y, tv.x);

            dx = ql1.x - kl1.x; dy = ql1.y - kl1.y;
            dist = sqrtf(fmaf(dx, dx, dy * dy));
            tp = dist * TAB_SCALE; ti = min((int)tp, NTAB - 2); fr = tp - (float)ti;
            tv = tsh[ti];
            s[n][3] += fmaf(fr, tv.y, tv.x);

            if (edge) {
                if (kb + c0     >= vlen) { s[n][0] = -CUDART_INF_F; s[n][2] = -CUDART_INF_F; }
                if (kb + c0 + 1 >= vlen) { s[n][1] = -CUDART_INF_F; s[n][3] = -CUDART_INF_F; }
            }
            tmax0 = fmaxf(tmax0, fmaxf(s[n][0], s[n][1]));
            tmax1 = fmaxf(tmax1, fmaxf(s[n][2], s[n][3]));
        }
        tmax0 = fmaxf(tmax0, __shfl_xor_sync(0xffffffffu, tmax0, 1));
        tmax0 = fmaxf(tmax0, __shfl_xor_sync(0xffffffffu, tmax0, 2));
        tmax1 = fmaxf(tmax1, __shfl_xor_sync(0xffffffffu, tmax1, 1));
        tmax1 = fmaxf(tmax1, __shfl_xor_sync(0xffffffffu, tmax1, 2));

        // ---- online softmax via exp2: p = 2^(s-m) (identical to e^(s'-m')) ----
        float mn0 = fmaxf(m0, tmax0), mn1 = fmaxf(m1, tmax1);
        float cor0 = ex2f(m0 - mn0), cor1 = ex2f(m1 - mn1);
        m0 = mn0; m1 = mn1;

        uint32_t pA[8], pB[8];
        __half2 rsa = __float2half2_rn(0.f), rsb = __float2half2_rn(0.f);
#pragma unroll
        for (int n = 0; n < 8; n++) {
            pA[n] = ex2h2(pack_f16x2(s[n][0] - mn0, s[n][1] - mn0));
            pB[n] = ex2h2(pack_f16x2(s[n][2] - mn1, s[n][3] - mn1));
            rsa = __hadd2(rsa, *(__half2*)&pA[n]);
            rsb = __hadd2(rsb, *(__half2*)&pB[n]);
        }
        float2 fa = __half22float2(rsa);
        float2 fb = __half22float2(rsb);
        float rs0 = fa.x + fa.y;
        float rs1 = fb.x + fb.y;
        rs0 += __shfl_xor_sync(0xffffffffu, rs0, 1);
        rs0 += __shfl_xor_sync(0xffffffffu, rs0, 2);
        rs1 += __shfl_xor_sync(0xffffffffu, rs1, 1);
        rs1 += __shfl_xor_sync(0xffffffffu, rs1, 2);
        l0 = l0 * cor0 + rs0;
        l1 = l1 * cor1 + rs1;
#pragma unroll
        for (int n = 0; n < 8; n++) {
            o[n][0] *= cor0; o[n][1] *= cor0;
            o[n][2] *= cor1; o[n][3] *= cor1;
        }

        // ---- O += P V : p halves are already PV A-frags ----
#pragma unroll
        for (int ks = 0; ks < 4; ks++) {
            uint32_t pa[4];
            pa[0] = pA[2 * ks];
            pa[1] = pB[2 * ks];
            pa[2] = pA[2 * ks + 1];
            pa[3] = pB[2 * ks + 1];
#pragma unroll
            for (int n = 0; n < 8; n++) {
                uint32_t b0 = sv[(n * 8 + g) * 36 + 8 * ks + t    ];
                uint32_t b1 = sv[(n * 8 + g) * 36 + 8 * ks + t + 4];
                mma_f16(o[n], pa, b0, b1);
            }
        }
        __syncthreads();
    }

    float inv0 = 1.0f / l0;
    float inv1 = 1.0f / l1;
    uint32_t* ctx32 = (uint32_t*)(g_ctx +
        (size_t)(b * QL + q0 + r0) * DMOD + h * DH);
    uint32_t* ctx32b = ctx32 + 4 * DMOD;
#pragma unroll
    for (int n = 0; n < 8; n++) {
        ctx32 [4 * n + t] = pack_f16x2(o[n][0] * inv0, o[n][1] * inv0);
        ctx32b[4 * n + t] = pack_f16x2(o[n][2] * inv1, o[n][3] * inv1);
    }
}

// ---------------------------------------------------------------------------
// Launch
// ---------------------------------------------------------------------------
extern "C" void kernel_launch(void* const* d_in, const int* in_sizes, int n_in,
                              void* d_out, int out_size)
{
    const float* qs    = (const float*)d_in[0];
    const float* ks    = (const float*)d_in[1];
    const float* vs    = (const float*)d_in[2];
    const float* qlocs = (const float*)d_in[3];
    const float* klocs = (const float*)d_in[4];
    const float* Wq    = (const float*)d_in[5];
    const float* bq    = (const float*)d_in[6];
    const float* Wk    = (const float*)d_in[7];
    const float* bk    = (const float*)d_in[8];
    const float* Wv    = (const float*)d_in[9];
    const float* bv    = (const float*)d_in[10];
    const float* Wo    = (const float*)d_in[11];
    const float* bo    = (const float*)d_in[12];
    const float* ap    = (const float*)d_in[13];
    const float* bp    = (const float*)d_in[14];
    const float* cp    = (const float*)d_in[15];
    const int*   vl    = (const int*)  d_in[16];
    float* out = (float*)d_out;

    static bool attr_set = false;
    if (!attr_set) {
        cudaFuncSetAttribute(gemm_qkv_kernel,
                             cudaFuncAttributeMaxDynamicSharedMemorySize, GEMM_SMEM);
        cudaFuncSetAttribute(gemm_out_kernel,
                             cudaFuncAttributeMaxDynamicSharedMemorySize, GEMM_SMEM);
        attr_set = true;
    }

    dim3 rga((BB * QL * DMOD / 8 + 255) / 256, 3);
    round_acts_kernel<<<rga, 256>>>(qs, ks, vs);
    dim3 twg(16, 16, 4), twb(32, 8);
    round_w_kernel<<<twg, twb>>>(Wq, Wk, Wv, Wo);

    build_table_kernel<<<(NH * NTAB + 255) / 256, 256>>>(ap, bp, cp);

    dim3 g3(DMOD / 128, (BB * QL) / 128, 3);
    gemm_qkv_kernel<<<g3, 256, GEMM_SMEM>>>(bq, bk, bv);

    dim3 tvg(KLEN / 64, DMOD / 64, BB);
    transpose_v_kernel<<<tvg, 256>>>();

    dim3 agrid(QL / 128, NH, BB);
    attn_tc_kernel<<<agrid, 256>>>(qlocs, klocs, vl);

    dim3 ggrid(DMOD / 128, (BB * QL) / 128);
    gemm_out_kernel<<<ggrid, 256, GEMM_SMEM>>>(bo, out);
}

// round 13
// speedup vs baseline: 5.4923x; 1.0255x over previous
#include <cuda_runtime.h>
#include <cuda_fp16.h>
#include <math.h>
#include <math_constants.h>
#include <cstdint>

// ---------------------------------------------------------------------------
// Problem constants
// ---------------------------------------------------------------------------
#define BB   2
#define QL   2048
#define KLEN 2048
#define DMOD 512
#define NH   8
#define NF   5
#define DH   64
#define NTAB 1024

static const float TAB_SCALE = (float)(NTAB - 1) / 14.2f;
#define LOG2E 1.4426950408889634f

// ---------------------------------------------------------------------------
// Device scratch (all fp16 intermediates)
// ---------------------------------------------------------------------------
__device__ __half g_qp [BB * QL   * DMOD];   // projected Q * (1/8)*log2e (fp16)
__device__ __half g_kp [BB * KLEN * DMOD];   // projected K (fp16)
__device__ __half g_vp [BB * KLEN * DMOD];   // projected V [b, key, dm]
__device__ __half g_vpT[BB * DMOD * KLEN];   // V transposed [b, dm, key]
__device__ __half g_ctx[BB * QL   * DMOD];   // attention output (fp16)
__device__ __half g_rq [BB * QL   * DMOD];   // fp16-rounded inputs
__device__ __half g_rk [BB * KLEN * DMOD];
__device__ __half g_rv [BB * KLEN * DMOD];
__device__ __half g_rw [4][DMOD * DMOD];     // fp16 TRANSPOSED weights [n][k]
__device__ float2 g_tab[NH * NTAB];          // bias table in log2 units

// ---------------------------------------------------------------------------
// Helpers
// ---------------------------------------------------------------------------
__device__ __forceinline__ uint32_t pack_f16x2(float lo, float hi) {
    uint32_t r;
    asm("cvt.rn.f16x2.f32 %0, %1, %2;" : "=r"(r) : "f"(hi), "f"(lo));
    return r;
}
__device__ __forceinline__ float ex2f(float x) {
    float r;
    asm("ex2.approx.f32 %0, %1;" : "=f"(r) : "f"(x));
    return r;
}
__device__ __forceinline__ uint32_t ex2h2(uint32_t x) {
    uint32_t r;
    asm("ex2.approx.f16x2 %0, %1;" : "=r"(r) : "r"(x));
    return r;
}
__device__ __forceinline__ float sqrt_ap(float x) {
    float r;
    asm("sqrt.approx.f32 %0, %1;" : "=f"(r) : "f"(x));
    return r;
}

// m16n8k16 fp16 MMA, fp32 accumulate
__device__ __forceinline__ void mma_f16(float* c, const uint32_t* a,
                                        uint32_t b0, uint32_t b1) {
    asm volatile("mma.sync.aligned.m16n8k16.row.col.f32.f16.f16.f32 "
                 "{%0,%1,%2,%3}, {%4,%5,%6,%7}, {%8,%9}, {%0,%1,%2,%3};"
                 : "+f"(c[0]), "+f"(c[1]), "+f"(c[2]), "+f"(c[3])
                 : "r"(a[0]), "r"(a[1]), "r"(a[2]), "r"(a[3]),
                   "r"(b0), "r"(b1));
}

__device__ __forceinline__ uint32_t sptr(const void* p) {
    return (uint32_t)__cvta_generic_to_shared(p);
}
__device__ __forceinline__ void cp16(uint32_t smem_addr, const void* gptr) {
    asm volatile("cp.async.cg.shared.global [%0], [%1], 16;"
                 :: "r"(smem_addr), "l"(gptr) : "memory");
}
__device__ __forceinline__ void cp_commit() {
    asm volatile("cp.async.commit_group;" ::: "memory");
}
template <int N>
__device__ __forceinline__ void cp_wait() {
    asm volatile("cp.async.wait_group %0;" :: "n"(N) : "memory");
}

// ---------------------------------------------------------------------------
// Fused prep: fp16-round activations (blocks 0..3071), fp16+transpose
// weights (3072..4095), bias table in log2 units (4096..4127).
// ---------------------------------------------------------------------------
__global__ __launch_bounds__(256)
void prep_kernel(const float* __restrict__ qs, const float* __restrict__ ks,
                 const float* __restrict__ vs,
                 const float* __restrict__ Wq, const float* __restrict__ Wk,
                 const float* __restrict__ Wv, const float* __restrict__ Wo,
                 const float* __restrict__ Ap, const float* __restrict__ Bp,
                 const float* __restrict__ Cp)
{
    __shared__ float tw[32][33];
    const int blk = blockIdx.x;
    const int tid = threadIdx.x;

    if (blk < 3072) {
        const int z = blk >> 10;            // 0..2
        const int inner = blk & 1023;
        const float* src = (z == 0) ? qs : (z == 1) ? ks : vs;
        __half* dst = (z == 0) ? g_rq : (z == 1) ? g_rk : g_rv;
        size_t i = ((size_t)inner * 256 + tid) * 8;
        if (i >= (size_t)BB * QL * DMOD) return;
        float4 v0 = *(const float4*)&src[i];
        float4 v1 = *(const float4*)&src[i + 4];
        uint4 o;
        o.x = pack_f16x2(v0.x, v0.y);
        o.y = pack_f16x2(v0.z, v0.w);
        o.z = pack_f16x2(v1.x, v1.y);
        o.w = pack_f16x2(v1.z, v1.w);
        *(uint4*)&dst[i] = o;
    } else if (blk < 4096) {
        const int gidx = blk - 3072;
        const int z    = gidx >> 8;         // 0..3
        const int rest = gidx & 255;
        const float* W = (z == 0) ? Wq : (z == 1) ? Wk : (z == 2) ? Wv : Wo;
        __half* Wt = g_rw[z];
        const int bx = (rest & 15) * 32;    // n
        const int by = (rest >> 4) * 32;    // k
        const int tx = tid & 31;
        const int ty = tid >> 5;            // 0..7
#pragma unroll
        for (int i = 0; i < 32; i += 8)
            tw[ty + i][tx] = W[(size_t)(by + ty + i) * DMOD + bx + tx];
        __syncthreads();
#pragma unroll
        for (int i = 0; i < 32; i += 8)
            Wt[(size_t)(bx + ty + i) * DMOD + by + tx] = __float2half(tw[tx][ty + i]);
    } else {
        int idx = (blk - 4096) * 256 + tid;
        if (idx >= NH * NTAB) return;
        int h = idx >> 10;
        int i = idx & 1023;
        const float STEP = 14.2f / (float)(NTAB - 1);
        float d0 = (float)i * STEP;
        float d1 = d0 + STEP;
        float v0 = 0.f, v1 = 0.f;
#pragma unroll
        for (int f = 0; f < NF; f++) {
            float af = Ap[h * NF + f];
            float bf = fabsf(Bp[h * NF + f]);
            float cf = Cp[h * NF + f];
            float t0 = d0 - cf;
            float t1 = d1 - cf;
            v0 += af * expf(-bf * t0 * t0);
            v1 += af * expf(-bf * t1 * t1);
        }
        v0 *= LOG2E;
        v1 *= LOG2E;
        g_tab[idx] = make_float2(v0, v1 - v0);
    }
}

// ---------------------------------------------------------------------------
// V transpose (fp16): g_vp [b, key, dm] -> g_vpT [b, dm, key].
// ---------------------------------------------------------------------------
__global__ __launch_bounds__(256)
void transpose_v_kernel()
{
    __shared__ __half t[64][72];
    const int b  = blockIdx.z;
    const int k0 = blockIdx.x * 64;
    const int d0 = blockIdx.y * 64;
    const int tid = threadIdx.x;
#pragma unroll
    for (int p = 0; p < 8; p++) {
        int e = tid + p * 256;
        int key = e >> 5;
        int dp  = e & 31;
        uint32_t v = *(const uint32_t*)&g_vp[((size_t)(b * KLEN + k0 + key)) * DMOD + d0 + 2 * dp];
        __half2 h2 = *(__half2*)&v;
        t[2 * dp    ][key] = __low2half(h2);
        t[2 * dp + 1][key] = __high2half(h2);
    }
    __syncthreads();
#pragma unroll
    for (int p = 0; p < 2; p++) {
        int e = tid + p * 256;
        int dm = e >> 3;
        int c  = e & 7;
        uint4 v = *(uint4*)&t[dm][c * 8];
        *(uint4*)&g_vpT[((size_t)(b * DMOD + d0 + dm)) * KLEN + k0 + c * 8] = v;
    }
}

// ---------------------------------------------------------------------------
// fp16 GEMM: 128x128 tile, BK=32, 3-stage cp.async, ONE barrier per chunk.
// 3 CTAs/SM (60KB smem, 85-reg cap) -> single wave at 384 CTAs.
// ---------------------------------------------------------------------------
#define GP 20
#define STG_U32 (128 * GP)
#define GSTAGES 3
#define GEMM_SMEM (GSTAGES * 2 * STG_U32 * 4)   // 61440 bytes

template <int MODE>
__device__ __forceinline__ void gemm_core(const __half* __restrict__ Ah,
                                          const __half* __restrict__ Wt,
                                          const float* __restrict__ bias,
                                          float scale,
                                          float* __restrict__ outF,
                                          __half* __restrict__ outH)
{
    extern __shared__ __align__(16) uint32_t dsm[];

    const int tid  = threadIdx.x;
    const int lane = tid & 31;
    const int wrp  = tid >> 5;
    const int m_off = (wrp >> 1) * 32;
    const int n_off = (wrp & 1) * 64;
    const int m0 = blockIdx.y * 128;
    const int n0 = blockIdx.x * 128;
    const int lq = lane >> 2;
    const int lr = lane & 3;

    const int ra = tid >> 1;
    const int ca = (tid & 1) * 2;

    float c[2][8][4];
#pragma unroll
    for (int i = 0; i < 2; i++)
#pragma unroll
        for (int j = 0; j < 8; j++)
#pragma unroll
            for (int e = 0; e < 4; e++) c[i][j][e] = 0.f;

#define GEMM_PREFETCH(CH, STG)                                                 \
    {                                                                          \
        uint32_t* A_s = dsm + (STG) * 2 * STG_U32;                             \
        uint32_t* B_s = A_s + STG_U32;                                         \
        const __half* Asrc = Ah + (size_t)(m0 + ra) * DMOD + (CH) * 32 + ca * 8; \
        cp16(sptr(&A_s[ra * GP + ca * 4]),     Asrc);                          \
        cp16(sptr(&A_s[ra * GP + ca * 4 + 4]), Asrc + 8);                      \
        const __half* Bsrc = Wt + (size_t)(n0 + ra) * DMOD + (CH) * 32 + ca * 8; \
        cp16(sptr(&B_s[ra * GP + ca * 4]),     Bsrc);                          \
        cp16(sptr(&B_s[ra * GP + ca * 4 + 4]), Bsrc + 8);                      \
        cp_commit();                                                           \
    }

    GEMM_PREFETCH(0, 0)
    GEMM_PREFETCH(1, 1)

    int st = 0, pst = 2;
    for (int ch = 0; ch < 16; ch++) {
        if (ch < 15) cp_wait<1>(); else cp_wait<0>();
        __syncthreads();
        if (ch + 2 < 16) GEMM_PREFETCH(ch + 2, pst)

        const uint32_t* cA = dsm + st * 2 * STG_U32;
        const uint32_t* cB = cA + STG_U32;
#pragma unroll
        for (int ks = 0; ks < 2; ks++) {
            const int k0 = ks * 8;
            uint32_t a[2][4];
#pragma unroll
            for (int i = 0; i < 2; i++) {
                int r = m_off + i * 16 + lq;
                a[i][0] = cA[(r    ) * GP + k0 + lr    ];
                a[i][1] = cA[(r + 8) * GP + k0 + lr    ];
                a[i][2] = cA[(r    ) * GP + k0 + lr + 4];
                a[i][3] = cA[(r + 8) * GP + k0 + lr + 4];
            }
#pragma unroll
            for (int jh = 0; jh < 2; jh++) {
                uint32_t b4[4][2];
#pragma unroll
                for (int j = 0; j < 4; j++) {
                    int n = n_off + (jh * 4 + j) * 8 + lq;
                    b4[j][0] = cB[n * GP + k0 + lr    ];
                    b4[j][1] = cB[n * GP + k0 + lr + 4];
                }
#pragma unroll
                for (int i = 0; i < 2; i++)
#pragma unroll
                    for (int j = 0; j < 4; j++)
                        mma_f16(c[i][jh * 4 + j], a[i], b4[j][0], b4[j][1]);
            }
        }
        st  = (st  == 2) ? 0 : st  + 1;
        pst = (pst == 2) ? 0 : pst + 1;
    }

#pragma unroll
    for (int i = 0; i < 2; i++) {
        int row = m0 + m_off + i * 16 + lq;
#pragma unroll
        for (int j = 0; j < 8; j++) {
            int col = n0 + n_off + j * 8 + 2 * lr;
            float b0 = bias[col], b1 = bias[col + 1];
            float v00 = (c[i][j][0] + b0) * scale;
            float v01 = (c[i][j][1] + b1) * scale;
            float v10 = (c[i][j][2] + b0) * scale;
            float v11 = (c[i][j][3] + b1) * scale;
            if (MODE == 0) {
                *(float2*)&outF[(size_t)row * DMOD + col] = make_float2(v00, v01);
                *(float2*)&outF[(size_t)(row + 8) * DMOD + col] = make_float2(v10, v11);
            } else {
                uint32_t* o32 = (uint32_t*)outH;
                o32[(size_t)row * (DMOD / 2) + (col >> 1)] = pack_f16x2(v00, v01);
                o32[(size_t)(row + 8) * (DMOD / 2) + (col >> 1)] = pack_f16x2(v10, v11);
            }
        }
    }
#undef GEMM_PREFETCH
}

__global__ __launch_bounds__(256, 3)
void gemm_qkv_kernel(const float* __restrict__ bq, const float* __restrict__ bk,
                     const float* __restrict__ bv)
{
    const int z = blockIdx.z;
    const __half* A = (z == 0) ? g_rq : (z == 1) ? g_rk : g_rv;
    const __half* W = g_rw[z];
    const float*  B = (z == 0) ? bq : (z == 1) ? bk : bv;
    __half*       C = (z == 0) ? g_qp : (z == 1) ? g_kp : g_vp;
    const float   s = (z == 0) ? 0.125f * LOG2E : 1.0f;
    gemm_core<1>(A, W, B, s, nullptr, C);
}

__global__ __launch_bounds__(256, 3)
void gemm_out_kernel(const float* __restrict__ bias, float* __restrict__ Cout)
{
    gemm_core<0>(g_ctx, g_rw[3], bias, 1.0f, Cout, nullptr);
}

// ---------------------------------------------------------------------------
// fp16 tensor-core flash attention; exp2 softmax; ONE barrier per tile.
// ---------------------------------------------------------------------------
#define KT 64

__global__ __launch_bounds__(256, 2)
void attn_tc_kernel(const float* __restrict__ qlocs,
                    const float* __restrict__ klocs,
                    const int*   __restrict__ vlens)
{
    __shared__ __align__(16) uint32_t sK [2][KT * 36];
    __shared__ __align__(16) uint32_t sVT[2][KT * 36];
    __shared__ __align__(16) float2   tsh[NTAB];
    __shared__ __align__(16) float2   lsh[2][KT];

    const int b   = blockIdx.z;
    const int h   = blockIdx.y;
    const int q0  = blockIdx.x * 128;
    const int tid = threadIdx.x;
    const int lane = tid & 31;
    const int w    = tid >> 5;
    const int g    = lane >> 2;
    const int t    = lane & 3;
    const int r0   = w * 16 + g;

    for (int i = tid; i < NTAB; i += 256) tsh[i] = g_tab[h * NTAB + i];

    uint32_t qa[4][4];
    {
        const uint32_t* q32a = (const uint32_t*)(g_qp +
            (size_t)(b * QL + q0 + r0) * DMOD + h * DH);
        const uint32_t* q32b = q32a + 4 * DMOD;
#pragma unroll
        for (int ks = 0; ks < 4; ks++) {
            qa[ks][0] = __ldg(&q32a[8 * ks + t]);
            qa[ks][1] = __ldg(&q32b[8 * ks + t]);
            qa[ks][2] = __ldg(&q32a[8 * ks + t + 4]);
            qa[ks][3] = __ldg(&q32b[8 * ks + t + 4]);
        }
    }
    float2 ql0 = *(const float2*)&qlocs[((size_t)(b * QL + q0 + r0)) * 2];
    float2 ql1 = *(const float2*)&qlocs[((size_t)(b * QL + q0 + r0 + 8)) * 2];

    const int vlen  = vlens[b];
    const int nfull = vlen >> 6;
    const int rem   = vlen & 63;
    const int ntiles = nfull + (rem ? 1 : 0);

    float o[8][4];
#pragma unroll
    for (int n = 0; n < 8; n++)
#pragma unroll
        for (int e = 0; e < 4; e++) o[n][e] = 0.f;
    float m0 = -CUDART_INF_F, m1 = -CUDART_INF_F;
    float l0 = 0.f, l1 = 0.f;

    const __half* kgh = g_kp + (size_t)b * KLEN * DMOD + h * DH;
    const __half* vgh = g_vpT + ((size_t)(b * DMOD + h * DH)) * KLEN;

    const int kr = tid >> 2;
    const int kc = (tid & 3) * 2;

    {
        const __half* ks_ = kgh + (size_t)kr * DMOD + kc * 8;
        cp16(sptr(&sK[0][kr * 36 + kc * 4]),     ks_);
        cp16(sptr(&sK[0][kr * 36 + kc * 4 + 4]), ks_ + 8);
        const __half* vs_ = vgh + (size_t)kr * KLEN + kc * 8;
        cp16(sptr(&sVT[0][kr * 36 + kc * 4]),     vs_);
        cp16(sptr(&sVT[0][kr * 36 + kc * 4 + 4]), vs_ + 8);
        if (tid < 32)
            cp16(sptr(&lsh[0][0]) + tid * 16,
                 &klocs[((size_t)(b * KLEN)) * 2 + tid * 4]);
        cp_commit();
    }

    for (int tile = 0; tile < ntiles; tile++) {
        const int st = tile & 1;
        const int kb = tile * KT;
        cp_wait<0>();
        __syncthreads();                 // also protects stage st^1 refill below
        if (tile + 1 < ntiles) {
            const int kb2 = kb + KT;
            const __half* ks_ = kgh + (size_t)(kb2 + kr) * DMOD + kc * 8;
            cp16(sptr(&sK[st ^ 1][kr * 36 + kc * 4]),     ks_);
            cp16(sptr(&sK[st ^ 1][kr * 36 + kc * 4 + 4]), ks_ + 8);
            const __half* vs_ = vgh + (size_t)kr * KLEN + kb2 + kc * 8;
            cp16(sptr(&sVT[st ^ 1][kr * 36 + kc * 4]),     vs_);
            cp16(sptr(&sVT[st ^ 1][kr * 36 + kc * 4 + 4]), vs_ + 8);
            if (tid < 32)
                cp16(sptr(&lsh[st ^ 1][0]) + tid * 16,
                     &klocs[((size_t)(b * KLEN + kb2)) * 2 + tid * 4]);
            cp_commit();
        }

        const uint32_t* sk = sK[st];
        const uint32_t* sv = sVT[st];
        const float2*   sl = lsh[st];

        // ---- S = Q K^T (log2 units) ----
        float s[8][4];
#pragma unroll
        for (int n = 0; n < 8; n++)
#pragma unroll
            for (int e = 0; e < 4; e++) s[n][e] = 0.f;
#pragma unroll
        for (int ks = 0; ks < 4; ks++) {
#pragma unroll
            for (int n = 0; n < 8; n++) {
                uint32_t b0 = sk[(n * 8 + g) * 36 + 8 * ks + t    ];
                uint32_t b1 = sk[(n * 8 + g) * 36 + 8 * ks + t + 4];
                mma_f16(s[n], qa[ks], b0, b1);
            }
        }

        // ---- bias (log2 units) + mask + tile row-max ----
        const bool edge = (rem != 0) && (tile == nfull);
        float tmax0 = -CUDART_INF_F, tmax1 = -CUDART_INF_F;
#pragma unroll
        for (int n = 0; n < 8; n++) {
            int c0 = n * 8 + 2 * t;
            float2 kl0 = sl[c0];
            float2 kl1 = sl[c0 + 1];
            float dx, dy, tp, fr;
            int ti;
            float2 tv;

            dx = ql0.x - kl0.x; dy = ql0.y - kl0.y;
            tp = sqrt_ap(fmaf(dx, dx, dy * dy)) * TAB_SCALE;
            ti = (int)tp; fr = tp - (float)ti;
            tv = tsh[ti];
            s[n][0] += fmaf(fr, tv.y, tv.x);

            dx = ql0.x - kl1.x; dy = ql0.y - kl1.y;
            tp = sqrt_ap(fmaf(dx, dx, dy * dy)) * TAB_SCALE;
            ti = (int)tp; fr = tp - (float)ti;
            tv = tsh[ti];
            s[n][1] += fmaf(fr, tv.y, tv.x);

            dx = ql1.x - kl0.x; dy = ql1.y - kl0.y;
            tp = sqrt_ap(fmaf(dx, dx, dy * dy)) * TAB_SCALE;
            ti = (int)tp; fr = tp - (float)ti;
            tv = tsh[ti];
            s[n][2] += fmaf(fr, tv.y, tv.x);

            dx = ql1.x - kl1.x; dy = ql1.y - kl1.y;
            tp = sqrt_ap(fmaf(dx, dx, dy * dy)) * TAB_SCALE;
            ti = (int)tp; fr = tp - (float)ti;
            tv = tsh[ti];
            s[n][3] += fmaf(fr, tv.y, tv.x);

            if (edge) {
                if (kb + c0     >= vlen) { s[n][0] = -CUDART_INF_F; s[n][2] = -CUDART_INF_F; }
                if (kb + c0 + 1 >= vlen) { s[n][1] = -CUDART_INF_F; s[n][3] = -CUDART_INF_F; }
            }
            tmax0 = fmaxf(tmax0, fmaxf(s[n][0], s[n][1]));
            tmax1 = fmaxf(tmax1, fmaxf(s[n][2], s[n][3]));
        }
        tmax0 = fmaxf(tmax0, __shfl_xor_sync(0xffffffffu, tmax0, 1));
        tmax0 = fmaxf(tmax0, __shfl_xor_sync(0xffffffffu, tmax0, 2));
        tmax1 = fmaxf(tmax1, __shfl_xor_sync(0xffffffffu, tmax1, 1));
        tmax1 = fmaxf(tmax1, __shfl_xor_sync(0xffffffffu, tmax1, 2));

        // ---- online softmax via exp2, conditional rescale ----
        float mn0 = fmaxf(m0, tmax0), mn1 = fmaxf(m1, tmax1);
        float dm0 = m0 - mn0, dm1 = m1 - mn1;
        m0 = mn0; m1 = mn1;
        if (__any_sync(0xffffffffu, fminf(dm0, dm1) < 0.f)) {
            float cor0 = ex2f(dm0), cor1 = ex2f(dm1);
            l0 *= cor0; l1 *= cor1;
#pragma unroll
            for (int n = 0; n < 8; n++) {
                o[n][0] *= cor0; o[n][1] *= cor0;
                o[n][2] *= cor1; o[n][3] *= cor1;
            }
        }

        uint32_t pA[8], pB[8];
        __half2 rsa = __float2half2_rn(0.f), rsb = __float2half2_rn(0.f);
#pragma unroll
        for (int n = 0; n < 8; n++) {
            pA[n] = ex2h2(pack_f16x2(s[n][0] - mn0, s[n][1] - mn0));
            pB[n] = ex2h2(pack_f16x2(s[n][2] - mn1, s[n][3] - mn1));
            rsa = __hadd2(rsa, *(__half2*)&pA[n]);
            rsb = __hadd2(rsb, *(__half2*)&pB[n]);
        }
        float2 fa = __half22float2(rsa);
        float2 fb = __half22float2(rsb);
        float rs0 = fa.x + fa.y;
        float rs1 = fb.x + fb.y;
        rs0 += __shfl_xor_sync(0xffffffffu, rs0, 1);
        rs0 += __shfl_xor_sync(0xffffffffu, rs0, 2);
        rs1 += __shfl_xor_sync(0xffffffffu, rs1, 1);
        rs1 += __shfl_xor_sync(0xffffffffu, rs1, 2);
        l0 += rs0;
        l1 += rs1;

        // ---- O += P V : p halves are already PV A-frags ----
#pragma unroll
        for (int ks = 0; ks < 4; ks++) {
            uint32_t pa[4];
            pa[0] = pA[2 * ks];
            pa[1] = pB[2 * ks];
            pa[2] = pA[2 * ks + 1];
            pa[3] = pB[2 * ks + 1];
#pragma unroll
            for (int n = 0; n < 8; n++) {
                uint32_t b0 = sv[(n * 8 + g) * 36 + 8 * ks + t    ];
                uint32_t b1 = sv[(n * 8 + g) * 36 + 8 * ks + t + 4];
                mma_f16(o[n], pa, b0, b1);
            }
        }
    }

    float inv0 = 1.0f / l0;
    float inv1 = 1.0f / l1;
    uint32_t* ctx32 = (uint32_t*)(g_ctx +
        (size_t)(b * QL + q0 + r0) * DMOD + h * DH);
    uint32_t* ctx32b = ctx32 + 4 * DMOD;
#pragma unroll
    for (int n = 0; n < 8; n++) {
        ctx32 [4 * n + t] = pack_f16x2(o[n][0] * inv0, o[n][1] * inv0);
        ctx32b[4 * n + t] = pack_f16x2(o[n][2] * inv1, o[n][3] * inv1);
    }
}

// ---------------------------------------------------------------------------
// Launch
// ---------------------------------------------------------------------------
extern "C" void kernel_launch(void* const* d_in, const int* in_sizes, int n_in,
                              void* d_out, int out_size)
{
    const float* qs    = (const float*)d_in[0];
    const float* ks    = (const float*)d_in[1];
    const float* vs    = (const float*)d_in[2];
    const float* qlocs = (const float*)d_in[3];
    const float* klocs = (const float*)d_in[4];
    const float* Wq    = (const float*)d_in[5];
    const float* bq    = (const float*)d_in[6];
    const float* Wk    = (const float*)d_in[7];
    const float* bk    = (const float*)d_in[8];
    const float* Wv    = (const float*)d_in[9];
    const float* bv    = (const float*)d_in[10];
    const float* Wo    = (const float*)d_in[11];
    const float* bo    = (const float*)d_in[12];
    const float* ap    = (const float*)d_in[13];
    const float* bp    = (const float*)d_in[14];
    const float* cp    = (const float*)d_in[15];
    const int*   vl    = (const int*)  d_in[16];
    float* out = (float*)d_out;

    static bool attr_set = false;
    if (!attr_set) {
        cudaFuncSetAttribute(gemm_qkv_kernel,
                             cudaFuncAttributeMaxDynamicSharedMemorySize, GEMM_SMEM);
        cudaFuncSetAttribute(gemm_out_kernel,
                             cudaFuncAttributeMaxDynamicSharedMemorySize, GEMM_SMEM);
        attr_set = true;
    }

    prep_kernel<<<4128, 256>>>(qs, ks, vs, Wq, Wk, Wv, Wo, ap, bp, cp);

    dim3 g3(DMOD / 128, (BB * QL) / 128, 3);
    gemm_qkv_kernel<<<g3, 256, GEMM_SMEM>>>(bq, bk, bv);

    dim3 tvg(KLEN / 64, DMOD / 64, BB);
    transpose_v_kernel<<<tvg, 256>>>();

    dim3 agrid(QL / 128, NH, BB);
    attn_tc_kernel<<<agrid, 256>>>(qlocs, klocs, vl);

    dim3 ggrid(DMOD / 128, (BB * QL) / 128);
    gemm_out_kernel<<<ggrid, 256, GEMM_SMEM>>>(bo, out);
}